// round 8
// baseline (speedup 1.0000x reference)
#include <cuda_runtime.h>
#include <math.h>
#include <stdint.h>

// Problem constants
#define CN 50000
#define CE 800000
#define CR 3
#define CT 16

typedef unsigned long long ull;

__device__ __forceinline__ ull fma2(ull a, ull b, ull c) {
    ull d; asm("fma.rn.f32x2 %0, %1, %2, %3;" : "=l"(d) : "l"(a), "l"(b), "l"(c)); return d;
}
__device__ __forceinline__ void unpack2(ull v, float& lo, float& hi) {
    asm("mov.b64 {%0,%1}, %2;" : "=f"(lo), "=f"(hi) : "l"(v));
}

// ---------------- scratch layout (floats) ----------------
constexpr size_t SZ_WCAT = 256 * 128;
constexpr size_t OFF_WCV = 0;
constexpr size_t OFF_WCS = OFF_WCV + SZ_WCAT;
constexpr size_t OFF_BCV = OFF_WCS + SZ_WCAT;
constexpr size_t OFF_BCS = OFF_BCV + 256;
constexpr size_t OFF_HV0 = OFF_BCS + 256;                 // N*64 each
constexpr size_t OFF_HV1 = OFF_HV0 + (size_t)CN * 64;
constexpr size_t OFF_HS0 = OFF_HV1 + (size_t)CN * 64;
constexpr size_t OFF_HS1 = OFF_HS0 + (size_t)CN * 64;
constexpr size_t OFF_CV  = OFF_HS1 + (size_t)CN * 64;
constexpr size_t OFF_CS  = OFF_CV + (size_t)CN * 64;
constexpr size_t OFF_XCAT= OFF_CS + (size_t)CN * 64;      // [xv|xp|xs|xp] N*512
constexpr size_t OFF_BIG = OFF_XCAT + (size_t)CN * 512;   // [hall0..2, xin0..2] N*768
constexpr size_t OFF_P1  = OFF_BIG + (size_t)CN * 768;    // N*128
constexpr size_t OFF_DEG = OFF_P1 + (size_t)CN * 128;     // N
constexpr size_t OFF_DINV= OFF_DEG + CN;                  // N
constexpr size_t OFF_F   = OFF_DINV + CN;                 // N*5*128
constexpr size_t OFF_SC  = OFF_F + (size_t)CN * 640;      // scores N*5
constexpr size_t OFF_RES = OFF_SC + (size_t)CN * 5 + 64;  // N*128
constexpr size_t SCRATCH_TOTAL = OFF_RES + (size_t)CN * 128;

__device__ float g_scratch[SCRATCH_TOTAL];
__device__ int g_csr[CE];
__device__ int g_off[CN + 1];
__device__ int g_cur[CN];

// =====================================================================
// FFMA2 GEMM core, pack-free A-duplication:
//  - A tile stored DUPLICATED (a,a) pairs: As2[16][256]. A-reads are
//    2-address/warp broadcasts -> 1 crossbar phase per LDS.128, and the
//    loaded ull is already a packed FFMA2 a-operand (no MOV packs).
//  - B tile plain floats (R5-proven): consecutive-column pairs read by
//    LDS.128 are ready b-operands.
//  - acc2[i][jj]: row (ty*8+i) x col pair (tx*8+2jj, +2jj+1).
// 128x128 tile, BK=16, double-buffered, 256 threads, 8x8/thread.
// =====================================================================
#define TILE_COMPUTE(cur)                                                      \
    _Pragma("unroll")                                                          \
    for (int kk = 0; kk < 16; kk++) {                                          \
        ull a2[8]; ull b2[4];                                                  \
        {                                                                      \
            const ulonglong2* ap = (const ulonglong2*)(&As2[cur][kk][ty * 16]);\
            ulonglong2 t0 = ap[0], t1 = ap[1], t2 = ap[2], t3 = ap[3];         \
            a2[0] = t0.x; a2[1] = t0.y; a2[2] = t1.x; a2[3] = t1.y;            \
            a2[4] = t2.x; a2[5] = t2.y; a2[6] = t3.x; a2[7] = t3.y;            \
            const ulonglong2* wp = (const ulonglong2*)(&Ws[cur][kk][tx * 8]);  \
            ulonglong2 w0 = wp[0]; ulonglong2 w1 = wp[1];                      \
            b2[0] = w0.x; b2[1] = w0.y; b2[2] = w1.x; b2[3] = w1.y;            \
        }                                                                      \
        _Pragma("unroll")                                                      \
        for (int i = 0; i < 8; i++)                                            \
            _Pragma("unroll")                                                  \
            for (int jj = 0; jj < 4; jj++)                                     \
                acc2[i][jj] = fma2(a2[i], b2[jj], acc2[i][jj]);                \
    }

#define STORE_TILE(buf)                                                                         \
    *(float2*)(&As2[buf][lk+0][2*lr]) = make_float2(pa0.x, pa0.x);                              \
    *(float2*)(&As2[buf][lk+1][2*lr]) = make_float2(pa0.y, pa0.y);                              \
    *(float2*)(&As2[buf][lk+2][2*lr]) = make_float2(pa0.z, pa0.z);                              \
    *(float2*)(&As2[buf][lk+3][2*lr]) = make_float2(pa0.w, pa0.w);                              \
    *(float2*)(&As2[buf][lk+0][2*(lr+64)]) = make_float2(pa1.x, pa1.x);                         \
    *(float2*)(&As2[buf][lk+1][2*(lr+64)]) = make_float2(pa1.y, pa1.y);                         \
    *(float2*)(&As2[buf][lk+2][2*(lr+64)]) = make_float2(pa1.z, pa1.z);                         \
    *(float2*)(&As2[buf][lk+3][2*(lr+64)]) = make_float2(pa1.w, pa1.w);                         \
    Ws[buf][lk+0][lr] = pw0.x; Ws[buf][lk+1][lr] = pw0.y;                                       \
    Ws[buf][lk+2][lr] = pw0.z; Ws[buf][lk+3][lr] = pw0.w;                                       \
    Ws[buf][lk+0][lr+64] = pw1.x; Ws[buf][lk+1][lr+64] = pw1.y;                                 \
    Ws[buf][lk+2][lr+64] = pw1.z; Ws[buf][lk+3][lr+64] = pw1.w;

// ---------------- generic SGEMM:  C = act(A @ W^T + bias) ----------------
__global__ __launch_bounds__(256) void sgemm_kernel(
    const float* __restrict__ A, int lda, int K1,
    const float* __restrict__ A2, int lda2,
    const float* __restrict__ W,
    const float* __restrict__ bias,
    float* __restrict__ C, int ldc,
    int M, int K, int act)
{
    __shared__ float As2[2][16][256];
    __shared__ float Ws[2][16][128];

    const int bm = blockIdx.y * 128;
    const int bn = blockIdx.x * 128;
    const int tid = threadIdx.x;
    const int lr = tid >> 2;
    const int lk = (tid & 3) << 2;
    const int ty = tid >> 4, tx = tid & 15;

    ull acc2[8][4];
#pragma unroll
    for (int i = 0; i < 8; i++)
#pragma unroll
        for (int jj = 0; jj < 4; jj++) acc2[i][jj] = 0ull;

    int r0 = bm + lr;      r0 = r0 < M ? r0 : (M - 1);
    int r1 = bm + lr + 64; r1 = r1 < M ? r1 : (M - 1);

    float4 pa0, pa1, pw0, pw1;
    {
        int kg = lk;
        pa0 = (kg < K1) ? *(const float4*)(A + (size_t)r0 * lda + kg)
                        : *(const float4*)(A2 + (size_t)r0 * lda2 + (kg - K1));
        pa1 = (kg < K1) ? *(const float4*)(A + (size_t)r1 * lda + kg)
                        : *(const float4*)(A2 + (size_t)r1 * lda2 + (kg - K1));
        pw0 = *(const float4*)(W + (size_t)(bn + lr) * K + kg);
        pw1 = *(const float4*)(W + (size_t)(bn + lr + 64) * K + kg);
    }
    STORE_TILE(0)
    __syncthreads();

    const int ntiles = K >> 4;
    for (int t = 0; t < ntiles; t++) {
        const int cur = t & 1, nxt = cur ^ 1;
        const bool has = (t + 1) < ntiles;
        if (has) {
            int kg = ((t + 1) << 4) + lk;
            pa0 = (kg < K1) ? *(const float4*)(A + (size_t)r0 * lda + kg)
                            : *(const float4*)(A2 + (size_t)r0 * lda2 + (kg - K1));
            pa1 = (kg < K1) ? *(const float4*)(A + (size_t)r1 * lda + kg)
                            : *(const float4*)(A2 + (size_t)r1 * lda2 + (kg - K1));
            pw0 = *(const float4*)(W + (size_t)(bn + lr) * K + kg);
            pw1 = *(const float4*)(W + (size_t)(bn + lr + 64) * K + kg);
        }
        TILE_COMPUTE(cur)
        if (has) { STORE_TILE(nxt) }
        __syncthreads();
    }

    float bs0[8];
    *(float4*)(&bs0[0]) = *(const float4*)(bias + bn + tx * 8);
    *(float4*)(&bs0[4]) = *(const float4*)(bias + bn + tx * 8 + 4);

#pragma unroll
    for (int i = 0; i < 8; i++) {
        int m = bm + ty * 8 + i;
        if (m >= M) continue;
        float v[8];
#pragma unroll
        for (int jj = 0; jj < 4; jj++) {
            float lo, hi; unpack2(acc2[i][jj], lo, hi);
            v[2 * jj] = lo; v[2 * jj + 1] = hi;
        }
#pragma unroll
        for (int j = 0; j < 8; j++) {
            float x = v[j] + bs0[j];
            if (act == 1)      x = x > 0.f ? x : 0.01f * x;
            else if (act == 2) x = tanhf(x);
            v[j] = x;
        }
        float* cp = C + (size_t)m * ldc + bn + tx * 8;
        *(float4*)(cp)     = *(float4*)(&v[0]);
        *(float4*)(cp + 4) = *(float4*)(&v[4]);
    }
}

static inline void gemm(const float* A, int lda, int K1,
                        const float* A2, int lda2,
                        const float* W, const float* bias,
                        float* C, int ldc, int M, int O, int K, int act)
{
    dim3 grid(O / 128, (M + 127) / 128);
    sgemm_kernel<<<grid, 256>>>(A, lda, K1, A2, lda2, W, bias, C, ldc, M, K, act);
}

// ---------------- score GEMM: score[m] = w2 . tanh(A[m] @ W^T + bias) ----------------
// O = 128 exactly (one column tile). Y never materialized.
__global__ __launch_bounds__(256) void sgemm_score_kernel(
    const float* __restrict__ A, int lda,
    const float* __restrict__ W,
    const float* __restrict__ bias,
    const float* __restrict__ w2,
    float* __restrict__ score,
    int M)
{
    __shared__ float As2[2][16][256];
    __shared__ float Ws[2][16][128];

    const int bm = blockIdx.y * 128;
    const int tid = threadIdx.x;
    const int lr = tid >> 2;
    const int lk = (tid & 3) << 2;
    const int ty = tid >> 4, tx = tid & 15;
    const int K = 128;

    ull acc2[8][4];
#pragma unroll
    for (int i = 0; i < 8; i++)
#pragma unroll
        for (int jj = 0; jj < 4; jj++) acc2[i][jj] = 0ull;

    int r0 = bm + lr;      r0 = r0 < M ? r0 : (M - 1);
    int r1 = bm + lr + 64; r1 = r1 < M ? r1 : (M - 1);

    float4 pa0, pa1, pw0, pw1;
    {
        int kg = lk;
        pa0 = *(const float4*)(A + (size_t)r0 * lda + kg);
        pa1 = *(const float4*)(A + (size_t)r1 * lda + kg);
        pw0 = *(const float4*)(W + (size_t)lr * K + kg);
        pw1 = *(const float4*)(W + (size_t)(lr + 64) * K + kg);
    }
    STORE_TILE(0)
    __syncthreads();

#pragma unroll
    for (int t = 0; t < 8; t++) {
        const int cur = t & 1, nxt = cur ^ 1;
        const bool has = t < 7;
        if (has) {
            int kg = ((t + 1) << 4) + lk;
            pa0 = *(const float4*)(A + (size_t)r0 * lda + kg);
            pa1 = *(const float4*)(A + (size_t)r1 * lda + kg);
            pw0 = *(const float4*)(W + (size_t)lr * K + kg);
            pw1 = *(const float4*)(W + (size_t)(lr + 64) * K + kg);
        }
        TILE_COMPUTE(cur)
        if (has) { STORE_TILE(nxt) }
        __syncthreads();
    }

    float bs0[8], w2l[8];
    *(float4*)(&bs0[0]) = *(const float4*)(bias + tx * 8);
    *(float4*)(&bs0[4]) = *(const float4*)(bias + tx * 8 + 4);
    *(float4*)(&w2l[0]) = *(const float4*)(w2 + tx * 8);
    *(float4*)(&w2l[4]) = *(const float4*)(w2 + tx * 8 + 4);

#pragma unroll
    for (int i = 0; i < 8; i++) {
        float v[8];
#pragma unroll
        for (int jj = 0; jj < 4; jj++) {
            float lo, hi; unpack2(acc2[i][jj], lo, hi);
            v[2 * jj] = lo; v[2 * jj + 1] = hi;
        }
        float p = 0.f;
#pragma unroll
        for (int j = 0; j < 8; j++)
            p += tanhf(v[j] + bs0[j]) * w2l[j];
#pragma unroll
        for (int off = 8; off; off >>= 1)
            p += __shfl_xor_sync(0xffffffffu, p, off);
        int m = bm + ty * 8 + i;
        if (tx == 0 && m < M) score[m] = p;
    }
}

// ---------------- fused dual-LSTM step kernel (FFMA2, A-dup) ----------------
__device__ __forceinline__ float sigf(float x) { return 1.f / (1.f + expf(-x)); }

__global__ __launch_bounds__(256) void lstm_step2_kernel(
    const float* __restrict__ Xv, const float* __restrict__ Xs, int ldx,
    const float* __restrict__ Hv, const float* __restrict__ Hs,
    const float* __restrict__ Wcv, const float* __restrict__ Wcs,
    const float* __restrict__ bcv, const float* __restrict__ bcs,
    float* __restrict__ Cv, float* __restrict__ Cs,
    float* __restrict__ Hvo, float* __restrict__ Hso)
{
    __shared__ float As2[2][16][256];
    __shared__ float Ws[2][16][128];

    const int sel = blockIdx.x >> 1;
    const float* X   = sel ? Xs  : Xv;
    const float* Hin = sel ? Hs  : Hv;
    const float* Wc  = sel ? Wcs : Wcv;
    const float* bc  = sel ? bcs : bcv;
    float* Cst  = sel ? Cs  : Cv;
    float* Hout = sel ? Hso : Hvo;

    const int M = CN;
    const int bm = blockIdx.y * 128;
    const int bn = (blockIdx.x & 1) * 128;
    const int tid = threadIdx.x;
    const int lr = tid >> 2;
    const int lk = (tid & 3) << 2;
    const int ty = tid >> 4, tx = tid & 15;

    ull acc2[8][4];
#pragma unroll
    for (int i = 0; i < 8; i++)
#pragma unroll
        for (int jj = 0; jj < 4; jj++) acc2[i][jj] = 0ull;

    int r0 = bm + lr;      r0 = r0 < M ? r0 : (M - 1);
    int r1 = bm + lr + 64; r1 = r1 < M ? r1 : (M - 1);

    float4 pa0, pa1, pw0, pw1;
    {
        int kg = lk;
        pa0 = (kg < 64) ? *(const float4*)(X + (size_t)r0 * ldx + kg)
                        : *(const float4*)(Hin + (size_t)r0 * 64 + (kg - 64));
        pa1 = (kg < 64) ? *(const float4*)(X + (size_t)r1 * ldx + kg)
                        : *(const float4*)(Hin + (size_t)r1 * 64 + (kg - 64));
        pw0 = *(const float4*)(Wc + (size_t)(bn + lr) * 128 + kg);
        pw1 = *(const float4*)(Wc + (size_t)(bn + lr + 64) * 128 + kg);
    }
    STORE_TILE(0)
    __syncthreads();

#pragma unroll
    for (int t = 0; t < 8; t++) {
        const int cur = t & 1, nxt = cur ^ 1;
        const bool has = t < 7;
        if (has) {
            int kg = ((t + 1) << 4) + lk;
            pa0 = (kg < 64) ? *(const float4*)(X + (size_t)r0 * ldx + kg)
                            : *(const float4*)(Hin + (size_t)r0 * 64 + (kg - 64));
            pa1 = (kg < 64) ? *(const float4*)(X + (size_t)r1 * ldx + kg)
                            : *(const float4*)(Hin + (size_t)r1 * 64 + (kg - 64));
            pw0 = *(const float4*)(Wc + (size_t)(bn + lr) * 128 + kg);
            pw1 = *(const float4*)(Wc + (size_t)(bn + lr + 64) * 128 + kg);
        }
        TILE_COMPUTE(cur)
        if (has) { STORE_TILE(nxt) }
        __syncthreads();
    }

    // epilogue: thread cols = 2 complete [i,f,g,o] quadruples -> units u0,u0+1
    const int colbase = bn + tx * 8;
    const int u0 = colbase >> 2;
    float bb[8];
    *(float4*)(&bb[0]) = *(const float4*)(bc + colbase);
    *(float4*)(&bb[4]) = *(const float4*)(bc + colbase + 4);

#pragma unroll
    for (int i = 0; i < 8; i++) {
        int m = bm + ty * 8 + i;
        if (m >= M) continue;
        float g[8];
#pragma unroll
        for (int jj = 0; jj < 4; jj++) {
            float lo, hi; unpack2(acc2[i][jj], lo, hi);
            g[2 * jj] = lo + bb[2 * jj]; g[2 * jj + 1] = hi + bb[2 * jj + 1];
        }
        float2 cold = *(float2*)(Cst + (size_t)m * 64 + u0);
        float c0 = sigf(g[1]) * cold.x + sigf(g[0]) * tanhf(g[2]);
        float c1 = sigf(g[5]) * cold.y + sigf(g[4]) * tanhf(g[6]);
        float2 cn = make_float2(c0, c1);
        float2 hn = make_float2(sigf(g[3]) * tanhf(c0), sigf(g[7]) * tanhf(c1));
        *(float2*)(Cst + (size_t)m * 64 + u0) = cn;
        *(float2*)(Hout + (size_t)m * 64 + u0) = hn;
    }
}

// ---------------- small kernels ----------------
__global__ void zero_kernel(float* p, size_t n)
{
    size_t i = (size_t)blockIdx.x * blockDim.x + threadIdx.x;
    size_t stride = (size_t)gridDim.x * blockDim.x;
    for (; i < n; i += stride) p[i] = 0.f;
}

// build interleaved LSTM weights: out row 4u+g <- orig row g*64+u, K = [x|h]
__global__ void prep_kernel(const float* __restrict__ Wih_v, const float* __restrict__ Whh_v,
                            const float* __restrict__ bih_v, const float* __restrict__ bhh_v,
                            const float* __restrict__ Wih_s, const float* __restrict__ Whh_s,
                            const float* __restrict__ bih_s, const float* __restrict__ bhh_s,
                            float* __restrict__ S)
{
    int idx = blockIdx.x * blockDim.x + threadIdx.x;
    if (idx < 256 * 128) {
        int o = idx >> 7, k = idx & 127;
        int u = o >> 2, g = o & 3;
        int orow = g * 64 + u;
        S[OFF_WCV + idx] = (k < 64) ? Wih_v[orow * 64 + k] : Whh_v[orow * 64 + (k - 64)];
        S[OFF_WCS + idx] = (k < 64) ? Wih_s[orow * 64 + k] : Whh_s[orow * 64 + (k - 64)];
        if (idx < 256) {
            int uu = idx >> 2, gg = idx & 3;
            int ob = gg * 64 + uu;
            S[OFF_BCV + idx] = bih_v[ob] + bhh_v[ob];
            S[OFF_BCS + idx] = bih_s[ob] + bhh_s[ob];
        }
    }
}

__global__ void copy_xp_kernel(float* __restrict__ S)
{
    size_t idx = (size_t)blockIdx.x * blockDim.x + threadIdx.x;
    if (idx >= (size_t)CN * 128) return;
    size_t n = idx >> 7;
    int j = (int)(idx & 127);
    S[OFF_XCAT + n * 512 + 384 + j] = S[OFF_XCAT + n * 512 + 128 + j];
}

__global__ void deg_kernel(const int* __restrict__ dst, float* __restrict__ deg)
{
    int e = blockIdx.x * blockDim.x + threadIdx.x;
    if (e < CE) atomicAdd(&deg[dst[e]], 1.0f);
}

__global__ void dinv_kernel(float* __restrict__ S)
{
    int n = blockIdx.x * blockDim.x + threadIdx.x;
    if (n < CN) S[OFF_DINV + n] = rsqrtf(fmaxf(S[OFF_DEG + n], 1.0f));
}

// single-block exclusive scan of (int)deg -> off[0..CN], cur = off
__global__ __launch_bounds__(1024) void scan_kernel(const float* __restrict__ deg,
                                                    int* __restrict__ off,
                                                    int* __restrict__ cur)
{
    __shared__ int part[1024];
    const int tid = threadIdx.x;
    const int chunk = (CN + 1023) / 1024;
    const int start = tid * chunk;
    const int end = min(start + chunk, CN);
    int s = 0;
    for (int i = start; i < end; i++) s += (int)deg[i];
    part[tid] = s;
    __syncthreads();
    for (int d = 1; d < 1024; d <<= 1) {
        int v = (tid >= d) ? part[tid - d] : 0;
        __syncthreads();
        part[tid] += v;
        __syncthreads();
    }
    int pre = (tid == 0) ? 0 : part[tid - 1];
    for (int i = start; i < end; i++) {
        off[i] = pre;
        cur[i] = pre;
        pre += (int)deg[i];
    }
    if (tid == 1023) off[CN] = pre;
}

// fill CSR: for each edge, place src into the dst's segment
__global__ void fill_kernel(const int* __restrict__ src, const int* __restrict__ dst,
                            int* __restrict__ cur, int* __restrict__ csr)
{
    int e = blockIdx.x * blockDim.x + threadIdx.x;
    if (e < CE) {
        int d = dst[e];
        int pos = atomicAdd(&cur[d], 1);
        csr[pos] = src[e];
    }
}

// gather propagation: out[n] = pin[n] - dinv[n] * sum_{s in N(n)} pin[s]*dinv[s]
__global__ __launch_bounds__(256) void prop_kernel(
    const float* __restrict__ pin, int ldin,
    const int* __restrict__ csr, const int* __restrict__ off,
    const float* __restrict__ dinv, float* __restrict__ outp)
{
    const int n = blockIdx.x * 8 + (threadIdx.x >> 5);
    if (n >= CN) return;
    const int lane = threadIdx.x & 31;
    const int col = lane * 4;
    float4 acc = make_float4(0.f, 0.f, 0.f, 0.f);
    const int s0 = off[n], s1 = off[n + 1];
    for (int e = s0; e < s1; e++) {
        int sn = csr[e];
        float ds = __ldg(&dinv[sn]);
        float4 v = *(const float4*)(pin + (size_t)sn * ldin + col);
        acc.x += v.x * ds; acc.y += v.y * ds; acc.z += v.z * ds; acc.w += v.w * ds;
    }
    const float dn = dinv[n];
    float4 pv = *(const float4*)(pin + (size_t)n * ldin + col);
    float4 o = make_float4(pv.x - acc.x * dn, pv.y - acc.y * dn,
                           pv.z - acc.z * dn, pv.w - acc.w * dn);
    *(float4*)(outp + (size_t)n * 128 + col) = o;
}

// second propagation fused with filter construction
__global__ __launch_bounds__(256) void prop2F_kernel(
    const float* __restrict__ p1,
    const float* __restrict__ p0, int ld0,
    const int* __restrict__ csr, const int* __restrict__ off,
    const float* __restrict__ dinv, float* __restrict__ F)
{
    const int n = blockIdx.x * 8 + (threadIdx.x >> 5);
    if (n >= CN) return;
    const int lane = threadIdx.x & 31;
    const int col = lane * 4;
    float4 acc = make_float4(0.f, 0.f, 0.f, 0.f);
    const int s0 = off[n], s1 = off[n + 1];
    for (int e = s0; e < s1; e++) {
        int sn = csr[e];
        float ds = __ldg(&dinv[sn]);
        float4 v = *(const float4*)(p1 + (size_t)sn * 128 + col);
        acc.x += v.x * ds; acc.y += v.y * ds; acc.z += v.z * ds; acc.w += v.w * ds;
    }
    const float dn = dinv[n];
    float4 b = *(const float4*)(p1 + (size_t)n * 128 + col);
    float4 a = *(const float4*)(p0 + (size_t)n * ld0 + col);
    float4 c = make_float4(b.x - acc.x * dn, b.y - acc.y * dn,
                           b.z - acc.z * dn, b.w - acc.w * dn);
    float* Fb = F + (size_t)n * 640 + col;
    float4 f0 = make_float4(0.8f * a.x - 0.5f * b.x, 0.8f * a.y - 0.5f * b.y,
                            0.8f * a.z - 0.5f * b.z, 0.8f * a.w - 0.5f * b.w);
    float4 f1 = make_float4(3.0f * a.x - 3.0f * b.x + 0.75f * c.x,
                            3.0f * a.y - 3.0f * b.y + 0.75f * c.y,
                            3.0f * a.z - 3.0f * b.z + 0.75f * c.z,
                            3.0f * a.w - 3.0f * b.w + 0.75f * c.w);
    float4 f2 = make_float4(3.0f * b.x - 1.5f * c.x, 3.0f * b.y - 1.5f * c.y,
                            3.0f * b.z - 1.5f * c.z, 3.0f * b.w - 1.5f * c.w);
    float4 f3 = make_float4(0.75f * c.x, 0.75f * c.y, 0.75f * c.z, 0.75f * c.w);
    float4 f4 = make_float4(-0.2f * a.x + 0.5f * b.x, -0.2f * a.y + 0.5f * b.y,
                            -0.2f * a.z + 0.5f * b.z, -0.2f * a.w + 0.5f * b.w);
    *(float4*)(Fb)       = f0;
    *(float4*)(Fb + 128) = f1;
    *(float4*)(Fb + 256) = f2;
    *(float4*)(Fb + 384) = f3;
    *(float4*)(Fb + 512) = f4;
}

// softmax over 5 per-node scores; res = sum_f soft_f * F_f
__global__ void attn_res_kernel(const float* __restrict__ score, const float* __restrict__ F,
                                float* __restrict__ res)
{
    size_t gid = (size_t)blockIdx.x * blockDim.x + threadIdx.x;
    int n = (int)(gid >> 5);
    int lane = (int)(gid & 31);
    if (n >= CN) return;
    float sc[5];
#pragma unroll
    for (int f = 0; f < 5; f++) sc[f] = score[(size_t)n * 5 + f];
    float mx = sc[0];
#pragma unroll
    for (int f = 1; f < 5; f++) mx = fmaxf(mx, sc[f]);
    float e[5], s = 0.f;
#pragma unroll
    for (int f = 0; f < 5; f++) { e[f] = expf(sc[f] - mx); s += e[f]; }
    float inv = 1.f / s;
    const float* Fb = F + (size_t)n * 640;
    const int col = lane * 4;
    float4 r = make_float4(0.f, 0.f, 0.f, 0.f);
#pragma unroll
    for (int f = 0; f < 5; f++) {
        float4 v = *(const float4*)(Fb + f * 128 + col);
        float w = e[f];
        r.x += w * v.x; r.y += w * v.y; r.z += w * v.z; r.w += w * v.w;
    }
    r.x *= inv; r.y *= inv; r.z *= inv; r.w *= inv;
    *(float4*)(res + (size_t)n * 128 + col) = r;
}

// out[n, c] = big[n, :] . W6[c, :] + b6[c], warp per node
__global__ void final_kernel(const float* __restrict__ big, const float* __restrict__ W6,
                             const float* __restrict__ b6, float* __restrict__ out)
{
    size_t gid = (size_t)blockIdx.x * blockDim.x + threadIdx.x;
    int n = (int)(gid >> 5);
    int lane = (int)(gid & 31);
    if (n >= CN) return;
    const float* row = big + (size_t)n * 768;
#pragma unroll
    for (int c = 0; c < 2; c++) {
        float a = 0.f;
        for (int j = lane; j < 768; j += 32) a += row[j] * W6[c * 768 + j];
#pragma unroll
        for (int off = 16; off; off >>= 1) a += __shfl_xor_sync(0xffffffffu, a, off);
        if (lane == 0) out[(size_t)n * 2 + c] = a + b6[c];
    }
}

// ---------------- orchestration ----------------
extern "C" void kernel_launch(void* const* d_in, const int* in_sizes, int n_in,
                              void* d_out, int out_size)
{
    const float* voc    = (const float*)d_in[0];
    const float* sms    = (const float*)d_in[1];
    const float* pers   = (const float*)d_in[2];
    const float* Wih_v  = (const float*)d_in[3];
    const float* Whh_v  = (const float*)d_in[4];
    const float* bih_v  = (const float*)d_in[5];
    const float* bhh_v  = (const float*)d_in[6];
    const float* Wih_s  = (const float*)d_in[7];
    const float* Whh_s  = (const float*)d_in[8];
    const float* bih_s  = (const float*)d_in[9];
    const float* bhh_s  = (const float*)d_in[10];
    const float* W_lin  = (const float*)d_in[11];
    const float* b_lin  = (const float*)d_in[12];
    const float* W_lin1 = (const float*)d_in[13];
    const float* b_lin1 = (const float*)d_in[14];
    const float* W_pers = (const float*)d_in[15];
    const float* b_pers = (const float*)d_in[16];
    const float* W_lin2 = (const float*)d_in[17];
    const float* b_lin2 = (const float*)d_in[18];
    const float* W_lin3 = (const float*)d_in[19];
    const float* b_lin3 = (const float*)d_in[20];
    const float* W_lin4 = (const float*)d_in[21];
    const float* b_lin4 = (const float*)d_in[22];
    const float* W_lin5 = (const float*)d_in[23];
    const float* b_lin5 = (const float*)d_in[24];
    const float* Wf1    = (const float*)d_in[25];
    const float* bf1    = (const float*)d_in[26];
    const float* Wf2    = (const float*)d_in[27];
    const float* W_lin6 = (const float*)d_in[28];
    const float* b_lin6 = (const float*)d_in[29];
    const int*   src    = (const int*)d_in[30];
    const int*   dst    = (const int*)d_in[31];
    float* out = (float*)d_out;

    float* S = nullptr;
    cudaGetSymbolAddress((void**)&S, g_scratch);
    int* csr = nullptr; cudaGetSymbolAddress((void**)&csr, g_csr);
    int* offp = nullptr; cudaGetSymbolAddress((void**)&offp, g_off);
    int* curp = nullptr; cudaGetSymbolAddress((void**)&curp, g_cur);

    // prep: interleaved LSTM weights/biases, zero states (HV0,HV1,HS0,HS1,CV,CS)
    prep_kernel<<<(256 * 128 + 255) / 256, 256>>>(Wih_v, Whh_v, bih_v, bhh_v,
                                                  Wih_s, Whh_s, bih_s, bhh_s, S);
    zero_kernel<<<4096, 256>>>(S + OFF_HV0, (size_t)6 * CN * 64);

    // ---- LSTMs: 16 steps, both LSTMs per launch, fused GEMM+cell ----
    dim3 lgrid(4, (CN + 127) / 128);
    for (int t = 0; t < CT; t++) {
        const float* hv_in  = S + ((t & 1) ? OFF_HV1 : OFF_HV0);
        float*       hv_out = S + ((t & 1) ? OFF_HV0 : OFF_HV1);
        const float* hs_in  = S + ((t & 1) ? OFF_HS1 : OFF_HS0);
        float*       hs_out = S + ((t & 1) ? OFF_HS0 : OFF_HS1);
        lstm_step2_kernel<<<lgrid, 256>>>(voc + (size_t)t * 64, sms + (size_t)t * 64, CT * 64,
                                          hv_in, hs_in,
                                          S + OFF_WCV, S + OFF_WCS,
                                          S + OFF_BCV, S + OFF_BCS,
                                          S + OFF_CV, S + OFF_CS,
                                          hv_out, hs_out);
    }
    // final h is in HV0 / HS0 (16 steps, even)

    // ---- projections ----
    gemm(S + OFF_HV0, 64, 64, S + OFF_HV0, 64, W_lin, b_lin,
         S + OFF_XCAT + 0, 512, CN, 128, 64, 1);
    gemm(S + OFF_HS0, 64, 64, S + OFF_HS0, 64, W_lin1, b_lin1,
         S + OFF_XCAT + 256, 512, CN, 128, 64, 1);
    gemm(pers, 32, 32, pers, 32, W_pers, b_pers,
         S + OFF_XCAT + 128, 512, CN, 128, 32, 1);
    copy_xp_kernel<<<((size_t)CN * 128 + 255) / 256, 256>>>(S);

    gemm(S + OFF_XCAT, 512, 256, S + OFF_XCAT, 512, W_lin2, b_lin2,
         S + OFF_BIG + 384, 768, CN, 128, 256, 1);
    gemm(S + OFF_XCAT + 256, 512, 256, S + OFF_XCAT + 256, 512, W_lin3, b_lin3,
         S + OFF_BIG + 512, 768, CN, 128, 256, 1);
    gemm(S + OFF_XCAT, 512, 512, S + OFF_XCAT, 512, W_lin4, b_lin4,
         S + OFF_BIG + 640, 768, CN, 128, 512, 1);

    // ---- relation graphs (CSR gather-based propagation) ----
    const int pgrid = (CN + 7) / 8;
    for (int r = 0; r < CR; r++) {
        const int* sr = src + (size_t)r * CE;
        const int* dr = dst + (size_t)r * CE;
        const float* p0 = S + OFF_BIG + 384 + 128 * r;  // lda 768

        zero_kernel<<<256, 256>>>(S + OFF_DEG, (size_t)CN);
        deg_kernel<<<(CE + 255) / 256, 256>>>(dr, S + OFF_DEG);
        dinv_kernel<<<(CN + 255) / 256, 256>>>(S);
        scan_kernel<<<1, 1024>>>(S + OFF_DEG, offp, curp);
        fill_kernel<<<(CE + 255) / 256, 256>>>(sr, dr, curp, csr);

        prop_kernel<<<pgrid, 256>>>(p0, 768, csr, offp, S + OFF_DINV, S + OFF_P1);
        prop2F_kernel<<<pgrid, 256>>>(S + OFF_P1, p0, 768, csr, offp,
                                      S + OFF_DINV, S + OFF_F);

        // scores = w2 . tanh(F @ Wf1^T + bf1) fused (Y never materialized)
        {
            dim3 sgrid(1, (CN * 5 + 127) / 128);
            sgemm_score_kernel<<<sgrid, 256>>>(S + OFF_F, 128,
                                               Wf1 + (size_t)r * 128 * 128,
                                               bf1 + (size_t)r * 128,
                                               Wf2 + (size_t)r * 128,
                                               S + OFF_SC, CN * 5);
        }

        attn_res_kernel<<<((size_t)CN * 32 + 255) / 256, 256>>>(S + OFF_SC, S + OFF_F,
                                                                S + OFF_RES);

        // hall_r = act(res @ W_lin5[r]^T + b_lin5[r]) -> big cols [128r, 128r+128)
        gemm(S + OFF_RES, 128, 128, S + OFF_RES, 128,
             W_lin5 + (size_t)r * 128 * 128, b_lin5 + (size_t)r * 128,
             S + OFF_BIG + 128 * r, 768, CN, 128, 128, 1);
    }

    // ---- final head ----
    final_kernel<<<((size_t)CN * 32 + 255) / 256, 256>>>(S + OFF_BIG, W_lin6, b_lin6, out);
}

// round 9
// speedup vs baseline: 1.4576x; 1.4576x over previous
#include <cuda_runtime.h>
#include <math.h>
#include <stdint.h>

// Problem constants
#define CN 50000
#define CE 800000
#define CR 3
#define CT 16

typedef unsigned long long ull;

__device__ __forceinline__ ull pack2(float lo, float hi) {
    ull r; asm("mov.b64 %0, {%1,%2};" : "=l"(r) : "f"(lo), "f"(hi)); return r;
}
__device__ __forceinline__ ull fma2(ull a, ull b, ull c) {
    ull d; asm("fma.rn.f32x2 %0, %1, %2, %3;" : "=l"(d) : "l"(a), "l"(b), "l"(c)); return d;
}
__device__ __forceinline__ void unpack2(ull v, float& lo, float& hi) {
    asm("mov.b64 {%0,%1}, %2;" : "=f"(lo), "=f"(hi) : "l"(v));
}

// ---------------- scratch layout (floats) ----------------
constexpr size_t SZ_WCAT = 256 * 128;
constexpr size_t OFF_WCV = 0;
constexpr size_t OFF_WCS = OFF_WCV + SZ_WCAT;
constexpr size_t OFF_BCV = OFF_WCS + SZ_WCAT;
constexpr size_t OFF_BCS = OFF_BCV + 256;
constexpr size_t OFF_HV0 = OFF_BCS + 256;                 // N*64 each
constexpr size_t OFF_HV1 = OFF_HV0 + (size_t)CN * 64;
constexpr size_t OFF_HS0 = OFF_HV1 + (size_t)CN * 64;
constexpr size_t OFF_HS1 = OFF_HS0 + (size_t)CN * 64;
constexpr size_t OFF_CV  = OFF_HS1 + (size_t)CN * 64;
constexpr size_t OFF_CS  = OFF_CV + (size_t)CN * 64;
constexpr size_t OFF_XCAT= OFF_CS + (size_t)CN * 64;      // [xv|xp|xs|xp] N*512
constexpr size_t OFF_BIG = OFF_XCAT + (size_t)CN * 512;   // [hall0..2, xin0..2] N*768
constexpr size_t OFF_P1  = OFF_BIG + (size_t)CN * 768;    // N*128
constexpr size_t OFF_DEG = OFF_P1 + (size_t)CN * 128;     // N
constexpr size_t OFF_DINV= OFF_DEG + CN;                  // N
constexpr size_t OFF_F   = OFF_DINV + CN;                 // N*5*128
constexpr size_t OFF_SC  = OFF_F + (size_t)CN * 640;      // scores/softmax N*5
constexpr size_t SCRATCH_TOTAL = OFF_SC + (size_t)CN * 5 + 64;

__device__ float g_scratch[SCRATCH_TOTAL];
__device__ int g_csr[CE];
__device__ int g_off[CN + 1];
__device__ int g_cur[CN];

// =====================================================================
// FFMA2 GEMM core (PROVEN R7 shape): 128x128 tile, BK=16, double-buffered,
// 256 threads, 8x8/thread; acc2[i][jj] packs output cols (2jj, 2jj+1).
// =====================================================================
#define TILE_COMPUTE(cur)                                                      \
    _Pragma("unroll")                                                          \
    for (int kk = 0; kk < 16; kk++) {                                          \
        float a[8]; ull b2[4];                                                 \
        *(float4*)(&a[0]) = *(const float4*)(&As[cur][kk][ty * 8]);            \
        *(float4*)(&a[4]) = *(const float4*)(&As[cur][kk][ty * 8 + 4]);        \
        {                                                                      \
            const ulonglong2* wp = (const ulonglong2*)(&Ws[cur][kk][tx * 8]);  \
            ulonglong2 w0 = wp[0]; ulonglong2 w1 = wp[1];                      \
            b2[0] = w0.x; b2[1] = w0.y; b2[2] = w1.x; b2[3] = w1.y;            \
        }                                                                      \
        _Pragma("unroll")                                                      \
        for (int i = 0; i < 8; i++) {                                          \
            ull ai = pack2(a[i], a[i]);                                        \
            _Pragma("unroll")                                                  \
            for (int jj = 0; jj < 4; jj++)                                     \
                acc2[i][jj] = fma2(ai, b2[jj], acc2[i][jj]);                   \
        }                                                                      \
    }

#define STORE_TILE(buf)                                                                         \
    As[buf][lk+0][lr] = pa0.x; As[buf][lk+1][lr] = pa0.y;                                       \
    As[buf][lk+2][lr] = pa0.z; As[buf][lk+3][lr] = pa0.w;                                       \
    As[buf][lk+0][lr+64] = pa1.x; As[buf][lk+1][lr+64] = pa1.y;                                 \
    As[buf][lk+2][lr+64] = pa1.z; As[buf][lk+3][lr+64] = pa1.w;                                 \
    Ws[buf][lk+0][lr] = pw0.x; Ws[buf][lk+1][lr] = pw0.y;                                       \
    Ws[buf][lk+2][lr] = pw0.z; Ws[buf][lk+3][lr] = pw0.w;                                       \
    Ws[buf][lk+0][lr+64] = pw1.x; Ws[buf][lk+1][lr+64] = pw1.y;                                 \
    Ws[buf][lk+2][lr+64] = pw1.z; Ws[buf][lk+3][lr+64] = pw1.w;

// ---------------- generic SGEMM:  C = act(A @ W^T + bias) ----------------
__global__ __launch_bounds__(256) void sgemm_kernel(
    const float* __restrict__ A, int lda, int K1,
    const float* __restrict__ A2, int lda2,
    const float* __restrict__ W,
    const float* __restrict__ bias,
    float* __restrict__ C, int ldc,
    int M, int K, int act)
{
    __shared__ float As[2][16][128];
    __shared__ float Ws[2][16][128];

    const int bm = blockIdx.y * 128;
    const int bn = blockIdx.x * 128;
    const int tid = threadIdx.x;
    const int lr = tid >> 2;
    const int lk = (tid & 3) << 2;
    const int ty = tid >> 4, tx = tid & 15;

    ull acc2[8][4];
#pragma unroll
    for (int i = 0; i < 8; i++)
#pragma unroll
        for (int jj = 0; jj < 4; jj++) acc2[i][jj] = 0ull;

    int r0 = bm + lr;      r0 = r0 < M ? r0 : (M - 1);
    int r1 = bm + lr + 64; r1 = r1 < M ? r1 : (M - 1);

    float4 pa0, pa1, pw0, pw1;
    {
        int kg = lk;
        pa0 = (kg < K1) ? *(const float4*)(A + (size_t)r0 * lda + kg)
                        : *(const float4*)(A2 + (size_t)r0 * lda2 + (kg - K1));
        pa1 = (kg < K1) ? *(const float4*)(A + (size_t)r1 * lda + kg)
                        : *(const float4*)(A2 + (size_t)r1 * lda2 + (kg - K1));
        pw0 = *(const float4*)(W + (size_t)(bn + lr) * K + kg);
        pw1 = *(const float4*)(W + (size_t)(bn + lr + 64) * K + kg);
    }
    STORE_TILE(0)
    __syncthreads();

    const int ntiles = K >> 4;
    for (int t = 0; t < ntiles; t++) {
        const int cur = t & 1, nxt = cur ^ 1;
        const bool has = (t + 1) < ntiles;
        if (has) {
            int kg = ((t + 1) << 4) + lk;
            pa0 = (kg < K1) ? *(const float4*)(A + (size_t)r0 * lda + kg)
                            : *(const float4*)(A2 + (size_t)r0 * lda2 + (kg - K1));
            pa1 = (kg < K1) ? *(const float4*)(A + (size_t)r1 * lda + kg)
                            : *(const float4*)(A2 + (size_t)r1 * lda2 + (kg - K1));
            pw0 = *(const float4*)(W + (size_t)(bn + lr) * K + kg);
            pw1 = *(const float4*)(W + (size_t)(bn + lr + 64) * K + kg);
        }
        TILE_COMPUTE(cur)
        if (has) { STORE_TILE(nxt) }
        __syncthreads();
    }

    float bs0[8];
    *(float4*)(&bs0[0]) = *(const float4*)(bias + bn + tx * 8);
    *(float4*)(&bs0[4]) = *(const float4*)(bias + bn + tx * 8 + 4);

#pragma unroll
    for (int i = 0; i < 8; i++) {
        int m = bm + ty * 8 + i;
        if (m >= M) continue;
        float v[8];
#pragma unroll
        for (int jj = 0; jj < 4; jj++) {
            float lo, hi; unpack2(acc2[i][jj], lo, hi);
            v[2 * jj] = lo; v[2 * jj + 1] = hi;
        }
#pragma unroll
        for (int j = 0; j < 8; j++) {
            float x = v[j] + bs0[j];
            if (act == 1)      x = x > 0.f ? x : 0.01f * x;
            else if (act == 2) x = tanhf(x);
            v[j] = x;
        }
        float* cp = C + (size_t)m * ldc + bn + tx * 8;
        *(float4*)(cp)     = *(float4*)(&v[0]);
        *(float4*)(cp + 4) = *(float4*)(&v[4]);
    }
}

static inline void gemm(const float* A, int lda, int K1,
                        const float* A2, int lda2,
                        const float* W, const float* bias,
                        float* C, int ldc, int M, int O, int K, int act)
{
    dim3 grid(O / 128, (M + 127) / 128);
    sgemm_kernel<<<grid, 256>>>(A, lda, K1, A2, lda2, W, bias, C, ldc, M, K, act);
}

// ---------------- score GEMM: score[m] = w2 . tanh(A[m] @ W^T + bias) ----------------
// O = 128 exactly (one column tile). Y never materialized. (R7-proven)
__global__ __launch_bounds__(256) void sgemm_score_kernel(
    const float* __restrict__ A, int lda,
    const float* __restrict__ W,
    const float* __restrict__ bias,
    const float* __restrict__ w2,
    float* __restrict__ score,
    int M)
{
    __shared__ float As[2][16][128];
    __shared__ float Ws[2][16][128];

    const int bm = blockIdx.y * 128;
    const int tid = threadIdx.x;
    const int lr = tid >> 2;
    const int lk = (tid & 3) << 2;
    const int ty = tid >> 4, tx = tid & 15;
    const int K = 128;

    ull acc2[8][4];
#pragma unroll
    for (int i = 0; i < 8; i++)
#pragma unroll
        for (int jj = 0; jj < 4; jj++) acc2[i][jj] = 0ull;

    int r0 = bm + lr;      r0 = r0 < M ? r0 : (M - 1);
    int r1 = bm + lr + 64; r1 = r1 < M ? r1 : (M - 1);

    float4 pa0, pa1, pw0, pw1;
    {
        int kg = lk;
        pa0 = *(const float4*)(A + (size_t)r0 * lda + kg);
        pa1 = *(const float4*)(A + (size_t)r1 * lda + kg);
        pw0 = *(const float4*)(W + (size_t)lr * K + kg);
        pw1 = *(const float4*)(W + (size_t)(lr + 64) * K + kg);
    }
    STORE_TILE(0)
    __syncthreads();

#pragma unroll
    for (int t = 0; t < 8; t++) {
        const int cur = t & 1, nxt = cur ^ 1;
        const bool has = t < 7;
        if (has) {
            int kg = ((t + 1) << 4) + lk;
            pa0 = *(const float4*)(A + (size_t)r0 * lda + kg);
            pa1 = *(const float4*)(A + (size_t)r1 * lda + kg);
            pw0 = *(const float4*)(W + (size_t)lr * K + kg);
            pw1 = *(const float4*)(W + (size_t)(lr + 64) * K + kg);
        }
        TILE_COMPUTE(cur)
        if (has) { STORE_TILE(nxt) }
        __syncthreads();
    }

    float bs0[8], w2l[8];
    *(float4*)(&bs0[0]) = *(const float4*)(bias + tx * 8);
    *(float4*)(&bs0[4]) = *(const float4*)(bias + tx * 8 + 4);
    *(float4*)(&w2l[0]) = *(const float4*)(w2 + tx * 8);
    *(float4*)(&w2l[4]) = *(const float4*)(w2 + tx * 8 + 4);

#pragma unroll
    for (int i = 0; i < 8; i++) {
        float v[8];
#pragma unroll
        for (int jj = 0; jj < 4; jj++) {
            float lo, hi; unpack2(acc2[i][jj], lo, hi);
            v[2 * jj] = lo; v[2 * jj + 1] = hi;
        }
        float p = 0.f;
#pragma unroll
        for (int j = 0; j < 8; j++)
            p += tanhf(v[j] + bs0[j]) * w2l[j];
#pragma unroll
        for (int off = 8; off; off >>= 1)
            p += __shfl_xor_sync(0xffffffffu, p, off);
        int m = bm + ty * 8 + i;
        if (tx == 0 && m < M) score[m] = p;
    }
}

// ---------------- attn GEMM: C = act((sum_f soft[m][f]*F[m][f]) @ W^T + b) --------
// A is synthesized on the fly from F (N x 5 x 128) and soft (N x 5).
// O = 128 exactly. reg-capped for 2 CTA/SM.
__global__ __launch_bounds__(256, 2) void sgemm_attn_kernel(
    const float* __restrict__ F,
    const float* __restrict__ soft,
    const float* __restrict__ W,
    const float* __restrict__ bias,
    float* __restrict__ C, int ldc,
    int M)
{
    __shared__ float As[2][16][128];
    __shared__ float Ws[2][16][128];

    const int bm = blockIdx.y * 128;
    const int tid = threadIdx.x;
    const int lr = tid >> 2;
    const int lk = (tid & 3) << 2;
    const int ty = tid >> 4, tx = tid & 15;
    const int K = 128;

    ull acc2[8][4];
#pragma unroll
    for (int i = 0; i < 8; i++)
#pragma unroll
        for (int jj = 0; jj < 4; jj++) acc2[i][jj] = 0ull;

    int r0 = bm + lr;      r0 = r0 < M ? r0 : (M - 1);
    int r1 = bm + lr + 64; r1 = r1 < M ? r1 : (M - 1);

    // softmax weights for both rows (persist across tiles)
    float s0[5], s1[5];
#pragma unroll
    for (int f = 0; f < 5; f++) {
        s0[f] = __ldg(soft + (size_t)r0 * 5 + f);
        s1[f] = __ldg(soft + (size_t)r1 * 5 + f);
    }

    float4 pa0, pa1, pw0, pw1;
#define LOAD_AF(dst, rr, ss, kg)                                               \
    {                                                                          \
        const float* Fb = F + (size_t)(rr) * 640 + (kg);                       \
        float4 acc_ = make_float4(0.f, 0.f, 0.f, 0.f);                         \
        _Pragma("unroll")                                                      \
        for (int f = 0; f < 5; f++) {                                          \
            float4 vv = *(const float4*)(Fb + f * 128);                        \
            float w_ = (ss)[f];                                                \
            acc_.x += w_ * vv.x; acc_.y += w_ * vv.y;                          \
            acc_.z += w_ * vv.z; acc_.w += w_ * vv.w;                          \
        }                                                                      \
        dst = acc_;                                                            \
    }
    {
        int kg = lk;
        LOAD_AF(pa0, r0, s0, kg)
        LOAD_AF(pa1, r1, s1, kg)
        pw0 = *(const float4*)(W + (size_t)lr * K + kg);
        pw1 = *(const float4*)(W + (size_t)(lr + 64) * K + kg);
    }
    STORE_TILE(0)
    __syncthreads();

#pragma unroll
    for (int t = 0; t < 8; t++) {
        const int cur = t & 1, nxt = cur ^ 1;
        const bool has = t < 7;
        if (has) {
            int kg = ((t + 1) << 4) + lk;
            LOAD_AF(pa0, r0, s0, kg)
            LOAD_AF(pa1, r1, s1, kg)
            pw0 = *(const float4*)(W + (size_t)lr * K + kg);
            pw1 = *(const float4*)(W + (size_t)(lr + 64) * K + kg);
        }
        TILE_COMPUTE(cur)
        if (has) { STORE_TILE(nxt) }
        __syncthreads();
    }
#undef LOAD_AF

    float bs0[8];
    *(float4*)(&bs0[0]) = *(const float4*)(bias + tx * 8);
    *(float4*)(&bs0[4]) = *(const float4*)(bias + tx * 8 + 4);

#pragma unroll
    for (int i = 0; i < 8; i++) {
        int m = bm + ty * 8 + i;
        if (m >= M) continue;
        float v[8];
#pragma unroll
        for (int jj = 0; jj < 4; jj++) {
            float lo, hi; unpack2(acc2[i][jj], lo, hi);
            v[2 * jj] = lo; v[2 * jj + 1] = hi;
        }
#pragma unroll
        for (int j = 0; j < 8; j++) {
            float x = v[j] + bs0[j];
            v[j] = x > 0.f ? x : 0.01f * x;   // leaky
        }
        float* cp = C + (size_t)m * ldc + tx * 8;
        *(float4*)(cp)     = *(float4*)(&v[0]);
        *(float4*)(cp + 4) = *(float4*)(&v[4]);
    }
}

// ---------------- fused dual-LSTM step kernel (FFMA2, R7-proven) ----------------
__device__ __forceinline__ float sigf(float x) { return 1.f / (1.f + expf(-x)); }

__global__ __launch_bounds__(256) void lstm_step2_kernel(
    const float* __restrict__ Xv, const float* __restrict__ Xs, int ldx,
    const float* __restrict__ Hv, const float* __restrict__ Hs,
    const float* __restrict__ Wcv, const float* __restrict__ Wcs,
    const float* __restrict__ bcv, const float* __restrict__ bcs,
    float* __restrict__ Cv, float* __restrict__ Cs,
    float* __restrict__ Hvo, float* __restrict__ Hso)
{
    __shared__ float As[2][16][128];
    __shared__ float Ws[2][16][128];

    const int sel = blockIdx.x >> 1;
    const float* X   = sel ? Xs  : Xv;
    const float* Hin = sel ? Hs  : Hv;
    const float* Wc  = sel ? Wcs : Wcv;
    const float* bc  = sel ? bcs : bcv;
    float* Cst  = sel ? Cs  : Cv;
    float* Hout = sel ? Hso : Hvo;

    const int M = CN;
    const int bm = blockIdx.y * 128;
    const int bn = (blockIdx.x & 1) * 128;
    const int tid = threadIdx.x;
    const int lr = tid >> 2;
    const int lk = (tid & 3) << 2;
    const int ty = tid >> 4, tx = tid & 15;

    ull acc2[8][4];
#pragma unroll
    for (int i = 0; i < 8; i++)
#pragma unroll
        for (int jj = 0; jj < 4; jj++) acc2[i][jj] = 0ull;

    int r0 = bm + lr;      r0 = r0 < M ? r0 : (M - 1);
    int r1 = bm + lr + 64; r1 = r1 < M ? r1 : (M - 1);

    float4 pa0, pa1, pw0, pw1;
    {
        int kg = lk;
        pa0 = (kg < 64) ? *(const float4*)(X + (size_t)r0 * ldx + kg)
                        : *(const float4*)(Hin + (size_t)r0 * 64 + (kg - 64));
        pa1 = (kg < 64) ? *(const float4*)(X + (size_t)r1 * ldx + kg)
                        : *(const float4*)(Hin + (size_t)r1 * 64 + (kg - 64));
        pw0 = *(const float4*)(Wc + (size_t)(bn + lr) * 128 + kg);
        pw1 = *(const float4*)(Wc + (size_t)(bn + lr + 64) * 128 + kg);
    }
    STORE_TILE(0)
    __syncthreads();

#pragma unroll
    for (int t = 0; t < 8; t++) {
        const int cur = t & 1, nxt = cur ^ 1;
        const bool has = t < 7;
        if (has) {
            int kg = ((t + 1) << 4) + lk;
            pa0 = (kg < 64) ? *(const float4*)(X + (size_t)r0 * ldx + kg)
                            : *(const float4*)(Hin + (size_t)r0 * 64 + (kg - 64));
            pa1 = (kg < 64) ? *(const float4*)(X + (size_t)r1 * ldx + kg)
                            : *(const float4*)(Hin + (size_t)r1 * 64 + (kg - 64));
            pw0 = *(const float4*)(Wc + (size_t)(bn + lr) * 128 + kg);
            pw1 = *(const float4*)(Wc + (size_t)(bn + lr + 64) * 128 + kg);
        }
        TILE_COMPUTE(cur)
        if (has) { STORE_TILE(nxt) }
        __syncthreads();
    }

    const int colbase = bn + tx * 8;
    const int u0 = colbase >> 2;
    float bb[8];
    *(float4*)(&bb[0]) = *(const float4*)(bc + colbase);
    *(float4*)(&bb[4]) = *(const float4*)(bc + colbase + 4);

#pragma unroll
    for (int i = 0; i < 8; i++) {
        int m = bm + ty * 8 + i;
        if (m >= M) continue;
        float g[8];
#pragma unroll
        for (int jj = 0; jj < 4; jj++) {
            float lo, hi; unpack2(acc2[i][jj], lo, hi);
            g[2 * jj] = lo + bb[2 * jj]; g[2 * jj + 1] = hi + bb[2 * jj + 1];
        }
        float2 cold = *(float2*)(Cst + (size_t)m * 64 + u0);
        float c0 = sigf(g[1]) * cold.x + sigf(g[0]) * tanhf(g[2]);
        float c1 = sigf(g[5]) * cold.y + sigf(g[4]) * tanhf(g[6]);
        float2 cn = make_float2(c0, c1);
        float2 hn = make_float2(sigf(g[3]) * tanhf(c0), sigf(g[7]) * tanhf(c1));
        *(float2*)(Cst + (size_t)m * 64 + u0) = cn;
        *(float2*)(Hout + (size_t)m * 64 + u0) = hn;
    }
}

// ---------------- small kernels ----------------
__global__ void zero_kernel(float* p, size_t n)
{
    size_t i = (size_t)blockIdx.x * blockDim.x + threadIdx.x;
    size_t stride = (size_t)gridDim.x * blockDim.x;
    for (; i < n; i += stride) p[i] = 0.f;
}

__global__ void prep_kernel(const float* __restrict__ Wih_v, const float* __restrict__ Whh_v,
                            const float* __restrict__ bih_v, const float* __restrict__ bhh_v,
                            const float* __restrict__ Wih_s, const float* __restrict__ Whh_s,
                            const float* __restrict__ bih_s, const float* __restrict__ bhh_s,
                            float* __restrict__ S)
{
    int idx = blockIdx.x * blockDim.x + threadIdx.x;
    if (idx < 256 * 128) {
        int o = idx >> 7, k = idx & 127;
        int u = o >> 2, g = o & 3;
        int orow = g * 64 + u;
        S[OFF_WCV + idx] = (k < 64) ? Wih_v[orow * 64 + k] : Whh_v[orow * 64 + (k - 64)];
        S[OFF_WCS + idx] = (k < 64) ? Wih_s[orow * 64 + k] : Whh_s[orow * 64 + (k - 64)];
        if (idx < 256) {
            int uu = idx >> 2, gg = idx & 3;
            int ob = gg * 64 + uu;
            S[OFF_BCV + idx] = bih_v[ob] + bhh_v[ob];
            S[OFF_BCS + idx] = bih_s[ob] + bhh_s[ob];
        }
    }
}

__global__ void copy_xp_kernel(float* __restrict__ S)
{
    size_t idx = (size_t)blockIdx.x * blockDim.x + threadIdx.x;
    if (idx >= (size_t)CN * 128) return;
    size_t n = idx >> 7;
    int j = (int)(idx & 127);
    S[OFF_XCAT + n * 512 + 384 + j] = S[OFF_XCAT + n * 512 + 128 + j];
}

__global__ void deg_kernel(const int* __restrict__ dst, float* __restrict__ deg)
{
    int e = blockIdx.x * blockDim.x + threadIdx.x;
    if (e < CE) atomicAdd(&deg[dst[e]], 1.0f);
}

// single-block exclusive scan of (int)deg -> off[0..CN], cur = off; also dinv
__global__ __launch_bounds__(1024) void scan_kernel(const float* __restrict__ deg,
                                                    int* __restrict__ off,
                                                    int* __restrict__ cur,
                                                    float* __restrict__ dinv)
{
    __shared__ int part[1024];
    const int tid = threadIdx.x;
    const int chunk = (CN + 1023) / 1024;
    const int start = tid * chunk;
    const int end = min(start + chunk, CN);
    int s = 0;
    for (int i = start; i < end; i++) s += (int)deg[i];
    part[tid] = s;
    __syncthreads();
    for (int d = 1; d < 1024; d <<= 1) {
        int v = (tid >= d) ? part[tid - d] : 0;
        __syncthreads();
        part[tid] += v;
        __syncthreads();
    }
    int pre = (tid == 0) ? 0 : part[tid - 1];
    for (int i = start; i < end; i++) {
        off[i] = pre;
        cur[i] = pre;
        float dg = deg[i];
        dinv[i] = rsqrtf(fmaxf(dg, 1.0f));
        pre += (int)dg;
    }
    if (tid == 1023) off[CN] = pre;
}

__global__ void fill_kernel(const int* __restrict__ src, const int* __restrict__ dst,
                            int* __restrict__ cur, int* __restrict__ csr)
{
    int e = blockIdx.x * blockDim.x + threadIdx.x;
    if (e < CE) {
        int d = dst[e];
        int pos = atomicAdd(&cur[d], 1);
        csr[pos] = src[e];
    }
}

// gather propagation: out[n] = pin[n] - dinv[n] * sum_{s in N(n)} pin[s]*dinv[s]
__global__ __launch_bounds__(256) void prop_kernel(
    const float* __restrict__ pin, int ldin,
    const int* __restrict__ csr, const int* __restrict__ off,
    const float* __restrict__ dinv, float* __restrict__ outp)
{
    const int n = blockIdx.x * 8 + (threadIdx.x >> 5);
    if (n >= CN) return;
    const int lane = threadIdx.x & 31;
    const int col = lane * 4;
    float4 acc = make_float4(0.f, 0.f, 0.f, 0.f);
    const int s0 = off[n], s1 = off[n + 1];
    for (int e = s0; e < s1; e++) {
        int sn = csr[e];
        float ds = __ldg(&dinv[sn]);
        float4 v = *(const float4*)(pin + (size_t)sn * ldin + col);
        acc.x += v.x * ds; acc.y += v.y * ds; acc.z += v.z * ds; acc.w += v.w * ds;
    }
    const float dn = dinv[n];
    float4 pv = *(const float4*)(pin + (size_t)n * ldin + col);
    float4 o = make_float4(pv.x - acc.x * dn, pv.y - acc.y * dn,
                           pv.z - acc.z * dn, pv.w - acc.w * dn);
    *(float4*)(outp + (size_t)n * 128 + col) = o;
}

// second propagation fused with filter construction
__global__ __launch_bounds__(256) void prop2F_kernel(
    const float* __restrict__ p1,
    const float* __restrict__ p0, int ld0,
    const int* __restrict__ csr, const int* __restrict__ off,
    const float* __restrict__ dinv, float* __restrict__ F)
{
    const int n = blockIdx.x * 8 + (threadIdx.x >> 5);
    if (n >= CN) return;
    const int lane = threadIdx.x & 31;
    const int col = lane * 4;
    float4 acc = make_float4(0.f, 0.f, 0.f, 0.f);
    const int s0 = off[n], s1 = off[n + 1];
    for (int e = s0; e < s1; e++) {
        int sn = csr[e];
        float ds = __ldg(&dinv[sn]);
        float4 v = *(const float4*)(p1 + (size_t)sn * 128 + col);
        acc.x += v.x * ds; acc.y += v.y * ds; acc.z += v.z * ds; acc.w += v.w * ds;
    }
    const float dn = dinv[n];
    float4 b = *(const float4*)(p1 + (size_t)n * 128 + col);
    float4 a = *(const float4*)(p0 + (size_t)n * ld0 + col);
    float4 c = make_float4(b.x - acc.x * dn, b.y - acc.y * dn,
                           b.z - acc.z * dn, b.w - acc.w * dn);
    float* Fb = F + (size_t)n * 640 + col;
    float4 f0 = make_float4(0.8f * a.x - 0.5f * b.x, 0.8f * a.y - 0.5f * b.y,
                            0.8f * a.z - 0.5f * b.z, 0.8f * a.w - 0.5f * b.w);
    float4 f1 = make_float4(3.0f * a.x - 3.0f * b.x + 0.75f * c.x,
                            3.0f * a.y - 3.0f * b.y + 0.75f * c.y,
                            3.0f * a.z - 3.0f * b.z + 0.75f * c.z,
                            3.0f * a.w - 3.0f * b.w + 0.75f * c.w);
    float4 f2 = make_float4(3.0f * b.x - 1.5f * c.x, 3.0f * b.y - 1.5f * c.y,
                            3.0f * b.z - 1.5f * c.z, 3.0f * b.w - 1.5f * c.w);
    float4 f3 = make_float4(0.75f * c.x, 0.75f * c.y, 0.75f * c.z, 0.75f * c.w);
    float4 f4 = make_float4(-0.2f * a.x + 0.5f * b.x, -0.2f * a.y + 0.5f * b.y,
                            -0.2f * a.z + 0.5f * b.z, -0.2f * a.w + 0.5f * b.w);
    *(float4*)(Fb)       = f0;
    *(float4*)(Fb + 128) = f1;
    *(float4*)(Fb + 256) = f2;
    *(float4*)(Fb + 384) = f3;
    *(float4*)(Fb + 512) = f4;
}

// softmax over 5 per-node scores, in place (scores -> weights)
__global__ void attn_sm_kernel(float* __restrict__ score)
{
    int n = blockIdx.x * blockDim.x + threadIdx.x;
    if (n >= CN) return;
    float sc[5];
#pragma unroll
    for (int f = 0; f < 5; f++) sc[f] = score[(size_t)n * 5 + f];
    float mx = sc[0];
#pragma unroll
    for (int f = 1; f < 5; f++) mx = fmaxf(mx, sc[f]);
    float e[5], s = 0.f;
#pragma unroll
    for (int f = 0; f < 5; f++) { e[f] = expf(sc[f] - mx); s += e[f]; }
    float inv = 1.f / s;
#pragma unroll
    for (int f = 0; f < 5; f++) score[(size_t)n * 5 + f] = e[f] * inv;
}

// out[n, c] = big[n, :] . W6[c, :] + b6[c], warp per node
__global__ void final_kernel(const float* __restrict__ big, const float* __restrict__ W6,
                             const float* __restrict__ b6, float* __restrict__ out)
{
    size_t gid = (size_t)blockIdx.x * blockDim.x + threadIdx.x;
    int n = (int)(gid >> 5);
    int lane = (int)(gid & 31);
    if (n >= CN) return;
    const float* row = big + (size_t)n * 768;
#pragma unroll
    for (int c = 0; c < 2; c++) {
        float a = 0.f;
        for (int j = lane; j < 768; j += 32) a += row[j] * W6[c * 768 + j];
#pragma unroll
        for (int off = 16; off; off >>= 1) a += __shfl_xor_sync(0xffffffffu, a, off);
        if (lane == 0) out[(size_t)n * 2 + c] = a + b6[c];
    }
}

// ---------------- orchestration ----------------
extern "C" void kernel_launch(void* const* d_in, const int* in_sizes, int n_in,
                              void* d_out, int out_size)
{
    const float* voc    = (const float*)d_in[0];
    const float* sms    = (const float*)d_in[1];
    const float* pers   = (const float*)d_in[2];
    const float* Wih_v  = (const float*)d_in[3];
    const float* Whh_v  = (const float*)d_in[4];
    const float* bih_v  = (const float*)d_in[5];
    const float* bhh_v  = (const float*)d_in[6];
    const float* Wih_s  = (const float*)d_in[7];
    const float* Whh_s  = (const float*)d_in[8];
    const float* bih_s  = (const float*)d_in[9];
    const float* bhh_s  = (const float*)d_in[10];
    const float* W_lin  = (const float*)d_in[11];
    const float* b_lin  = (const float*)d_in[12];
    const float* W_lin1 = (const float*)d_in[13];
    const float* b_lin1 = (const float*)d_in[14];
    const float* W_pers = (const float*)d_in[15];
    const float* b_pers = (const float*)d_in[16];
    const float* W_lin2 = (const float*)d_in[17];
    const float* b_lin2 = (const float*)d_in[18];
    const float* W_lin3 = (const float*)d_in[19];
    const float* b_lin3 = (const float*)d_in[20];
    const float* W_lin4 = (const float*)d_in[21];
    const float* b_lin4 = (const float*)d_in[22];
    const float* W_lin5 = (const float*)d_in[23];
    const float* b_lin5 = (const float*)d_in[24];
    const float* Wf1    = (const float*)d_in[25];
    const float* bf1    = (const float*)d_in[26];
    const float* Wf2    = (const float*)d_in[27];
    const float* W_lin6 = (const float*)d_in[28];
    const float* b_lin6 = (const float*)d_in[29];
    const int*   src    = (const int*)d_in[30];
    const int*   dst    = (const int*)d_in[31];
    float* out = (float*)d_out;

    float* S = nullptr;
    cudaGetSymbolAddress((void**)&S, g_scratch);
    int* csr = nullptr; cudaGetSymbolAddress((void**)&csr, g_csr);
    int* offp = nullptr; cudaGetSymbolAddress((void**)&offp, g_off);
    int* curp = nullptr; cudaGetSymbolAddress((void**)&curp, g_cur);

    // prep: interleaved LSTM weights/biases, zero states (HV0,HV1,HS0,HS1,CV,CS)
    prep_kernel<<<(256 * 128 + 255) / 256, 256>>>(Wih_v, Whh_v, bih_v, bhh_v,
                                                  Wih_s, Whh_s, bih_s, bhh_s, S);
    zero_kernel<<<4096, 256>>>(S + OFF_HV0, (size_t)6 * CN * 64);

    // ---- LSTMs: 16 steps, both LSTMs per launch, fused GEMM+cell ----
    dim3 lgrid(4, (CN + 127) / 128);
    for (int t = 0; t < CT; t++) {
        const float* hv_in  = S + ((t & 1) ? OFF_HV1 : OFF_HV0);
        float*       hv_out = S + ((t & 1) ? OFF_HV0 : OFF_HV1);
        const float* hs_in  = S + ((t & 1) ? OFF_HS1 : OFF_HS0);
        float*       hs_out = S + ((t & 1) ? OFF_HS0 : OFF_HS1);
        lstm_step2_kernel<<<lgrid, 256>>>(voc + (size_t)t * 64, sms + (size_t)t * 64, CT * 64,
                                          hv_in, hs_in,
                                          S + OFF_WCV, S + OFF_WCS,
                                          S + OFF_BCV, S + OFF_BCS,
                                          S + OFF_CV, S + OFF_CS,
                                          hv_out, hs_out);
    }

    // ---- projections ----
    gemm(S + OFF_HV0, 64, 64, S + OFF_HV0, 64, W_lin, b_lin,
         S + OFF_XCAT + 0, 512, CN, 128, 64, 1);
    gemm(S + OFF_HS0, 64, 64, S + OFF_HS0, 64, W_lin1, b_lin1,
         S + OFF_XCAT + 256, 512, CN, 128, 64, 1);
    gemm(pers, 32, 32, pers, 32, W_pers, b_pers,
         S + OFF_XCAT + 128, 512, CN, 128, 32, 1);
    copy_xp_kernel<<<((size_t)CN * 128 + 255) / 256, 256>>>(S);

    gemm(S + OFF_XCAT, 512, 256, S + OFF_XCAT, 512, W_lin2, b_lin2,
         S + OFF_BIG + 384, 768, CN, 128, 256, 1);
    gemm(S + OFF_XCAT + 256, 512, 256, S + OFF_XCAT + 256, 512, W_lin3, b_lin3,
         S + OFF_BIG + 512, 768, CN, 128, 256, 1);
    gemm(S + OFF_XCAT, 512, 512, S + OFF_XCAT, 512, W_lin4, b_lin4,
         S + OFF_BIG + 640, 768, CN, 128, 512, 1);

    // ---- relation graphs (CSR gather-based propagation) ----
    const int pgrid = (CN + 7) / 8;
    for (int r = 0; r < CR; r++) {
        const int* sr = src + (size_t)r * CE;
        const int* dr = dst + (size_t)r * CE;
        const float* p0 = S + OFF_BIG + 384 + 128 * r;  // lda 768

        zero_kernel<<<256, 256>>>(S + OFF_DEG, (size_t)CN);
        deg_kernel<<<(CE + 255) / 256, 256>>>(dr, S + OFF_DEG);
        scan_kernel<<<1, 1024>>>(S + OFF_DEG, offp, curp, S + OFF_DINV);
        fill_kernel<<<(CE + 255) / 256, 256>>>(sr, dr, curp, csr);

        prop_kernel<<<pgrid, 256>>>(p0, 768, csr, offp, S + OFF_DINV, S + OFF_P1);
        prop2F_kernel<<<pgrid, 256>>>(S + OFF_P1, p0, 768, csr, offp,
                                      S + OFF_DINV, S + OFF_F);

        // scores = w2 . tanh(F @ Wf1^T + bf1) fused (Y never materialized)
        {
            dim3 sgrid(1, (CN * 5 + 127) / 128);
            sgemm_score_kernel<<<sgrid, 256>>>(S + OFF_F, 128,
                                               Wf1 + (size_t)r * 128 * 128,
                                               bf1 + (size_t)r * 128,
                                               Wf2 + (size_t)r * 128,
                                               S + OFF_SC, CN * 5);
        }
        // softmax in place
        attn_sm_kernel<<<(CN + 255) / 256, 256>>>(S + OFF_SC);

        // hall_r = act((soft . F) @ W_lin5[r]^T + b_lin5[r]) -> big cols [128r,+128)
        {
            dim3 agrid(1, (CN + 127) / 128);
            sgemm_attn_kernel<<<agrid, 256>>>(S + OFF_F, S + OFF_SC,
                                              W_lin5 + (size_t)r * 128 * 128,
                                              b_lin5 + (size_t)r * 128,
                                              S + OFF_BIG + 128 * r, 768, CN);
        }
    }

    // ---- final head ----
    final_kernel<<<((size_t)CN * 32 + 255) / 256, 256>>>(S + OFF_BIG, W_lin6, b_lin6, out);
}

// round 10
// speedup vs baseline: 1.5223x; 1.0444x over previous
#include <cuda_runtime.h>
#include <math.h>
#include <stdint.h>

// Problem constants
#define CN 50000
#define CE 800000
#define CR 3
#define CT 16

typedef unsigned long long ull;

__device__ __forceinline__ ull pack2(float lo, float hi) {
    ull r; asm("mov.b64 %0, {%1,%2};" : "=l"(r) : "f"(lo), "f"(hi)); return r;
}
__device__ __forceinline__ ull fma2(ull a, ull b, ull c) {
    ull d; asm("fma.rn.f32x2 %0, %1, %2, %3;" : "=l"(d) : "l"(a), "l"(b), "l"(c)); return d;
}
__device__ __forceinline__ void unpack2(ull v, float& lo, float& hi) {
    asm("mov.b64 {%0,%1}, %2;" : "=f"(lo), "=f"(hi) : "l"(v));
}

// ---------------- scratch layout (floats) ----------------
constexpr size_t SZ_WCAT = 256 * 128;
constexpr size_t OFF_WCV = 0;
constexpr size_t OFF_WCS = OFF_WCV + SZ_WCAT;
constexpr size_t OFF_BCV = OFF_WCS + SZ_WCAT;
constexpr size_t OFF_BCS = OFF_BCV + 256;
constexpr size_t OFF_HV0 = OFF_BCS + 256;                 // N*64 each
constexpr size_t OFF_HV1 = OFF_HV0 + (size_t)CN * 64;
constexpr size_t OFF_HS0 = OFF_HV1 + (size_t)CN * 64;
constexpr size_t OFF_HS1 = OFF_HS0 + (size_t)CN * 64;
constexpr size_t OFF_CV  = OFF_HS1 + (size_t)CN * 64;
constexpr size_t OFF_CS  = OFF_CV + (size_t)CN * 64;
constexpr size_t OFF_XCAT= OFF_CS + (size_t)CN * 64;      // [xv|xp|xs|xp] N*512
constexpr size_t OFF_BIG = OFF_XCAT + (size_t)CN * 512;   // [hall0..2, xin0..2] N*768
constexpr size_t OFF_P1  = OFF_BIG + (size_t)CN * 768;    // N*128
constexpr size_t OFF_P2  = OFF_P1 + (size_t)CN * 128;     // N*128
constexpr size_t OFF_YA  = OFF_P2 + (size_t)CN * 128;     // N*128 x3 (contiguous)
constexpr size_t OFF_YB  = OFF_YA + (size_t)CN * 128;
constexpr size_t OFF_YC  = OFF_YB + (size_t)CN * 128;
constexpr size_t OFF_RES = OFF_YC + (size_t)CN * 128;     // N*128
constexpr size_t OFF_DEG = OFF_RES + (size_t)CN * 128;    // N
constexpr size_t OFF_DINV= OFF_DEG + CN;                  // N
constexpr size_t SCRATCH_TOTAL = OFF_DINV + CN + 64;

__device__ float g_scratch[SCRATCH_TOTAL];
__device__ int g_csr[CE];
__device__ int g_off[CN + 1];
__device__ int g_cur[CN];

// THETAS coefficients on (p0, p1, p2)
__device__ __constant__ float c_th0[5] = {0.8f, 3.0f, 0.0f, 0.0f, -0.2f};
__device__ __constant__ float c_th1[5] = {-0.5f, -3.0f, 3.0f, 0.0f, 0.5f};
__device__ __constant__ float c_th2[5] = {0.0f, 0.75f, -1.5f, 0.75f, 0.0f};

// =====================================================================
// FFMA2 GEMM core (PROVEN R7 shape): 128x128 tile, BK=16, double-buffered,
// 256 threads, 8x8/thread; acc2[i][jj] packs output cols (2jj, 2jj+1).
// =====================================================================
#define TILE_COMPUTE(cur)                                                      \
    _Pragma("unroll")                                                          \
    for (int kk = 0; kk < 16; kk++) {                                          \
        float a[8]; ull b2[4];                                                 \
        *(float4*)(&a[0]) = *(const float4*)(&As[cur][kk][ty * 8]);            \
        *(float4*)(&a[4]) = *(const float4*)(&As[cur][kk][ty * 8 + 4]);        \
        {                                                                      \
            const ulonglong2* wp = (const ulonglong2*)(&Ws[cur][kk][tx * 8]);  \
            ulonglong2 w0 = wp[0]; ulonglong2 w1 = wp[1];                      \
            b2[0] = w0.x; b2[1] = w0.y; b2[2] = w1.x; b2[3] = w1.y;            \
        }                                                                      \
        _Pragma("unroll")                                                      \
        for (int i = 0; i < 8; i++) {                                          \
            ull ai = pack2(a[i], a[i]);                                        \
            _Pragma("unroll")                                                  \
            for (int jj = 0; jj < 4; jj++)                                     \
                acc2[i][jj] = fma2(ai, b2[jj], acc2[i][jj]);                   \
        }                                                                      \
    }

#define STORE_TILE(buf)                                                                         \
    As[buf][lk+0][lr] = pa0.x; As[buf][lk+1][lr] = pa0.y;                                       \
    As[buf][lk+2][lr] = pa0.z; As[buf][lk+3][lr] = pa0.w;                                       \
    As[buf][lk+0][lr+64] = pa1.x; As[buf][lk+1][lr+64] = pa1.y;                                 \
    As[buf][lk+2][lr+64] = pa1.z; As[buf][lk+3][lr+64] = pa1.w;                                 \
    Ws[buf][lk+0][lr] = pw0.x; Ws[buf][lk+1][lr] = pw0.y;                                       \
    Ws[buf][lk+2][lr] = pw0.z; Ws[buf][lk+3][lr] = pw0.w;                                       \
    Ws[buf][lk+0][lr+64] = pw1.x; Ws[buf][lk+1][lr+64] = pw1.y;                                 \
    Ws[buf][lk+2][lr+64] = pw1.z; Ws[buf][lk+3][lr+64] = pw1.w;

// ---------------- generic SGEMM:  C = act(A @ W^T + bias) ----------------
__global__ __launch_bounds__(256) void sgemm_kernel(
    const float* __restrict__ A, int lda, int K1,
    const float* __restrict__ A2, int lda2,
    const float* __restrict__ W,
    const float* __restrict__ bias,
    float* __restrict__ C, int ldc,
    int M, int K, int act)
{
    __shared__ float As[2][16][128];
    __shared__ float Ws[2][16][128];

    const int bm = blockIdx.y * 128;
    const int bn = blockIdx.x * 128;
    const int tid = threadIdx.x;
    const int lr = tid >> 2;
    const int lk = (tid & 3) << 2;
    const int ty = tid >> 4, tx = tid & 15;

    ull acc2[8][4];
#pragma unroll
    for (int i = 0; i < 8; i++)
#pragma unroll
        for (int jj = 0; jj < 4; jj++) acc2[i][jj] = 0ull;

    int r0 = bm + lr;      r0 = r0 < M ? r0 : (M - 1);
    int r1 = bm + lr + 64; r1 = r1 < M ? r1 : (M - 1);

    float4 pa0, pa1, pw0, pw1;
    {
        int kg = lk;
        pa0 = (kg < K1) ? *(const float4*)(A + (size_t)r0 * lda + kg)
                        : *(const float4*)(A2 + (size_t)r0 * lda2 + (kg - K1));
        pa1 = (kg < K1) ? *(const float4*)(A + (size_t)r1 * lda + kg)
                        : *(const float4*)(A2 + (size_t)r1 * lda2 + (kg - K1));
        pw0 = *(const float4*)(W + (size_t)(bn + lr) * K + kg);
        pw1 = *(const float4*)(W + (size_t)(bn + lr + 64) * K + kg);
    }
    STORE_TILE(0)
    __syncthreads();

    const int ntiles = K >> 4;
    for (int t = 0; t < ntiles; t++) {
        const int cur = t & 1, nxt = cur ^ 1;
        const bool has = (t + 1) < ntiles;
        if (has) {
            int kg = ((t + 1) << 4) + lk;
            pa0 = (kg < K1) ? *(const float4*)(A + (size_t)r0 * lda + kg)
                            : *(const float4*)(A2 + (size_t)r0 * lda2 + (kg - K1));
            pa1 = (kg < K1) ? *(const float4*)(A + (size_t)r1 * lda + kg)
                            : *(const float4*)(A2 + (size_t)r1 * lda2 + (kg - K1));
            pw0 = *(const float4*)(W + (size_t)(bn + lr) * K + kg);
            pw1 = *(const float4*)(W + (size_t)(bn + lr + 64) * K + kg);
        }
        TILE_COMPUTE(cur)
        if (has) { STORE_TILE(nxt) }
        __syncthreads();
    }

    float bs0[8];
    *(float4*)(&bs0[0]) = *(const float4*)(bias + bn + tx * 8);
    *(float4*)(&bs0[4]) = *(const float4*)(bias + bn + tx * 8 + 4);

#pragma unroll
    for (int i = 0; i < 8; i++) {
        int m = bm + ty * 8 + i;
        if (m >= M) continue;
        float v[8];
#pragma unroll
        for (int jj = 0; jj < 4; jj++) {
            float lo, hi; unpack2(acc2[i][jj], lo, hi);
            v[2 * jj] = lo; v[2 * jj + 1] = hi;
        }
#pragma unroll
        for (int j = 0; j < 8; j++) {
            float x = v[j] + bs0[j];
            if (act == 1)      x = x > 0.f ? x : 0.01f * x;
            else if (act == 2) x = tanhf(x);
            v[j] = x;
        }
        float* cp = C + (size_t)m * ldc + bn + tx * 8;
        *(float4*)(cp)     = *(float4*)(&v[0]);
        *(float4*)(cp + 4) = *(float4*)(&v[4]);
    }
}

static inline void gemm(const float* A, int lda, int K1,
                        const float* A2, int lda2,
                        const float* W, const float* bias,
                        float* C, int ldc, int M, int O, int K, int act)
{
    dim3 grid(O / 128, (M + 127) / 128);
    sgemm_kernel<<<grid, 256>>>(A, lda, K1, A2, lda2, W, bias, C, ldc, M, K, act);
}

// ---------------- Yabc GEMM: Y_sel = A_sel @ Wf1^T  (no bias/act) ------------
// grid (3, 391). sel: 0 -> p0 (lda0), 1 -> p1 (128), 2 -> p2 (128).
// Y outputs contiguous: Y + sel*N*128.
__global__ __launch_bounds__(256) void yabc_kernel(
    const float* __restrict__ P0, int lda0,
    const float* __restrict__ P1,
    const float* __restrict__ P2,
    const float* __restrict__ W,
    float* __restrict__ Y)
{
    __shared__ float As[2][16][128];
    __shared__ float Ws[2][16][128];

    const int sel = blockIdx.x;
    const float* A = sel == 0 ? P0 : (sel == 1 ? P1 : P2);
    const int lda = sel == 0 ? lda0 : 128;
    float* C = Y + (size_t)sel * CN * 128;

    const int M = CN;
    const int bm = blockIdx.y * 128;
    const int tid = threadIdx.x;
    const int lr = tid >> 2;
    const int lk = (tid & 3) << 2;
    const int ty = tid >> 4, tx = tid & 15;
    const int K = 128;

    ull acc2[8][4];
#pragma unroll
    for (int i = 0; i < 8; i++)
#pragma unroll
        for (int jj = 0; jj < 4; jj++) acc2[i][jj] = 0ull;

    int r0 = bm + lr;      r0 = r0 < M ? r0 : (M - 1);
    int r1 = bm + lr + 64; r1 = r1 < M ? r1 : (M - 1);

    float4 pa0, pa1, pw0, pw1;
    {
        int kg = lk;
        pa0 = *(const float4*)(A + (size_t)r0 * lda + kg);
        pa1 = *(const float4*)(A + (size_t)r1 * lda + kg);
        pw0 = *(const float4*)(W + (size_t)lr * K + kg);
        pw1 = *(const float4*)(W + (size_t)(lr + 64) * K + kg);
    }
    STORE_TILE(0)
    __syncthreads();

#pragma unroll
    for (int t = 0; t < 8; t++) {
        const int cur = t & 1, nxt = cur ^ 1;
        const bool has = t < 7;
        if (has) {
            int kg = ((t + 1) << 4) + lk;
            pa0 = *(const float4*)(A + (size_t)r0 * lda + kg);
            pa1 = *(const float4*)(A + (size_t)r1 * lda + kg);
            pw0 = *(const float4*)(W + (size_t)lr * K + kg);
            pw1 = *(const float4*)(W + (size_t)(lr + 64) * K + kg);
        }
        TILE_COMPUTE(cur)
        if (has) { STORE_TILE(nxt) }
        __syncthreads();
    }

#pragma unroll
    for (int i = 0; i < 8; i++) {
        int m = bm + ty * 8 + i;
        if (m >= M) continue;
        float v[8];
#pragma unroll
        for (int jj = 0; jj < 4; jj++) {
            float lo, hi; unpack2(acc2[i][jj], lo, hi);
            v[2 * jj] = lo; v[2 * jj + 1] = hi;
        }
        float* cp = C + (size_t)m * 128 + tx * 8;
        *(float4*)(cp)     = *(float4*)(&v[0]);
        *(float4*)(cp + 4) = *(float4*)(&v[4]);
    }
}

// ---------------- fused dual-LSTM step kernel (FFMA2, R7-proven) ----------------
__device__ __forceinline__ float sigf(float x) { return 1.f / (1.f + expf(-x)); }

__global__ __launch_bounds__(256) void lstm_step2_kernel(
    const float* __restrict__ Xv, const float* __restrict__ Xs, int ldx,
    const float* __restrict__ Hv, const float* __restrict__ Hs,
    const float* __restrict__ Wcv, const float* __restrict__ Wcs,
    const float* __restrict__ bcv, const float* __restrict__ bcs,
    float* __restrict__ Cv, float* __restrict__ Cs,
    float* __restrict__ Hvo, float* __restrict__ Hso)
{
    __shared__ float As[2][16][128];
    __shared__ float Ws[2][16][128];

    const int sel = blockIdx.x >> 1;
    const float* X   = sel ? Xs  : Xv;
    const float* Hin = sel ? Hs  : Hv;
    const float* Wc  = sel ? Wcs : Wcv;
    const float* bc  = sel ? bcs : bcv;
    float* Cst  = sel ? Cs  : Cv;
    float* Hout = sel ? Hso : Hvo;

    const int M = CN;
    const int bm = blockIdx.y * 128;
    const int bn = (blockIdx.x & 1) * 128;
    const int tid = threadIdx.x;
    const int lr = tid >> 2;
    const int lk = (tid & 3) << 2;
    const int ty = tid >> 4, tx = tid & 15;

    ull acc2[8][4];
#pragma unroll
    for (int i = 0; i < 8; i++)
#pragma unroll
        for (int jj = 0; jj < 4; jj++) acc2[i][jj] = 0ull;

    int r0 = bm + lr;      r0 = r0 < M ? r0 : (M - 1);
    int r1 = bm + lr + 64; r1 = r1 < M ? r1 : (M - 1);

    float4 pa0, pa1, pw0, pw1;
    {
        int kg = lk;
        pa0 = (kg < 64) ? *(const float4*)(X + (size_t)r0 * ldx + kg)
                        : *(const float4*)(Hin + (size_t)r0 * 64 + (kg - 64));
        pa1 = (kg < 64) ? *(const float4*)(X + (size_t)r1 * ldx + kg)
                        : *(const float4*)(Hin + (size_t)r1 * 64 + (kg - 64));
        pw0 = *(const float4*)(Wc + (size_t)(bn + lr) * 128 + kg);
        pw1 = *(const float4*)(Wc + (size_t)(bn + lr + 64) * 128 + kg);
    }
    STORE_TILE(0)
    __syncthreads();

#pragma unroll
    for (int t = 0; t < 8; t++) {
        const int cur = t & 1, nxt = cur ^ 1;
        const bool has = t < 7;
        if (has) {
            int kg = ((t + 1) << 4) + lk;
            pa0 = (kg < 64) ? *(const float4*)(X + (size_t)r0 * ldx + kg)
                            : *(const float4*)(Hin + (size_t)r0 * 64 + (kg - 64));
            pa1 = (kg < 64) ? *(const float4*)(X + (size_t)r1 * ldx + kg)
                            : *(const float4*)(Hin + (size_t)r1 * 64 + (kg - 64));
            pw0 = *(const float4*)(Wc + (size_t)(bn + lr) * 128 + kg);
            pw1 = *(const float4*)(Wc + (size_t)(bn + lr + 64) * 128 + kg);
        }
        TILE_COMPUTE(cur)
        if (has) { STORE_TILE(nxt) }
        __syncthreads();
    }

    const int colbase = bn + tx * 8;
    const int u0 = colbase >> 2;
    float bb[8];
    *(float4*)(&bb[0]) = *(const float4*)(bc + colbase);
    *(float4*)(&bb[4]) = *(const float4*)(bc + colbase + 4);

#pragma unroll
    for (int i = 0; i < 8; i++) {
        int m = bm + ty * 8 + i;
        if (m >= M) continue;
        float g[8];
#pragma unroll
        for (int jj = 0; jj < 4; jj++) {
            float lo, hi; unpack2(acc2[i][jj], lo, hi);
            g[2 * jj] = lo + bb[2 * jj]; g[2 * jj + 1] = hi + bb[2 * jj + 1];
        }
        float2 cold = *(float2*)(Cst + (size_t)m * 64 + u0);
        float c0 = sigf(g[1]) * cold.x + sigf(g[0]) * tanhf(g[2]);
        float c1 = sigf(g[5]) * cold.y + sigf(g[4]) * tanhf(g[6]);
        float2 cn = make_float2(c0, c1);
        float2 hn = make_float2(sigf(g[3]) * tanhf(c0), sigf(g[7]) * tanhf(c1));
        *(float2*)(Cst + (size_t)m * 64 + u0) = cn;
        *(float2*)(Hout + (size_t)m * 64 + u0) = hn;
    }
}

// ---------------- small kernels ----------------
__global__ void zero_kernel(float* p, size_t n)
{
    size_t i = (size_t)blockIdx.x * blockDim.x + threadIdx.x;
    size_t stride = (size_t)gridDim.x * blockDim.x;
    for (; i < n; i += stride) p[i] = 0.f;
}

__global__ void prep_kernel(const float* __restrict__ Wih_v, const float* __restrict__ Whh_v,
                            const float* __restrict__ bih_v, const float* __restrict__ bhh_v,
                            const float* __restrict__ Wih_s, const float* __restrict__ Whh_s,
                            const float* __restrict__ bih_s, const float* __restrict__ bhh_s,
                            float* __restrict__ S)
{
    int idx = blockIdx.x * blockDim.x + threadIdx.x;
    if (idx < 256 * 128) {
        int o = idx >> 7, k = idx & 127;
        int u = o >> 2, g = o & 3;
        int orow = g * 64 + u;
        S[OFF_WCV + idx] = (k < 64) ? Wih_v[orow * 64 + k] : Whh_v[orow * 64 + (k - 64)];
        S[OFF_WCS + idx] = (k < 64) ? Wih_s[orow * 64 + k] : Whh_s[orow * 64 + (k - 64)];
        if (idx < 256) {
            int uu = idx >> 2, gg = idx & 3;
            int ob = gg * 64 + uu;
            S[OFF_BCV + idx] = bih_v[ob] + bhh_v[ob];
            S[OFF_BCS + idx] = bih_s[ob] + bhh_s[ob];
        }
    }
}

__global__ void copy_xp_kernel(float* __restrict__ S)
{
    size_t idx = (size_t)blockIdx.x * blockDim.x + threadIdx.x;
    if (idx >= (size_t)CN * 128) return;
    size_t n = idx >> 7;
    int j = (int)(idx & 127);
    S[OFF_XCAT + n * 512 + 384 + j] = S[OFF_XCAT + n * 512 + 128 + j];
}

__global__ void deg_kernel(const int* __restrict__ dst, float* __restrict__ deg)
{
    int e = blockIdx.x * blockDim.x + threadIdx.x;
    if (e < CE) atomicAdd(&deg[dst[e]], 1.0f);
}

// single-block exclusive scan of (int)deg -> off[0..CN], cur = off; also dinv
__global__ __launch_bounds__(1024) void scan_kernel(const float* __restrict__ deg,
                                                    int* __restrict__ off,
                                                    int* __restrict__ cur,
                                                    float* __restrict__ dinv)
{
    __shared__ int part[1024];
    const int tid = threadIdx.x;
    const int chunk = (CN + 1023) / 1024;
    const int start = tid * chunk;
    const int end = min(start + chunk, CN);
    int s = 0;
    for (int i = start; i < end; i++) s += (int)deg[i];
    part[tid] = s;
    __syncthreads();
    for (int d = 1; d < 1024; d <<= 1) {
        int v = (tid >= d) ? part[tid - d] : 0;
        __syncthreads();
        part[tid] += v;
        __syncthreads();
    }
    int pre = (tid == 0) ? 0 : part[tid - 1];
    for (int i = start; i < end; i++) {
        off[i] = pre;
        cur[i] = pre;
        float dg = deg[i];
        dinv[i] = rsqrtf(fmaxf(dg, 1.0f));
        pre += (int)dg;
    }
    if (tid == 1023) off[CN] = pre;
}

__global__ void fill_kernel(const int* __restrict__ src, const int* __restrict__ dst,
                            int* __restrict__ cur, int* __restrict__ csr)
{
    int e = blockIdx.x * blockDim.x + threadIdx.x;
    if (e < CE) {
        int d = dst[e];
        int pos = atomicAdd(&cur[d], 1);
        csr[pos] = src[e];
    }
}

// gather propagation: out[n] = pin[n] - dinv[n] * sum_{s in N(n)} pin[s]*dinv[s]
__global__ __launch_bounds__(256) void prop_kernel(
    const float* __restrict__ pin, int ldin,
    const int* __restrict__ csr, const int* __restrict__ off,
    const float* __restrict__ dinv, float* __restrict__ outp)
{
    const int n = blockIdx.x * 8 + (threadIdx.x >> 5);
    if (n >= CN) return;
    const int lane = threadIdx.x & 31;
    const int col = lane * 4;
    float4 acc = make_float4(0.f, 0.f, 0.f, 0.f);
    const int s0 = off[n], s1 = off[n + 1];
    for (int e = s0; e < s1; e++) {
        int sn = csr[e];
        float ds = __ldg(&dinv[sn]);
        float4 v = *(const float4*)(pin + (size_t)sn * ldin + col);
        acc.x += v.x * ds; acc.y += v.y * ds; acc.z += v.z * ds; acc.w += v.w * ds;
    }
    const float dn = dinv[n];
    float4 pv = *(const float4*)(pin + (size_t)n * ldin + col);
    float4 o = make_float4(pv.x - acc.x * dn, pv.y - acc.y * dn,
                           pv.z - acc.z * dn, pv.w - acc.w * dn);
    *(float4*)(outp + (size_t)n * 128 + col) = o;
}

// combine: per node, build the 5 filter scores from Ya,Yb,Yc, softmax,
// then res = ca*p0 + cb*p1 + cc*p2. Warp per node.
__global__ __launch_bounds__(256) void attn_comb_kernel(
    const float* __restrict__ Y,             // [3][N][128]
    const float* __restrict__ P0, int ld0,
    const float* __restrict__ P1,
    const float* __restrict__ P2,
    const float* __restrict__ bf1,           // 128
    const float* __restrict__ w2,            // 128
    float* __restrict__ res)
{
    const int n = blockIdx.x * 8 + (threadIdx.x >> 5);
    if (n >= CN) return;
    const int lane = threadIdx.x & 31;
    const int col = lane * 4;

    float4 ya = *(const float4*)(Y + (size_t)n * 128 + col);
    float4 yb = *(const float4*)(Y + (size_t)CN * 128 + (size_t)n * 128 + col);
    float4 yc = *(const float4*)(Y + (size_t)2 * CN * 128 + (size_t)n * 128 + col);
    float4 bf = *(const float4*)(bf1 + col);
    float4 wl = *(const float4*)(w2 + col);

    float sc[5];
#pragma unroll
    for (int f = 0; f < 5; f++) {
        float t0 = c_th0[f], t1 = c_th1[f], t2 = c_th2[f];
        float gx = t0 * ya.x + t1 * yb.x + t2 * yc.x + bf.x;
        float gy = t0 * ya.y + t1 * yb.y + t2 * yc.y + bf.y;
        float gz = t0 * ya.z + t1 * yb.z + t2 * yc.z + bf.z;
        float gw = t0 * ya.w + t1 * yb.w + t2 * yc.w + bf.w;
        float p = tanhf(gx) * wl.x + tanhf(gy) * wl.y + tanhf(gz) * wl.z + tanhf(gw) * wl.w;
#pragma unroll
        for (int off = 16; off; off >>= 1) p += __shfl_xor_sync(0xffffffffu, p, off);
        sc[f] = p;
    }
    float mx = sc[0];
#pragma unroll
    for (int f = 1; f < 5; f++) mx = fmaxf(mx, sc[f]);
    float e[5], s = 0.f;
#pragma unroll
    for (int f = 0; f < 5; f++) { e[f] = expf(sc[f] - mx); s += e[f]; }
    float inv = 1.f / s;
    float ca = 0.f, cb = 0.f, cc = 0.f;
#pragma unroll
    for (int f = 0; f < 5; f++) {
        float w = e[f] * inv;
        ca += w * c_th0[f]; cb += w * c_th1[f]; cc += w * c_th2[f];
    }
    float4 a = *(const float4*)(P0 + (size_t)n * ld0 + col);
    float4 b = *(const float4*)(P1 + (size_t)n * 128 + col);
    float4 c = *(const float4*)(P2 + (size_t)n * 128 + col);
    float4 r = make_float4(ca * a.x + cb * b.x + cc * c.x,
                           ca * a.y + cb * b.y + cc * c.y,
                           ca * a.z + cb * b.z + cc * c.z,
                           ca * a.w + cb * b.w + cc * c.w);
    *(float4*)(res + (size_t)n * 128 + col) = r;
}

// out[n, c] = big[n, :] . W6[c, :] + b6[c], warp per node
__global__ void final_kernel(const float* __restrict__ big, const float* __restrict__ W6,
                             const float* __restrict__ b6, float* __restrict__ out)
{
    size_t gid = (size_t)blockIdx.x * blockDim.x + threadIdx.x;
    int n = (int)(gid >> 5);
    int lane = (int)(gid & 31);
    if (n >= CN) return;
    const float* row = big + (size_t)n * 768;
#pragma unroll
    for (int c = 0; c < 2; c++) {
        float a = 0.f;
        for (int j = lane; j < 768; j += 32) a += row[j] * W6[c * 768 + j];
#pragma unroll
        for (int off = 16; off; off >>= 1) a += __shfl_xor_sync(0xffffffffu, a, off);
        if (lane == 0) out[(size_t)n * 2 + c] = a + b6[c];
    }
}

// ---------------- orchestration ----------------
extern "C" void kernel_launch(void* const* d_in, const int* in_sizes, int n_in,
                              void* d_out, int out_size)
{
    const float* voc    = (const float*)d_in[0];
    const float* sms    = (const float*)d_in[1];
    const float* pers   = (const float*)d_in[2];
    const float* Wih_v  = (const float*)d_in[3];
    const float* Whh_v  = (const float*)d_in[4];
    const float* bih_v  = (const float*)d_in[5];
    const float* bhh_v  = (const float*)d_in[6];
    const float* Wih_s  = (const float*)d_in[7];
    const float* Whh_s  = (const float*)d_in[8];
    const float* bih_s  = (const float*)d_in[9];
    const float* bhh_s  = (const float*)d_in[10];
    const float* W_lin  = (const float*)d_in[11];
    const float* b_lin  = (const float*)d_in[12];
    const float* W_lin1 = (const float*)d_in[13];
    const float* b_lin1 = (const float*)d_in[14];
    const float* W_pers = (const float*)d_in[15];
    const float* b_pers = (const float*)d_in[16];
    const float* W_lin2 = (const float*)d_in[17];
    const float* b_lin2 = (const float*)d_in[18];
    const float* W_lin3 = (const float*)d_in[19];
    const float* b_lin3 = (const float*)d_in[20];
    const float* W_lin4 = (const float*)d_in[21];
    const float* b_lin4 = (const float*)d_in[22];
    const float* W_lin5 = (const float*)d_in[23];
    const float* b_lin5 = (const float*)d_in[24];
    const float* Wf1    = (const float*)d_in[25];
    const float* bf1    = (const float*)d_in[26];
    const float* Wf2    = (const float*)d_in[27];
    const float* W_lin6 = (const float*)d_in[28];
    const float* b_lin6 = (const float*)d_in[29];
    const int*   src    = (const int*)d_in[30];
    const int*   dst    = (const int*)d_in[31];
    float* out = (float*)d_out;

    float* S = nullptr;
    cudaGetSymbolAddress((void**)&S, g_scratch);
    int* csr = nullptr; cudaGetSymbolAddress((void**)&csr, g_csr);
    int* offp = nullptr; cudaGetSymbolAddress((void**)&offp, g_off);
    int* curp = nullptr; cudaGetSymbolAddress((void**)&curp, g_cur);

    // prep: interleaved LSTM weights/biases, zero states (HV0,HV1,HS0,HS1,CV,CS)
    prep_kernel<<<(256 * 128 + 255) / 256, 256>>>(Wih_v, Whh_v, bih_v, bhh_v,
                                                  Wih_s, Whh_s, bih_s, bhh_s, S);
    zero_kernel<<<4096, 256>>>(S + OFF_HV0, (size_t)6 * CN * 64);

    // ---- LSTMs: 16 steps, both LSTMs per launch, fused GEMM+cell ----
    dim3 lgrid(4, (CN + 127) / 128);
    for (int t = 0; t < CT; t++) {
        const float* hv_in  = S + ((t & 1) ? OFF_HV1 : OFF_HV0);
        float*       hv_out = S + ((t & 1) ? OFF_HV0 : OFF_HV1);
        const float* hs_in  = S + ((t & 1) ? OFF_HS1 : OFF_HS0);
        float*       hs_out = S + ((t & 1) ? OFF_HS0 : OFF_HS1);
        lstm_step2_kernel<<<lgrid, 256>>>(voc + (size_t)t * 64, sms + (size_t)t * 64, CT * 64,
                                          hv_in, hs_in,
                                          S + OFF_WCV, S + OFF_WCS,
                                          S + OFF_BCV, S + OFF_BCS,
                                          S + OFF_CV, S + OFF_CS,
                                          hv_out, hs_out);
    }

    // ---- projections ----
    gemm(S + OFF_HV0, 64, 64, S + OFF_HV0, 64, W_lin, b_lin,
         S + OFF_XCAT + 0, 512, CN, 128, 64, 1);
    gemm(S + OFF_HS0, 64, 64, S + OFF_HS0, 64, W_lin1, b_lin1,
         S + OFF_XCAT + 256, 512, CN, 128, 64, 1);
    gemm(pers, 32, 32, pers, 32, W_pers, b_pers,
         S + OFF_XCAT + 128, 512, CN, 128, 32, 1);
    copy_xp_kernel<<<((size_t)CN * 128 + 255) / 256, 256>>>(S);

    gemm(S + OFF_XCAT, 512, 256, S + OFF_XCAT, 512, W_lin2, b_lin2,
         S + OFF_BIG + 384, 768, CN, 128, 256, 1);
    gemm(S + OFF_XCAT + 256, 512, 256, S + OFF_XCAT + 256, 512, W_lin3, b_lin3,
         S + OFF_BIG + 512, 768, CN, 128, 256, 1);
    gemm(S + OFF_XCAT, 512, 512, S + OFF_XCAT, 512, W_lin4, b_lin4,
         S + OFF_BIG + 640, 768, CN, 128, 512, 1);

    // ---- relation graphs (CSR gather + linear filter algebra) ----
    const int pgrid = (CN + 7) / 8;
    for (int r = 0; r < CR; r++) {
        const int* sr = src + (size_t)r * CE;
        const int* dr = dst + (size_t)r * CE;
        const float* p0 = S + OFF_BIG + 384 + 128 * r;  // lda 768

        zero_kernel<<<256, 256>>>(S + OFF_DEG, (size_t)CN);
        deg_kernel<<<(CE + 255) / 256, 256>>>(dr, S + OFF_DEG);
        scan_kernel<<<1, 1024>>>(S + OFF_DEG, offp, curp, S + OFF_DINV);
        fill_kernel<<<(CE + 255) / 256, 256>>>(sr, dr, curp, csr);

        prop_kernel<<<pgrid, 256>>>(p0, 768, csr, offp, S + OFF_DINV, S + OFF_P1);
        prop_kernel<<<pgrid, 256>>>(S + OFF_P1, 128, csr, offp, S + OFF_DINV, S + OFF_P2);

        // Ya/Yb/Yc = {p0,p1,p2} @ Wf1^T  (one launch, 3x M=50k)
        {
            dim3 ygrid(3, (CN + 127) / 128);
            yabc_kernel<<<ygrid, 256>>>(p0, 768, S + OFF_P1, S + OFF_P2,
                                        Wf1 + (size_t)r * 128 * 128, S + OFF_YA);
        }

        // scores + softmax + res, all from (Ya,Yb,Yc) and (p0,p1,p2)
        attn_comb_kernel<<<pgrid, 256>>>(S + OFF_YA, p0, 768, S + OFF_P1, S + OFF_P2,
                                         bf1 + (size_t)r * 128, Wf2 + (size_t)r * 128,
                                         S + OFF_RES);

        // hall_r = act(res @ W_lin5[r]^T + b_lin5[r]) -> big cols [128r, 128r+128)
        gemm(S + OFF_RES, 128, 128, S + OFF_RES, 128,
             W_lin5 + (size_t)r * 128 * 128, b_lin5 + (size_t)r * 128,
             S + OFF_BIG + 128 * r, 768, CN, 128, 128, 1);
    }

    // ---- final head ----
    final_kernel<<<((size_t)CN * 32 + 255) / 256, 256>>>(S + OFF_BIG, W_lin6, b_lin6, out);
}

// round 11
// speedup vs baseline: 1.6126x; 1.0593x over previous
#include <cuda_runtime.h>
#include <math.h>
#include <stdint.h>

// Problem constants
#define CN 50000
#define CE 800000
#define CR 3
#define CT 16

typedef unsigned long long ull;

__device__ __forceinline__ ull pack2(float lo, float hi) {
    ull r; asm("mov.b64 %0, {%1,%2};" : "=l"(r) : "f"(lo), "f"(hi)); return r;
}
__device__ __forceinline__ ull fma2(ull a, ull b, ull c) {
    ull d; asm("fma.rn.f32x2 %0, %1, %2, %3;" : "=l"(d) : "l"(a), "l"(b), "l"(c)); return d;
}
__device__ __forceinline__ void unpack2(ull v, float& lo, float& hi) {
    asm("mov.b64 {%0,%1}, %2;" : "=f"(lo), "=f"(hi) : "l"(v));
}

// ---------------- scratch layout (floats) ----------------
constexpr size_t SZ_WCAT = 256 * 128;
constexpr size_t OFF_WCV = 0;
constexpr size_t OFF_WCS = OFF_WCV + SZ_WCAT;
constexpr size_t OFF_BCV = OFF_WCS + SZ_WCAT;
constexpr size_t OFF_BCS = OFF_BCV + 256;
constexpr size_t OFF_HV0 = OFF_BCS + 256;                 // N*64 each
constexpr size_t OFF_HV1 = OFF_HV0 + (size_t)CN * 64;
constexpr size_t OFF_HS0 = OFF_HV1 + (size_t)CN * 64;
constexpr size_t OFF_HS1 = OFF_HS0 + (size_t)CN * 64;
constexpr size_t OFF_CV  = OFF_HS1 + (size_t)CN * 64;
constexpr size_t OFF_CS  = OFF_CV + (size_t)CN * 64;
constexpr size_t OFF_XCAT= OFF_CS + (size_t)CN * 64;      // [xv|xp|xs|xp] N*512
constexpr size_t OFF_BIG = OFF_XCAT + (size_t)CN * 512;   // [hall0..2, xin0..2] N*768
constexpr size_t OFF_P1  = OFF_BIG + (size_t)CN * 768;    // 3 x N*128
constexpr size_t OFF_P2  = OFF_P1 + (size_t)3 * CN * 128; // 3 x N*128
constexpr size_t OFF_Y   = OFF_P2 + (size_t)3 * CN * 128; // 3 x 3 x N*128
constexpr size_t OFF_RES = OFF_Y + (size_t)9 * CN * 128;  // 3 x N*128
constexpr size_t OFF_DEG = OFF_RES + (size_t)3 * CN * 128;// 3 x N
constexpr size_t OFF_DINV= OFF_DEG + (size_t)3 * CN;      // 3 x N
constexpr size_t SCRATCH_TOTAL = OFF_DINV + (size_t)3 * CN + 64;

__device__ float g_scratch[SCRATCH_TOTAL];
__device__ int g_csr[3 * CE];
__device__ int g_off[3 * (CN + 1)];
__device__ int g_cur[3 * CN];

// THETAS coefficients on (p0, p1, p2)
__device__ __constant__ float c_th0[5] = {0.8f, 3.0f, 0.0f, 0.0f, -0.2f};
__device__ __constant__ float c_th1[5] = {-0.5f, -3.0f, 3.0f, 0.0f, 0.5f};
__device__ __constant__ float c_th2[5] = {0.0f, 0.75f, -1.5f, 0.75f, 0.0f};

// =====================================================================
// FFMA2 GEMM core (PROVEN shape): 128x128 tile, BK=16, double-buffered,
// 256 threads, 8x8/thread; acc2[i][jj] packs output cols (2jj, 2jj+1).
// =====================================================================
#define TILE_COMPUTE(cur)                                                      \
    _Pragma("unroll")                                                          \
    for (int kk = 0; kk < 16; kk++) {                                          \
        float a[8]; ull b2[4];                                                 \
        *(float4*)(&a[0]) = *(const float4*)(&As[cur][kk][ty * 8]);            \
        *(float4*)(&a[4]) = *(const float4*)(&As[cur][kk][ty * 8 + 4]);        \
        {                                                                      \
            const ulonglong2* wp = (const ulonglong2*)(&Ws[cur][kk][tx * 8]);  \
            ulonglong2 w0 = wp[0]; ulonglong2 w1 = wp[1];                      \
            b2[0] = w0.x; b2[1] = w0.y; b2[2] = w1.x; b2[3] = w1.y;            \
        }                                                                      \
        _Pragma("unroll")                                                      \
        for (int i = 0; i < 8; i++) {                                          \
            ull ai = pack2(a[i], a[i]);                                        \
            _Pragma("unroll")                                                  \
            for (int jj = 0; jj < 4; jj++)                                     \
                acc2[i][jj] = fma2(ai, b2[jj], acc2[i][jj]);                   \
        }                                                                      \
    }

#define STORE_TILE(buf)                                                                         \
    As[buf][lk+0][lr] = pa0.x; As[buf][lk+1][lr] = pa0.y;                                       \
    As[buf][lk+2][lr] = pa0.z; As[buf][lk+3][lr] = pa0.w;                                       \
    As[buf][lk+0][lr+64] = pa1.x; As[buf][lk+1][lr+64] = pa1.y;                                 \
    As[buf][lk+2][lr+64] = pa1.z; As[buf][lk+3][lr+64] = pa1.w;                                 \
    Ws[buf][lk+0][lr] = pw0.x; Ws[buf][lk+1][lr] = pw0.y;                                       \
    Ws[buf][lk+2][lr] = pw0.z; Ws[buf][lk+3][lr] = pw0.w;                                       \
    Ws[buf][lk+0][lr+64] = pw1.x; Ws[buf][lk+1][lr+64] = pw1.y;                                 \
    Ws[buf][lk+2][lr+64] = pw1.z; Ws[buf][lk+3][lr+64] = pw1.w;

// ---------------- generic SGEMM:  C = act(A @ W^T + bias), optional dup store --------
__global__ __launch_bounds__(256) void sgemm_kernel(
    const float* __restrict__ A, int lda, int K1,
    const float* __restrict__ A2, int lda2,
    const float* __restrict__ W,
    const float* __restrict__ bias,
    float* __restrict__ C, int ldc,
    int M, int K, int act, int dup)
{
    __shared__ float As[2][16][128];
    __shared__ float Ws[2][16][128];

    const int bm = blockIdx.y * 128;
    const int bn = blockIdx.x * 128;
    const int tid = threadIdx.x;
    const int lr = tid >> 2;
    const int lk = (tid & 3) << 2;
    const int ty = tid >> 4, tx = tid & 15;

    ull acc2[8][4];
#pragma unroll
    for (int i = 0; i < 8; i++)
#pragma unroll
        for (int jj = 0; jj < 4; jj++) acc2[i][jj] = 0ull;

    int r0 = bm + lr;      r0 = r0 < M ? r0 : (M - 1);
    int r1 = bm + lr + 64; r1 = r1 < M ? r1 : (M - 1);

    float4 pa0, pa1, pw0, pw1;
    {
        int kg = lk;
        pa0 = (kg < K1) ? *(const float4*)(A + (size_t)r0 * lda + kg)
                        : *(const float4*)(A2 + (size_t)r0 * lda2 + (kg - K1));
        pa1 = (kg < K1) ? *(const float4*)(A + (size_t)r1 * lda + kg)
                        : *(const float4*)(A2 + (size_t)r1 * lda2 + (kg - K1));
        pw0 = *(const float4*)(W + (size_t)(bn + lr) * K + kg);
        pw1 = *(const float4*)(W + (size_t)(bn + lr + 64) * K + kg);
    }
    STORE_TILE(0)
    __syncthreads();

    const int ntiles = K >> 4;
    for (int t = 0; t < ntiles; t++) {
        const int cur = t & 1, nxt = cur ^ 1;
        const bool has = (t + 1) < ntiles;
        if (has) {
            int kg = ((t + 1) << 4) + lk;
            pa0 = (kg < K1) ? *(const float4*)(A + (size_t)r0 * lda + kg)
                            : *(const float4*)(A2 + (size_t)r0 * lda2 + (kg - K1));
            pa1 = (kg < K1) ? *(const float4*)(A + (size_t)r1 * lda + kg)
                            : *(const float4*)(A2 + (size_t)r1 * lda2 + (kg - K1));
            pw0 = *(const float4*)(W + (size_t)(bn + lr) * K + kg);
            pw1 = *(const float4*)(W + (size_t)(bn + lr + 64) * K + kg);
        }
        TILE_COMPUTE(cur)
        if (has) { STORE_TILE(nxt) }
        __syncthreads();
    }

    float bs0[8];
    *(float4*)(&bs0[0]) = *(const float4*)(bias + bn + tx * 8);
    *(float4*)(&bs0[4]) = *(const float4*)(bias + bn + tx * 8 + 4);

#pragma unroll
    for (int i = 0; i < 8; i++) {
        int m = bm + ty * 8 + i;
        if (m >= M) continue;
        float v[8];
#pragma unroll
        for (int jj = 0; jj < 4; jj++) {
            float lo, hi; unpack2(acc2[i][jj], lo, hi);
            v[2 * jj] = lo; v[2 * jj + 1] = hi;
        }
#pragma unroll
        for (int j = 0; j < 8; j++) {
            float x = v[j] + bs0[j];
            if (act == 1)      x = x > 0.f ? x : 0.01f * x;
            else if (act == 2) x = tanhf(x);
            v[j] = x;
        }
        float* cp = C + (size_t)m * ldc + bn + tx * 8;
        *(float4*)(cp)     = *(float4*)(&v[0]);
        *(float4*)(cp + 4) = *(float4*)(&v[4]);
        if (dup) {
            *(float4*)(cp + dup)     = *(float4*)(&v[0]);
            *(float4*)(cp + dup + 4) = *(float4*)(&v[4]);
        }
    }
}

static inline void gemm(const float* A, int lda, int K1,
                        const float* A2, int lda2,
                        const float* W, const float* bias,
                        float* C, int ldc, int M, int O, int K, int act, int dup = 0)
{
    dim3 grid(O / 128, (M + 127) / 128);
    sgemm_kernel<<<grid, 256>>>(A, lda, K1, A2, lda2, W, bias, C, ldc, M, K, act, dup);
}

// ---------------- 9-way Y GEMM: Y[r][w] = P_w(r) @ Wf1[r]^T -----------------
__global__ __launch_bounds__(256) void yabc9_kernel(
    const float* __restrict__ BIGp, // p0 base (BIG+384), ld 768, r offset 128
    const float* __restrict__ P1,   // r stride N*128
    const float* __restrict__ P2,
    const float* __restrict__ Wf1,  // r stride 128*128
    float* __restrict__ Y)          // (r*3+w) stride N*128
{
    __shared__ float As[2][16][128];
    __shared__ float Ws[2][16][128];

    const int sel = blockIdx.x;
    const int r = sel / 3, w = sel % 3;
    const float* A = w == 0 ? (BIGp + 128 * r)
                   : (w == 1 ? (P1 + (size_t)r * CN * 128) : (P2 + (size_t)r * CN * 128));
    const int lda = w == 0 ? 768 : 128;
    const float* W = Wf1 + (size_t)r * 128 * 128;
    float* C = Y + (size_t)sel * CN * 128;

    const int M = CN;
    const int bm = blockIdx.y * 128;
    const int tid = threadIdx.x;
    const int lr = tid >> 2;
    const int lk = (tid & 3) << 2;
    const int ty = tid >> 4, tx = tid & 15;
    const int K = 128;

    ull acc2[8][4];
#pragma unroll
    for (int i = 0; i < 8; i++)
#pragma unroll
        for (int jj = 0; jj < 4; jj++) acc2[i][jj] = 0ull;

    int r0 = bm + lr;      r0 = r0 < M ? r0 : (M - 1);
    int r1 = bm + lr + 64; r1 = r1 < M ? r1 : (M - 1);

    float4 pa0, pa1, pw0, pw1;
    {
        int kg = lk;
        pa0 = *(const float4*)(A + (size_t)r0 * lda + kg);
        pa1 = *(const float4*)(A + (size_t)r1 * lda + kg);
        pw0 = *(const float4*)(W + (size_t)lr * K + kg);
        pw1 = *(const float4*)(W + (size_t)(lr + 64) * K + kg);
    }
    STORE_TILE(0)
    __syncthreads();

#pragma unroll
    for (int t = 0; t < 8; t++) {
        const int cur = t & 1, nxt = cur ^ 1;
        const bool has = t < 7;
        if (has) {
            int kg = ((t + 1) << 4) + lk;
            pa0 = *(const float4*)(A + (size_t)r0 * lda + kg);
            pa1 = *(const float4*)(A + (size_t)r1 * lda + kg);
            pw0 = *(const float4*)(W + (size_t)lr * K + kg);
            pw1 = *(const float4*)(W + (size_t)(lr + 64) * K + kg);
        }
        TILE_COMPUTE(cur)
        if (has) { STORE_TILE(nxt) }
        __syncthreads();
    }

#pragma unroll
    for (int i = 0; i < 8; i++) {
        int m = bm + ty * 8 + i;
        if (m >= M) continue;
        float v[8];
#pragma unroll
        for (int jj = 0; jj < 4; jj++) {
            float lo, hi; unpack2(acc2[i][jj], lo, hi);
            v[2 * jj] = lo; v[2 * jj + 1] = hi;
        }
        float* cp = C + (size_t)m * 128 + tx * 8;
        *(float4*)(cp)     = *(float4*)(&v[0]);
        *(float4*)(cp + 4) = *(float4*)(&v[4]);
    }
}

// ---------------- 3-way lin5 GEMM: BIG[:,128r..] = leaky(RES_r @ W5[r]^T + b5[r]) ----
__global__ __launch_bounds__(256) void lin5b_kernel(
    const float* __restrict__ RES,   // r stride N*128
    const float* __restrict__ W5,    // r stride 128*128
    const float* __restrict__ b5,    // r stride 128
    float* __restrict__ BIGc)        // col offset 128*r, ld 768
{
    __shared__ float As[2][16][128];
    __shared__ float Ws[2][16][128];

    const int r = blockIdx.x;
    const float* A = RES + (size_t)r * CN * 128;
    const float* W = W5 + (size_t)r * 128 * 128;
    const float* bias = b5 + (size_t)r * 128;
    float* C = BIGc + 128 * r;

    const int M = CN;
    const int bm = blockIdx.y * 128;
    const int tid = threadIdx.x;
    const int lr = tid >> 2;
    const int lk = (tid & 3) << 2;
    const int ty = tid >> 4, tx = tid & 15;
    const int K = 128;

    ull acc2[8][4];
#pragma unroll
    for (int i = 0; i < 8; i++)
#pragma unroll
        for (int jj = 0; jj < 4; jj++) acc2[i][jj] = 0ull;

    int r0 = bm + lr;      r0 = r0 < M ? r0 : (M - 1);
    int r1 = bm + lr + 64; r1 = r1 < M ? r1 : (M - 1);

    float4 pa0, pa1, pw0, pw1;
    {
        int kg = lk;
        pa0 = *(const float4*)(A + (size_t)r0 * 128 + kg);
        pa1 = *(const float4*)(A + (size_t)r1 * 128 + kg);
        pw0 = *(const float4*)(W + (size_t)lr * K + kg);
        pw1 = *(const float4*)(W + (size_t)(lr + 64) * K + kg);
    }
    STORE_TILE(0)
    __syncthreads();

#pragma unroll
    for (int t = 0; t < 8; t++) {
        const int cur = t & 1, nxt = cur ^ 1;
        const bool has = t < 7;
        if (has) {
            int kg = ((t + 1) << 4) + lk;
            pa0 = *(const float4*)(A + (size_t)r0 * 128 + kg);
            pa1 = *(const float4*)(A + (size_t)r1 * 128 + kg);
            pw0 = *(const float4*)(W + (size_t)lr * K + kg);
            pw1 = *(const float4*)(W + (size_t)(lr + 64) * K + kg);
        }
        TILE_COMPUTE(cur)
        if (has) { STORE_TILE(nxt) }
        __syncthreads();
    }

    float bs0[8];
    *(float4*)(&bs0[0]) = *(const float4*)(bias + tx * 8);
    *(float4*)(&bs0[4]) = *(const float4*)(bias + tx * 8 + 4);

#pragma unroll
    for (int i = 0; i < 8; i++) {
        int m = bm + ty * 8 + i;
        if (m >= M) continue;
        float v[8];
#pragma unroll
        for (int jj = 0; jj < 4; jj++) {
            float lo, hi; unpack2(acc2[i][jj], lo, hi);
            v[2 * jj] = lo; v[2 * jj + 1] = hi;
        }
#pragma unroll
        for (int j = 0; j < 8; j++) {
            float x = v[j] + bs0[j];
            v[j] = x > 0.f ? x : 0.01f * x;
        }
        float* cp = C + (size_t)m * 768 + tx * 8;
        *(float4*)(cp)     = *(float4*)(&v[0]);
        *(float4*)(cp + 4) = *(float4*)(&v[4]);
    }
}

// ---------------- fused dual-LSTM step kernel (FFMA2, proven) ----------------
__device__ __forceinline__ float sigf(float x) { return 1.f / (1.f + expf(-x)); }

__global__ __launch_bounds__(256) void lstm_step2_kernel(
    const float* __restrict__ Xv, const float* __restrict__ Xs, int ldx,
    const float* __restrict__ Hv, const float* __restrict__ Hs,
    const float* __restrict__ Wcv, const float* __restrict__ Wcs,
    const float* __restrict__ bcv, const float* __restrict__ bcs,
    float* __restrict__ Cv, float* __restrict__ Cs,
    float* __restrict__ Hvo, float* __restrict__ Hso)
{
    __shared__ float As[2][16][128];
    __shared__ float Ws[2][16][128];

    const int sel = blockIdx.x >> 1;
    const float* X   = sel ? Xs  : Xv;
    const float* Hin = sel ? Hs  : Hv;
    const float* Wc  = sel ? Wcs : Wcv;
    const float* bc  = sel ? bcs : bcv;
    float* Cst  = sel ? Cs  : Cv;
    float* Hout = sel ? Hso : Hvo;

    const int M = CN;
    const int bm = blockIdx.y * 128;
    const int bn = (blockIdx.x & 1) * 128;
    const int tid = threadIdx.x;
    const int lr = tid >> 2;
    const int lk = (tid & 3) << 2;
    const int ty = tid >> 4, tx = tid & 15;

    ull acc2[8][4];
#pragma unroll
    for (int i = 0; i < 8; i++)
#pragma unroll
        for (int jj = 0; jj < 4; jj++) acc2[i][jj] = 0ull;

    int r0 = bm + lr;      r0 = r0 < M ? r0 : (M - 1);
    int r1 = bm + lr + 64; r1 = r1 < M ? r1 : (M - 1);

    float4 pa0, pa1, pw0, pw1;
    {
        int kg = lk;
        pa0 = (kg < 64) ? *(const float4*)(X + (size_t)r0 * ldx + kg)
                        : *(const float4*)(Hin + (size_t)r0 * 64 + (kg - 64));
        pa1 = (kg < 64) ? *(const float4*)(X + (size_t)r1 * ldx + kg)
                        : *(const float4*)(Hin + (size_t)r1 * 64 + (kg - 64));
        pw0 = *(const float4*)(Wc + (size_t)(bn + lr) * 128 + kg);
        pw1 = *(const float4*)(Wc + (size_t)(bn + lr + 64) * 128 + kg);
    }
    STORE_TILE(0)
    __syncthreads();

#pragma unroll
    for (int t = 0; t < 8; t++) {
        const int cur = t & 1, nxt = cur ^ 1;
        const bool has = t < 7;
        if (has) {
            int kg = ((t + 1) << 4) + lk;
            pa0 = (kg < 64) ? *(const float4*)(X + (size_t)r0 * ldx + kg)
                            : *(const float4*)(Hin + (size_t)r0 * 64 + (kg - 64));
            pa1 = (kg < 64) ? *(const float4*)(X + (size_t)r1 * ldx + kg)
                            : *(const float4*)(Hin + (size_t)r1 * 64 + (kg - 64));
            pw0 = *(const float4*)(Wc + (size_t)(bn + lr) * 128 + kg);
            pw1 = *(const float4*)(Wc + (size_t)(bn + lr + 64) * 128 + kg);
        }
        TILE_COMPUTE(cur)
        if (has) { STORE_TILE(nxt) }
        __syncthreads();
    }

    const int colbase = bn + tx * 8;
    const int u0 = colbase >> 2;
    float bb[8];
    *(float4*)(&bb[0]) = *(const float4*)(bc + colbase);
    *(float4*)(&bb[4]) = *(const float4*)(bc + colbase + 4);

#pragma unroll
    for (int i = 0; i < 8; i++) {
        int m = bm + ty * 8 + i;
        if (m >= M) continue;
        float g[8];
#pragma unroll
        for (int jj = 0; jj < 4; jj++) {
            float lo, hi; unpack2(acc2[i][jj], lo, hi);
            g[2 * jj] = lo + bb[2 * jj]; g[2 * jj + 1] = hi + bb[2 * jj + 1];
        }
        float2 cold = *(float2*)(Cst + (size_t)m * 64 + u0);
        float c0 = sigf(g[1]) * cold.x + sigf(g[0]) * tanhf(g[2]);
        float c1 = sigf(g[5]) * cold.y + sigf(g[4]) * tanhf(g[6]);
        float2 cn = make_float2(c0, c1);
        float2 hn = make_float2(sigf(g[3]) * tanhf(c0), sigf(g[7]) * tanhf(c1));
        *(float2*)(Cst + (size_t)m * 64 + u0) = cn;
        *(float2*)(Hout + (size_t)m * 64 + u0) = hn;
    }
}

// ---------------- small kernels ----------------
__global__ void zero_kernel(float* p, size_t n)
{
    size_t i = (size_t)blockIdx.x * blockDim.x + threadIdx.x;
    size_t stride = (size_t)gridDim.x * blockDim.x;
    for (; i < n; i += stride) p[i] = 0.f;
}

__global__ void prep_kernel(const float* __restrict__ Wih_v, const float* __restrict__ Whh_v,
                            const float* __restrict__ bih_v, const float* __restrict__ bhh_v,
                            const float* __restrict__ Wih_s, const float* __restrict__ Whh_s,
                            const float* __restrict__ bih_s, const float* __restrict__ bhh_s,
                            float* __restrict__ S)
{
    int idx = blockIdx.x * blockDim.x + threadIdx.x;
    if (idx < 256 * 128) {
        int o = idx >> 7, k = idx & 127;
        int u = o >> 2, g = o & 3;
        int orow = g * 64 + u;
        S[OFF_WCV + idx] = (k < 64) ? Wih_v[orow * 64 + k] : Whh_v[orow * 64 + (k - 64)];
        S[OFF_WCS + idx] = (k < 64) ? Wih_s[orow * 64 + k] : Whh_s[orow * 64 + (k - 64)];
        if (idx < 256) {
            int uu = idx >> 2, gg = idx & 3;
            int ob = gg * 64 + uu;
            S[OFF_BCV + idx] = bih_v[ob] + bhh_v[ob];
            S[OFF_BCS + idx] = bih_s[ob] + bhh_s[ob];
        }
    }
}

// batched over relations: grid.y = r
__global__ void deg3_kernel(const int* __restrict__ dst, float* __restrict__ deg)
{
    int e = blockIdx.x * blockDim.x + threadIdx.x;
    int r = blockIdx.y;
    if (e < CE) atomicAdd(&deg[(size_t)r * CN + dst[(size_t)r * CE + e]], 1.0f);
}

// 3 blocks, one per relation: scan + dinv
__global__ __launch_bounds__(1024) void scan3_kernel(const float* __restrict__ degB,
                                                     int* __restrict__ offB,
                                                     int* __restrict__ curB,
                                                     float* __restrict__ dinvB)
{
    __shared__ int part[1024];
    const int r = blockIdx.x;
    const float* deg = degB + (size_t)r * CN;
    int* off = offB + (size_t)r * (CN + 1);
    int* cur = curB + (size_t)r * CN;
    float* dinv = dinvB + (size_t)r * CN;

    const int tid = threadIdx.x;
    const int chunk = (CN + 1023) / 1024;
    const int start = tid * chunk;
    const int end = min(start + chunk, CN);
    int s = 0;
    for (int i = start; i < end; i++) s += (int)deg[i];
    part[tid] = s;
    __syncthreads();
    for (int d = 1; d < 1024; d <<= 1) {
        int v = (tid >= d) ? part[tid - d] : 0;
        __syncthreads();
        part[tid] += v;
        __syncthreads();
    }
    int pre = (tid == 0) ? 0 : part[tid - 1];
    for (int i = start; i < end; i++) {
        off[i] = pre;
        cur[i] = pre;
        float dg = deg[i];
        dinv[i] = rsqrtf(fmaxf(dg, 1.0f));
        pre += (int)dg;
    }
    if (tid == 1023) off[CN] = pre;
}

__global__ void fill3_kernel(const int* __restrict__ src, const int* __restrict__ dst,
                             int* __restrict__ curB, int* __restrict__ csrB)
{
    int e = blockIdx.x * blockDim.x + threadIdx.x;
    int r = blockIdx.y;
    if (e < CE) {
        int d = dst[(size_t)r * CE + e];
        int pos = atomicAdd(&curB[(size_t)r * CN + d], 1);
        csrB[(size_t)r * CE + pos] = src[(size_t)r * CE + e];
    }
}

// batched gather propagation, grid.y = r.
// pin_r = pin + r*pin_rstride (ld = ldin); out_r = out + r*N*128
__global__ __launch_bounds__(256) void prop3_kernel(
    const float* __restrict__ pin, int ldin, size_t pin_rstride,
    const int* __restrict__ csrB, const int* __restrict__ offB,
    const float* __restrict__ dinvB, float* __restrict__ outB)
{
    const int r = blockIdx.y;
    const int n = blockIdx.x * 8 + (threadIdx.x >> 5);
    if (n >= CN) return;
    const int lane = threadIdx.x & 31;
    const int col = lane * 4;
    const float* pinr = pin + (size_t)r * pin_rstride;
    const int* csr = csrB + (size_t)r * CE;
    const int* off = offB + (size_t)r * (CN + 1);
    const float* dinv = dinvB + (size_t)r * CN;
    float* outp = outB + (size_t)r * CN * 128;

    float4 acc = make_float4(0.f, 0.f, 0.f, 0.f);
    const int s0 = off[n], s1 = off[n + 1];
    for (int e = s0; e < s1; e++) {
        int sn = csr[e];
        float ds = __ldg(&dinv[sn]);
        float4 v = *(const float4*)(pinr + (size_t)sn * ldin + col);
        acc.x += v.x * ds; acc.y += v.y * ds; acc.z += v.z * ds; acc.w += v.w * ds;
    }
    const float dn = dinv[n];
    float4 pv = *(const float4*)(pinr + (size_t)n * ldin + col);
    float4 o = make_float4(pv.x - acc.x * dn, pv.y - acc.y * dn,
                           pv.z - acc.z * dn, pv.w - acc.w * dn);
    *(float4*)(outp + (size_t)n * 128 + col) = o;
}

// combine batched over relations: grid.y = r
__global__ __launch_bounds__(256) void attn_comb3_kernel(
    const float* __restrict__ YB,            // (r*3+w) stride N*128
    const float* __restrict__ BIGp,          // p0 base (BIG+384), ld 768, r off 128
    const float* __restrict__ P1B,
    const float* __restrict__ P2B,
    const float* __restrict__ bf1,           // r stride 128
    const float* __restrict__ w2,            // r stride 128
    float* __restrict__ resB)                // r stride N*128
{
    const int r = blockIdx.y;
    const int n = blockIdx.x * 8 + (threadIdx.x >> 5);
    if (n >= CN) return;
    const int lane = threadIdx.x & 31;
    const int col = lane * 4;

    const float* Y = YB + (size_t)r * 3 * CN * 128;
    const float* P0 = BIGp + 128 * r;
    const float* P1 = P1B + (size_t)r * CN * 128;
    const float* P2 = P2B + (size_t)r * CN * 128;

    float4 ya = *(const float4*)(Y + (size_t)n * 128 + col);
    float4 yb = *(const float4*)(Y + (size_t)CN * 128 + (size_t)n * 128 + col);
    float4 yc = *(const float4*)(Y + (size_t)2 * CN * 128 + (size_t)n * 128 + col);
    float4 bf = *(const float4*)(bf1 + (size_t)r * 128 + col);
    float4 wl = *(const float4*)(w2 + (size_t)r * 128 + col);

    float sc[5];
#pragma unroll
    for (int f = 0; f < 5; f++) {
        float t0 = c_th0[f], t1 = c_th1[f], t2 = c_th2[f];
        float gx = t0 * ya.x + t1 * yb.x + t2 * yc.x + bf.x;
        float gy = t0 * ya.y + t1 * yb.y + t2 * yc.y + bf.y;
        float gz = t0 * ya.z + t1 * yb.z + t2 * yc.z + bf.z;
        float gw = t0 * ya.w + t1 * yb.w + t2 * yc.w + bf.w;
        float p = tanhf(gx) * wl.x + tanhf(gy) * wl.y + tanhf(gz) * wl.z + tanhf(gw) * wl.w;
#pragma unroll
        for (int off = 16; off; off >>= 1) p += __shfl_xor_sync(0xffffffffu, p, off);
        sc[f] = p;
    }
    float mx = sc[0];
#pragma unroll
    for (int f = 1; f < 5; f++) mx = fmaxf(mx, sc[f]);
    float e[5], s = 0.f;
#pragma unroll
    for (int f = 0; f < 5; f++) { e[f] = expf(sc[f] - mx); s += e[f]; }
    float inv = 1.f / s;
    float ca = 0.f, cb = 0.f, cc = 0.f;
#pragma unroll
    for (int f = 0; f < 5; f++) {
        float w = e[f] * inv;
        ca += w * c_th0[f]; cb += w * c_th1[f]; cc += w * c_th2[f];
    }
    float4 a = *(const float4*)(P0 + (size_t)n * 768 + col);
    float4 b = *(const float4*)(P1 + (size_t)n * 128 + col);
    float4 c = *(const float4*)(P2 + (size_t)n * 128 + col);
    float4 rr = make_float4(ca * a.x + cb * b.x + cc * c.x,
                            ca * a.y + cb * b.y + cc * c.y,
                            ca * a.z + cb * b.z + cc * c.z,
                            ca * a.w + cb * b.w + cc * c.w);
    *(float4*)(resB + (size_t)r * CN * 128 + (size_t)n * 128 + col) = rr;
}

// out[n, c] = big[n, :] . W6[c, :] + b6[c], warp per node
__global__ void final_kernel(const float* __restrict__ big, const float* __restrict__ W6,
                             const float* __restrict__ b6, float* __restrict__ out)
{
    size_t gid = (size_t)blockIdx.x * blockDim.x + threadIdx.x;
    int n = (int)(gid >> 5);
    int lane = (int)(gid & 31);
    if (n >= CN) return;
    const float* row = big + (size_t)n * 768;
#pragma unroll
    for (int c = 0; c < 2; c++) {
        float a = 0.f;
        for (int j = lane; j < 768; j += 32) a += row[j] * W6[c * 768 + j];
#pragma unroll
        for (int off = 16; off; off >>= 1) a += __shfl_xor_sync(0xffffffffu, a, off);
        if (lane == 0) out[(size_t)n * 2 + c] = a + b6[c];
    }
}

// ---------------- orchestration ----------------
extern "C" void kernel_launch(void* const* d_in, const int* in_sizes, int n_in,
                              void* d_out, int out_size)
{
    const float* voc    = (const float*)d_in[0];
    const float* sms    = (const float*)d_in[1];
    const float* pers   = (const float*)d_in[2];
    const float* Wih_v  = (const float*)d_in[3];
    const float* Whh_v  = (const float*)d_in[4];
    const float* bih_v  = (const float*)d_in[5];
    const float* bhh_v  = (const float*)d_in[6];
    const float* Wih_s  = (const float*)d_in[7];
    const float* Whh_s  = (const float*)d_in[8];
    const float* bih_s  = (const float*)d_in[9];
    const float* bhh_s  = (const float*)d_in[10];
    const float* W_lin  = (const float*)d_in[11];
    const float* b_lin  = (const float*)d_in[12];
    const float* W_lin1 = (const float*)d_in[13];
    const float* b_lin1 = (const float*)d_in[14];
    const float* W_pers = (const float*)d_in[15];
    const float* b_pers = (const float*)d_in[16];
    const float* W_lin2 = (const float*)d_in[17];
    const float* b_lin2 = (const float*)d_in[18];
    const float* W_lin3 = (const float*)d_in[19];
    const float* b_lin3 = (const float*)d_in[20];
    const float* W_lin4 = (const float*)d_in[21];
    const float* b_lin4 = (const float*)d_in[22];
    const float* W_lin5 = (const float*)d_in[23];
    const float* b_lin5 = (const float*)d_in[24];
    const float* Wf1    = (const float*)d_in[25];
    const float* bf1    = (const float*)d_in[26];
    const float* Wf2    = (const float*)d_in[27];
    const float* W_lin6 = (const float*)d_in[28];
    const float* b_lin6 = (const float*)d_in[29];
    const int*   src    = (const int*)d_in[30];
    const int*   dst    = (const int*)d_in[31];
    float* out = (float*)d_out;

    float* S = nullptr;
    cudaGetSymbolAddress((void**)&S, g_scratch);
    int* csr = nullptr; cudaGetSymbolAddress((void**)&csr, g_csr);
    int* offp = nullptr; cudaGetSymbolAddress((void**)&offp, g_off);
    int* curp = nullptr; cudaGetSymbolAddress((void**)&curp, g_cur);

    // prep + zero states
    prep_kernel<<<(256 * 128 + 255) / 256, 256>>>(Wih_v, Whh_v, bih_v, bhh_v,
                                                  Wih_s, Whh_s, bih_s, bhh_s, S);
    zero_kernel<<<4096, 256>>>(S + OFF_HV0, (size_t)6 * CN * 64);
    // zero all 3 deg arrays up front (independent of LSTM chain position)
    zero_kernel<<<256, 256>>>(S + OFF_DEG, (size_t)3 * CN);

    // ---- LSTMs: 16 steps, both LSTMs per launch, fused GEMM+cell ----
    dim3 lgrid(4, (CN + 127) / 128);
    for (int t = 0; t < CT; t++) {
        const float* hv_in  = S + ((t & 1) ? OFF_HV1 : OFF_HV0);
        float*       hv_out = S + ((t & 1) ? OFF_HV0 : OFF_HV1);
        const float* hs_in  = S + ((t & 1) ? OFF_HS1 : OFF_HS0);
        float*       hs_out = S + ((t & 1) ? OFF_HS0 : OFF_HS1);
        lstm_step2_kernel<<<lgrid, 256>>>(voc + (size_t)t * 64, sms + (size_t)t * 64, CT * 64,
                                          hv_in, hs_in,
                                          S + OFF_WCV, S + OFF_WCS,
                                          S + OFF_BCV, S + OFF_BCS,
                                          S + OFF_CV, S + OFF_CS,
                                          hv_out, hs_out);
    }

    // ---- projections ----
    gemm(S + OFF_HV0, 64, 64, S + OFF_HV0, 64, W_lin, b_lin,
         S + OFF_XCAT + 0, 512, CN, 128, 64, 1);
    gemm(S + OFF_HS0, 64, 64, S + OFF_HS0, 64, W_lin1, b_lin1,
         S + OFF_XCAT + 256, 512, CN, 128, 64, 1);
    gemm(pers, 32, 32, pers, 32, W_pers, b_pers,
         S + OFF_XCAT + 128, 512, CN, 128, 32, 1, /*dup=*/256);

    gemm(S + OFF_XCAT, 512, 256, S + OFF_XCAT, 512, W_lin2, b_lin2,
         S + OFF_BIG + 384, 768, CN, 128, 256, 1);
    gemm(S + OFF_XCAT + 256, 512, 256, S + OFF_XCAT + 256, 512, W_lin3, b_lin3,
         S + OFF_BIG + 512, 768, CN, 128, 256, 1);
    gemm(S + OFF_XCAT, 512, 512, S + OFF_XCAT, 512, W_lin4, b_lin4,
         S + OFF_BIG + 640, 768, CN, 128, 512, 1);

    // ---- relation graphs: fully batched across the 3 relations ----
    const int pgrid = (CN + 7) / 8;
    const float* BIGp = S + OFF_BIG + 384;   // p0 base, ld 768, r offset 128

    deg3_kernel<<<dim3((CE + 255) / 256, 3), 256>>>(dst, S + OFF_DEG);
    scan3_kernel<<<3, 1024>>>(S + OFF_DEG, offp, curp, S + OFF_DINV);
    fill3_kernel<<<dim3((CE + 255) / 256, 3), 256>>>(src, dst, curp, csr);

    prop3_kernel<<<dim3(pgrid, 3), 256>>>(BIGp, 768, 128,
                                          csr, offp, S + OFF_DINV, S + OFF_P1);
    prop3_kernel<<<dim3(pgrid, 3), 256>>>(S + OFF_P1, 128, (size_t)CN * 128,
                                          csr, offp, S + OFF_DINV, S + OFF_P2);

    yabc9_kernel<<<dim3(9, (CN + 127) / 128), 256>>>(BIGp, S + OFF_P1, S + OFF_P2,
                                                     Wf1, S + OFF_Y);

    attn_comb3_kernel<<<dim3(pgrid, 3), 256>>>(S + OFF_Y, BIGp, S + OFF_P1, S + OFF_P2,
                                               bf1, Wf2, S + OFF_RES);

    lin5b_kernel<<<dim3(3, (CN + 127) / 128), 256>>>(S + OFF_RES, W_lin5, b_lin5,
                                                     S + OFF_BIG);

    // ---- final head ----
    final_kernel<<<((size_t)CN * 32 + 255) / 256, 256>>>(S + OFF_BIG, W_lin6, b_lin6, out);
}

// round 12
// speedup vs baseline: 1.6684x; 1.0346x over previous
#include <cuda_runtime.h>
#include <math.h>
#include <stdint.h>

// Problem constants
#define CN 50000
#define CE 800000
#define CR 3
#define CT 16

typedef unsigned long long ull;

__device__ __forceinline__ ull pack2(float lo, float hi) {
    ull r; asm("mov.b64 %0, {%1,%2};" : "=l"(r) : "f"(lo), "f"(hi)); return r;
}
__device__ __forceinline__ ull fma2(ull a, ull b, ull c) {
    ull d; asm("fma.rn.f32x2 %0, %1, %2, %3;" : "=l"(d) : "l"(a), "l"(b), "l"(c)); return d;
}
__device__ __forceinline__ void unpack2(ull v, float& lo, float& hi) {
    asm("mov.b64 {%0,%1}, %2;" : "=f"(lo), "=f"(hi) : "l"(v));
}

// ---------------- scratch layout (floats) ----------------
constexpr size_t SZ_WCAT = 256 * 128;
constexpr size_t OFF_WCV = 0;
constexpr size_t OFF_WCS = OFF_WCV + SZ_WCAT;
constexpr size_t OFF_BCV = OFF_WCS + SZ_WCAT;
constexpr size_t OFF_BCS = OFF_BCV + 256;
constexpr size_t OFF_HV0 = OFF_BCS + 256;                 // N*64 each
constexpr size_t OFF_HV1 = OFF_HV0 + (size_t)CN * 64;
constexpr size_t OFF_HS0 = OFF_HV1 + (size_t)CN * 64;
constexpr size_t OFF_HS1 = OFF_HS0 + (size_t)CN * 64;
constexpr size_t OFF_CV  = OFF_HS1 + (size_t)CN * 64;
constexpr size_t OFF_CS  = OFF_CV + (size_t)CN * 64;
constexpr size_t OFF_XCAT= OFF_CS + (size_t)CN * 64;      // [xv|xp|xs|xp] N*512
constexpr size_t OFF_BIG = OFF_XCAT + (size_t)CN * 512;   // [hall0..2, xin0..2] N*768
constexpr size_t OFF_P1  = OFF_BIG + (size_t)CN * 768;    // 3 x N*128
constexpr size_t OFF_P2  = OFF_P1 + (size_t)3 * CN * 128; // 3 x N*128
constexpr size_t OFF_Y   = OFF_P2 + (size_t)3 * CN * 128; // 3 x 3 x N*128
constexpr size_t OFF_RES = OFF_Y + (size_t)9 * CN * 128;  // 3 x N*128
constexpr size_t OFF_DEG = OFF_RES + (size_t)3 * CN * 128;// 3 x N
constexpr size_t OFF_DINV= OFF_DEG + (size_t)3 * CN;      // 3 x N
constexpr size_t SCRATCH_TOTAL = OFF_DINV + (size_t)3 * CN + 64;

__device__ float g_scratch[SCRATCH_TOTAL];
__device__ int g_csr[3 * CE];
__device__ int g_off[3 * (CN + 1)];
__device__ int g_cur[3 * CN];

// THETAS coefficients on (p0, p1, p2)
__device__ __constant__ float c_th0[5] = {0.8f, 3.0f, 0.0f, 0.0f, -0.2f};
__device__ __constant__ float c_th1[5] = {-0.5f, -3.0f, 3.0f, 0.0f, 0.5f};
__device__ __constant__ float c_th2[5] = {0.0f, 0.75f, -1.5f, 0.75f, 0.0f};

// =====================================================================
// FFMA2 GEMM core (PROVEN shape): 128x128 tile, BK=16, double-buffered,
// 256 threads, 8x8/thread; acc2[i][jj] packs output cols (2jj, 2jj+1).
// =====================================================================
#define TILE_COMPUTE(cur)                                                      \
    _Pragma("unroll")                                                          \
    for (int kk = 0; kk < 16; kk++) {                                          \
        float a[8]; ull b2[4];                                                 \
        *(float4*)(&a[0]) = *(const float4*)(&As[cur][kk][ty * 8]);            \
        *(float4*)(&a[4]) = *(const float4*)(&As[cur][kk][ty * 8 + 4]);        \
        {                                                                      \
            const ulonglong2* wp = (const ulonglong2*)(&Ws[cur][kk][tx * 8]);  \
            ulonglong2 w0 = wp[0]; ulonglong2 w1 = wp[1];                      \
            b2[0] = w0.x; b2[1] = w0.y; b2[2] = w1.x; b2[3] = w1.y;            \
        }                                                                      \
        _Pragma("unroll")                                                      \
        for (int i = 0; i < 8; i++) {                                          \
            ull ai = pack2(a[i], a[i]);                                        \
            _Pragma("unroll")                                                  \
            for (int jj = 0; jj < 4; jj++)                                     \
                acc2[i][jj] = fma2(ai, b2[jj], acc2[i][jj]);                   \
        }                                                                      \
    }

#define STORE_TILE(buf)                                                                         \
    As[buf][lk+0][lr] = pa0.x; As[buf][lk+1][lr] = pa0.y;                                       \
    As[buf][lk+2][lr] = pa0.z; As[buf][lk+3][lr] = pa0.w;                                       \
    As[buf][lk+0][lr+64] = pa1.x; As[buf][lk+1][lr+64] = pa1.y;                                 \
    As[buf][lk+2][lr+64] = pa1.z; As[buf][lk+3][lr+64] = pa1.w;                                 \
    Ws[buf][lk+0][lr] = pw0.x; Ws[buf][lk+1][lr] = pw0.y;                                       \
    Ws[buf][lk+2][lr] = pw0.z; Ws[buf][lk+3][lr] = pw0.w;                                       \
    Ws[buf][lk+0][lr+64] = pw1.x; Ws[buf][lk+1][lr+64] = pw1.y;                                 \
    Ws[buf][lk+2][lr+64] = pw1.z; Ws[buf][lk+3][lr+64] = pw1.w;

// ---------------- generic SGEMM:  C = act(A @ W^T + bias), optional dup store --------
__global__ __launch_bounds__(256) void sgemm_kernel(
    const float* __restrict__ A, int lda, int K1,
    const float* __restrict__ A2, int lda2,
    const float* __restrict__ W,
    const float* __restrict__ bias,
    float* __restrict__ C, int ldc,
    int M, int K, int act, int dup)
{
    __shared__ float As[2][16][128];
    __shared__ float Ws[2][16][128];

    const int bm = blockIdx.y * 128;
    const int bn = blockIdx.x * 128;
    const int tid = threadIdx.x;
    const int lr = tid >> 2;
    const int lk = (tid & 3) << 2;
    const int ty = tid >> 4, tx = tid & 15;

    ull acc2[8][4];
#pragma unroll
    for (int i = 0; i < 8; i++)
#pragma unroll
        for (int jj = 0; jj < 4; jj++) acc2[i][jj] = 0ull;

    int r0 = bm + lr;      r0 = r0 < M ? r0 : (M - 1);
    int r1 = bm + lr + 64; r1 = r1 < M ? r1 : (M - 1);

    float4 pa0, pa1, pw0, pw1;
    {
        int kg = lk;
        pa0 = (kg < K1) ? *(const float4*)(A + (size_t)r0 * lda + kg)
                        : *(const float4*)(A2 + (size_t)r0 * lda2 + (kg - K1));
        pa1 = (kg < K1) ? *(const float4*)(A + (size_t)r1 * lda + kg)
                        : *(const float4*)(A2 + (size_t)r1 * lda2 + (kg - K1));
        pw0 = *(const float4*)(W + (size_t)(bn + lr) * K + kg);
        pw1 = *(const float4*)(W + (size_t)(bn + lr + 64) * K + kg);
    }
    STORE_TILE(0)
    __syncthreads();

    const int ntiles = K >> 4;
    for (int t = 0; t < ntiles; t++) {
        const int cur = t & 1, nxt = cur ^ 1;
        const bool has = (t + 1) < ntiles;
        if (has) {
            int kg = ((t + 1) << 4) + lk;
            pa0 = (kg < K1) ? *(const float4*)(A + (size_t)r0 * lda + kg)
                            : *(const float4*)(A2 + (size_t)r0 * lda2 + (kg - K1));
            pa1 = (kg < K1) ? *(const float4*)(A + (size_t)r1 * lda + kg)
                            : *(const float4*)(A2 + (size_t)r1 * lda2 + (kg - K1));
            pw0 = *(const float4*)(W + (size_t)(bn + lr) * K + kg);
            pw1 = *(const float4*)(W + (size_t)(bn + lr + 64) * K + kg);
        }
        TILE_COMPUTE(cur)
        if (has) { STORE_TILE(nxt) }
        __syncthreads();
    }

    float bs0[8];
    *(float4*)(&bs0[0]) = *(const float4*)(bias + bn + tx * 8);
    *(float4*)(&bs0[4]) = *(const float4*)(bias + bn + tx * 8 + 4);

#pragma unroll
    for (int i = 0; i < 8; i++) {
        int m = bm + ty * 8 + i;
        if (m >= M) continue;
        float v[8];
#pragma unroll
        for (int jj = 0; jj < 4; jj++) {
            float lo, hi; unpack2(acc2[i][jj], lo, hi);
            v[2 * jj] = lo; v[2 * jj + 1] = hi;
        }
#pragma unroll
        for (int j = 0; j < 8; j++) {
            float x = v[j] + bs0[j];
            if (act == 1)      x = x > 0.f ? x : 0.01f * x;
            else if (act == 2) x = tanhf(x);
            v[j] = x;
        }
        float* cp = C + (size_t)m * ldc + bn + tx * 8;
        *(float4*)(cp)     = *(float4*)(&v[0]);
        *(float4*)(cp + 4) = *(float4*)(&v[4]);
        if (dup) {
            *(float4*)(cp + dup)     = *(float4*)(&v[0]);
            *(float4*)(cp + dup + 4) = *(float4*)(&v[4]);
        }
    }
}

static inline void gemm(const float* A, int lda, int K1,
                        const float* A2, int lda2,
                        const float* W, const float* bias,
                        float* C, int ldc, int M, int O, int K, int act, int dup = 0)
{
    dim3 grid(O / 128, (M + 127) / 128);
    sgemm_kernel<<<grid, 256>>>(A, lda, K1, A2, lda2, W, bias, C, ldc, M, K, act, dup);
}

// ---------------- 9-way Y GEMM: Y[r][w] = P_w(r) @ Wf1[r]^T -----------------
__global__ __launch_bounds__(256) void yabc9_kernel(
    const float* __restrict__ BIGp, // p0 base (BIG+384), ld 768, r offset 128
    const float* __restrict__ P1,   // r stride N*128
    const float* __restrict__ P2,
    const float* __restrict__ Wf1,  // r stride 128*128
    float* __restrict__ Y)          // (r*3+w) stride N*128
{
    __shared__ float As[2][16][128];
    __shared__ float Ws[2][16][128];

    const int sel = blockIdx.x;
    const int r = sel / 3, w = sel % 3;
    const float* A = w == 0 ? (BIGp + 128 * r)
                   : (w == 1 ? (P1 + (size_t)r * CN * 128) : (P2 + (size_t)r * CN * 128));
    const int lda = w == 0 ? 768 : 128;
    const float* W = Wf1 + (size_t)r * 128 * 128;
    float* C = Y + (size_t)sel * CN * 128;

    const int M = CN;
    const int bm = blockIdx.y * 128;
    const int tid = threadIdx.x;
    const int lr = tid >> 2;
    const int lk = (tid & 3) << 2;
    const int ty = tid >> 4, tx = tid & 15;
    const int K = 128;

    ull acc2[8][4];
#pragma unroll
    for (int i = 0; i < 8; i++)
#pragma unroll
        for (int jj = 0; jj < 4; jj++) acc2[i][jj] = 0ull;

    int r0 = bm + lr;      r0 = r0 < M ? r0 : (M - 1);
    int r1 = bm + lr + 64; r1 = r1 < M ? r1 : (M - 1);

    float4 pa0, pa1, pw0, pw1;
    {
        int kg = lk;
        pa0 = *(const float4*)(A + (size_t)r0 * lda + kg);
        pa1 = *(const float4*)(A + (size_t)r1 * lda + kg);
        pw0 = *(const float4*)(W + (size_t)lr * K + kg);
        pw1 = *(const float4*)(W + (size_t)(lr + 64) * K + kg);
    }
    STORE_TILE(0)
    __syncthreads();

#pragma unroll
    for (int t = 0; t < 8; t++) {
        const int cur = t & 1, nxt = cur ^ 1;
        const bool has = t < 7;
        if (has) {
            int kg = ((t + 1) << 4) + lk;
            pa0 = *(const float4*)(A + (size_t)r0 * lda + kg);
            pa1 = *(const float4*)(A + (size_t)r1 * lda + kg);
            pw0 = *(const float4*)(W + (size_t)lr * K + kg);
            pw1 = *(const float4*)(W + (size_t)(lr + 64) * K + kg);
        }
        TILE_COMPUTE(cur)
        if (has) { STORE_TILE(nxt) }
        __syncthreads();
    }

#pragma unroll
    for (int i = 0; i < 8; i++) {
        int m = bm + ty * 8 + i;
        if (m >= M) continue;
        float v[8];
#pragma unroll
        for (int jj = 0; jj < 4; jj++) {
            float lo, hi; unpack2(acc2[i][jj], lo, hi);
            v[2 * jj] = lo; v[2 * jj + 1] = hi;
        }
        float* cp = C + (size_t)m * 128 + tx * 8;
        *(float4*)(cp)     = *(float4*)(&v[0]);
        *(float4*)(cp + 4) = *(float4*)(&v[4]);
    }
}

// ---------------- 3-way lin5 GEMM: BIG[:,128r..] = leaky(RES_r @ W5[r]^T + b5[r]) ----
__global__ __launch_bounds__(256) void lin5b_kernel(
    const float* __restrict__ RES,   // r stride N*128
    const float* __restrict__ W5,    // r stride 128*128
    const float* __restrict__ b5,    // r stride 128
    float* __restrict__ BIGc)        // col offset 128*r, ld 768
{
    __shared__ float As[2][16][128];
    __shared__ float Ws[2][16][128];

    const int r = blockIdx.x;
    const float* A = RES + (size_t)r * CN * 128;
    const float* W = W5 + (size_t)r * 128 * 128;
    const float* bias = b5 + (size_t)r * 128;
    float* C = BIGc + 128 * r;

    const int M = CN;
    const int bm = blockIdx.y * 128;
    const int tid = threadIdx.x;
    const int lr = tid >> 2;
    const int lk = (tid & 3) << 2;
    const int ty = tid >> 4, tx = tid & 15;
    const int K = 128;

    ull acc2[8][4];
#pragma unroll
    for (int i = 0; i < 8; i++)
#pragma unroll
        for (int jj = 0; jj < 4; jj++) acc2[i][jj] = 0ull;

    int r0 = bm + lr;      r0 = r0 < M ? r0 : (M - 1);
    int r1 = bm + lr + 64; r1 = r1 < M ? r1 : (M - 1);

    float4 pa0, pa1, pw0, pw1;
    {
        int kg = lk;
        pa0 = *(const float4*)(A + (size_t)r0 * 128 + kg);
        pa1 = *(const float4*)(A + (size_t)r1 * 128 + kg);
        pw0 = *(const float4*)(W + (size_t)lr * K + kg);
        pw1 = *(const float4*)(W + (size_t)(lr + 64) * K + kg);
    }
    STORE_TILE(0)
    __syncthreads();

#pragma unroll
    for (int t = 0; t < 8; t++) {
        const int cur = t & 1, nxt = cur ^ 1;
        const bool has = t < 7;
        if (has) {
            int kg = ((t + 1) << 4) + lk;
            pa0 = *(const float4*)(A + (size_t)r0 * 128 + kg);
            pa1 = *(const float4*)(A + (size_t)r1 * 128 + kg);
            pw0 = *(const float4*)(W + (size_t)lr * K + kg);
            pw1 = *(const float4*)(W + (size_t)(lr + 64) * K + kg);
        }
        TILE_COMPUTE(cur)
        if (has) { STORE_TILE(nxt) }
        __syncthreads();
    }

    float bs0[8];
    *(float4*)(&bs0[0]) = *(const float4*)(bias + tx * 8);
    *(float4*)(&bs0[4]) = *(const float4*)(bias + tx * 8 + 4);

#pragma unroll
    for (int i = 0; i < 8; i++) {
        int m = bm + ty * 8 + i;
        if (m >= M) continue;
        float v[8];
#pragma unroll
        for (int jj = 0; jj < 4; jj++) {
            float lo, hi; unpack2(acc2[i][jj], lo, hi);
            v[2 * jj] = lo; v[2 * jj + 1] = hi;
        }
#pragma unroll
        for (int j = 0; j < 8; j++) {
            float x = v[j] + bs0[j];
            v[j] = x > 0.f ? x : 0.01f * x;
        }
        float* cp = C + (size_t)m * 768 + tx * 8;
        *(float4*)(cp)     = *(float4*)(&v[0]);
        *(float4*)(cp + 4) = *(float4*)(&v[4]);
    }
}

// ---------------- fused dual-LSTM step kernel + CSR piggyback ----------------
// blockIdx.x < 4: LSTM GEMM+cell (proven). blockIdx.x == 4: aux CSR work
// (aux_mode 1 = degree atomics, 2 = scan (blocks y<3), 3 = CSR fill).
__device__ __forceinline__ float sigf(float x) { return 1.f / (1.f + expf(-x)); }

__global__ __launch_bounds__(256, 2) void lstm_step2_kernel(
    const float* __restrict__ Xv, const float* __restrict__ Xs, int ldx,
    const float* __restrict__ Hv, const float* __restrict__ Hs,
    const float* __restrict__ Wcv, const float* __restrict__ Wcs,
    const float* __restrict__ bcv, const float* __restrict__ bcs,
    float* __restrict__ Cv, float* __restrict__ Cs,
    float* __restrict__ Hvo, float* __restrict__ Hso,
    int aux_mode,
    const int* __restrict__ srcB, const int* __restrict__ dstB,
    float* __restrict__ degB, int* __restrict__ offB, int* __restrict__ curB,
    float* __restrict__ dinvB, int* __restrict__ csrB)
{
    __shared__ float As[2][16][128];
    __shared__ float Ws[2][16][128];
    __shared__ int part[256];

    const int tid = threadIdx.x;

    if (blockIdx.x == 4) {
        if (aux_mode == 1) {
            // degree: grid-stride over 3*CE edges
            size_t idx = (size_t)blockIdx.y * 256 + tid;
            const size_t stride = (size_t)gridDim.y * 256;
            for (; idx < (size_t)3 * CE; idx += stride) {
                int r = (int)(idx / CE);
                atomicAdd(&degB[(size_t)r * CN + dstB[idx]], 1.0f);
            }
        } else if (aux_mode == 2) {
            // scan: blocks y<3, 256 threads each
            const int r = blockIdx.y;
            if (r < 3) {
                const float* deg = degB + (size_t)r * CN;
                int* off = offB + (size_t)r * (CN + 1);
                int* cur = curB + (size_t)r * CN;
                float* dinv = dinvB + (size_t)r * CN;
                const int chunk = (CN + 255) / 256;
                const int start = tid * chunk;
                const int end = min(start + chunk, CN);
                int s = 0;
                for (int i = start; i < end; i++) s += (int)deg[i];
                part[tid] = s;
                __syncthreads();
                for (int d = 1; d < 256; d <<= 1) {
                    int v = (tid >= d) ? part[tid - d] : 0;
                    __syncthreads();
                    part[tid] += v;
                    __syncthreads();
                }
                int pre = (tid == 0) ? 0 : part[tid - 1];
                for (int i = start; i < end; i++) {
                    off[i] = pre;
                    cur[i] = pre;
                    float dg = deg[i];
                    dinv[i] = rsqrtf(fmaxf(dg, 1.0f));
                    pre += (int)dg;
                }
                if (tid == 255) off[CN] = pre;
            }
        } else if (aux_mode == 3) {
            // fill: grid-stride over 3*CE edges
            size_t idx = (size_t)blockIdx.y * 256 + tid;
            const size_t stride = (size_t)gridDim.y * 256;
            for (; idx < (size_t)3 * CE; idx += stride) {
                int r = (int)(idx / CE);
                int d = dstB[idx];
                int pos = atomicAdd(&curB[(size_t)r * CN + d], 1);
                csrB[(size_t)r * CE + pos] = srcB[idx];
            }
        }
        return;
    }

    const int sel = blockIdx.x >> 1;
    const float* X   = sel ? Xs  : Xv;
    const float* Hin = sel ? Hs  : Hv;
    const float* Wc  = sel ? Wcs : Wcv;
    const float* bc  = sel ? bcs : bcv;
    float* Cst  = sel ? Cs  : Cv;
    float* Hout = sel ? Hso : Hvo;

    const int M = CN;
    const int bm = blockIdx.y * 128;
    const int bn = (blockIdx.x & 1) * 128;
    const int lr = tid >> 2;
    const int lk = (tid & 3) << 2;
    const int ty = tid >> 4, tx = tid & 15;

    ull acc2[8][4];
#pragma unroll
    for (int i = 0; i < 8; i++)
#pragma unroll
        for (int jj = 0; jj < 4; jj++) acc2[i][jj] = 0ull;

    int r0 = bm + lr;      r0 = r0 < M ? r0 : (M - 1);
    int r1 = bm + lr + 64; r1 = r1 < M ? r1 : (M - 1);

    float4 pa0, pa1, pw0, pw1;
    {
        int kg = lk;
        pa0 = (kg < 64) ? *(const float4*)(X + (size_t)r0 * ldx + kg)
                        : *(const float4*)(Hin + (size_t)r0 * 64 + (kg - 64));
        pa1 = (kg < 64) ? *(const float4*)(X + (size_t)r1 * ldx + kg)
                        : *(const float4*)(Hin + (size_t)r1 * 64 + (kg - 64));
        pw0 = *(const float4*)(Wc + (size_t)(bn + lr) * 128 + kg);
        pw1 = *(const float4*)(Wc + (size_t)(bn + lr + 64) * 128 + kg);
    }
    STORE_TILE(0)
    __syncthreads();

#pragma unroll
    for (int t = 0; t < 8; t++) {
        const int cur = t & 1, nxt = cur ^ 1;
        const bool has = t < 7;
        if (has) {
            int kg = ((t + 1) << 4) + lk;
            pa0 = (kg < 64) ? *(const float4*)(X + (size_t)r0 * ldx + kg)
                            : *(const float4*)(Hin + (size_t)r0 * 64 + (kg - 64));
            pa1 = (kg < 64) ? *(const float4*)(X + (size_t)r1 * ldx + kg)
                            : *(const float4*)(Hin + (size_t)r1 * 64 + (kg - 64));
            pw0 = *(const float4*)(Wc + (size_t)(bn + lr) * 128 + kg);
            pw1 = *(const float4*)(Wc + (size_t)(bn + lr + 64) * 128 + kg);
        }
        TILE_COMPUTE(cur)
        if (has) { STORE_TILE(nxt) }
        __syncthreads();
    }

    const int colbase = bn + tx * 8;
    const int u0 = colbase >> 2;
    float bb[8];
    *(float4*)(&bb[0]) = *(const float4*)(bc + colbase);
    *(float4*)(&bb[4]) = *(const float4*)(bc + colbase + 4);

#pragma unroll
    for (int i = 0; i < 8; i++) {
        int m = bm + ty * 8 + i;
        if (m >= M) continue;
        float g[8];
#pragma unroll
        for (int jj = 0; jj < 4; jj++) {
            float lo, hi; unpack2(acc2[i][jj], lo, hi);
            g[2 * jj] = lo + bb[2 * jj]; g[2 * jj + 1] = hi + bb[2 * jj + 1];
        }
        float2 cold = *(float2*)(Cst + (size_t)m * 64 + u0);
        float c0 = sigf(g[1]) * cold.x + sigf(g[0]) * tanhf(g[2]);
        float c1 = sigf(g[5]) * cold.y + sigf(g[4]) * tanhf(g[6]);
        float2 cn = make_float2(c0, c1);
        float2 hn = make_float2(sigf(g[3]) * tanhf(c0), sigf(g[7]) * tanhf(c1));
        *(float2*)(Cst + (size_t)m * 64 + u0) = cn;
        *(float2*)(Hout + (size_t)m * 64 + u0) = hn;
    }
}

// ---------------- small kernels ----------------
__global__ void zero_kernel(float* p, size_t n)
{
    size_t i = (size_t)blockIdx.x * blockDim.x + threadIdx.x;
    size_t stride = (size_t)gridDim.x * blockDim.x;
    for (; i < n; i += stride) p[i] = 0.f;
}

__global__ void prep_kernel(const float* __restrict__ Wih_v, const float* __restrict__ Whh_v,
                            const float* __restrict__ bih_v, const float* __restrict__ bhh_v,
                            const float* __restrict__ Wih_s, const float* __restrict__ Whh_s,
                            const float* __restrict__ bih_s, const float* __restrict__ bhh_s,
                            float* __restrict__ S)
{
    int idx = blockIdx.x * blockDim.x + threadIdx.x;
    if (idx < 256 * 128) {
        int o = idx >> 7, k = idx & 127;
        int u = o >> 2, g = o & 3;
        int orow = g * 64 + u;
        S[OFF_WCV + idx] = (k < 64) ? Wih_v[orow * 64 + k] : Whh_v[orow * 64 + (k - 64)];
        S[OFF_WCS + idx] = (k < 64) ? Wih_s[orow * 64 + k] : Whh_s[orow * 64 + (k - 64)];
        if (idx < 256) {
            int uu = idx >> 2, gg = idx & 3;
            int ob = gg * 64 + uu;
            S[OFF_BCV + idx] = bih_v[ob] + bhh_v[ob];
            S[OFF_BCS + idx] = bih_s[ob] + bhh_s[ob];
        }
    }
}

// batched gather propagation, grid.y = r; edge loop unrolled x4 for MLP
__global__ __launch_bounds__(256) void prop3_kernel(
    const float* __restrict__ pin, int ldin, size_t pin_rstride,
    const int* __restrict__ csrB, const int* __restrict__ offB,
    const float* __restrict__ dinvB, float* __restrict__ outB)
{
    const int r = blockIdx.y;
    const int n = blockIdx.x * 8 + (threadIdx.x >> 5);
    if (n >= CN) return;
    const int lane = threadIdx.x & 31;
    const int col = lane * 4;
    const float* pinr = pin + (size_t)r * pin_rstride;
    const int* csr = csrB + (size_t)r * CE;
    const int* off = offB + (size_t)r * (CN + 1);
    const float* dinv = dinvB + (size_t)r * CN;
    float* outp = outB + (size_t)r * CN * 128;

    float4 acc = make_float4(0.f, 0.f, 0.f, 0.f);
    const int s0 = off[n], s1 = off[n + 1];
    int e = s0;
    for (; e + 4 <= s1; e += 4) {
        int sn0 = csr[e], sn1 = csr[e + 1], sn2 = csr[e + 2], sn3 = csr[e + 3];
        float d0 = __ldg(&dinv[sn0]), d1 = __ldg(&dinv[sn1]);
        float d2 = __ldg(&dinv[sn2]), d3 = __ldg(&dinv[sn3]);
        float4 v0 = *(const float4*)(pinr + (size_t)sn0 * ldin + col);
        float4 v1 = *(const float4*)(pinr + (size_t)sn1 * ldin + col);
        float4 v2 = *(const float4*)(pinr + (size_t)sn2 * ldin + col);
        float4 v3 = *(const float4*)(pinr + (size_t)sn3 * ldin + col);
        acc.x += v0.x * d0 + v1.x * d1 + v2.x * d2 + v3.x * d3;
        acc.y += v0.y * d0 + v1.y * d1 + v2.y * d2 + v3.y * d3;
        acc.z += v0.z * d0 + v1.z * d1 + v2.z * d2 + v3.z * d3;
        acc.w += v0.w * d0 + v1.w * d1 + v2.w * d2 + v3.w * d3;
    }
    for (; e < s1; e++) {
        int sn = csr[e];
        float ds = __ldg(&dinv[sn]);
        float4 v = *(const float4*)(pinr + (size_t)sn * ldin + col);
        acc.x += v.x * ds; acc.y += v.y * ds; acc.z += v.z * ds; acc.w += v.w * ds;
    }
    const float dn = dinv[n];
    float4 pv = *(const float4*)(pinr + (size_t)n * ldin + col);
    float4 o = make_float4(pv.x - acc.x * dn, pv.y - acc.y * dn,
                           pv.z - acc.z * dn, pv.w - acc.w * dn);
    *(float4*)(outp + (size_t)n * 128 + col) = o;
}

// combine batched over relations: grid.y = r
__global__ __launch_bounds__(256) void attn_comb3_kernel(
    const float* __restrict__ YB,            // (r*3+w) stride N*128
    const float* __restrict__ BIGp,          // p0 base (BIG+384), ld 768, r off 128
    const float* __restrict__ P1B,
    const float* __restrict__ P2B,
    const float* __restrict__ bf1,           // r stride 128
    const float* __restrict__ w2,            // r stride 128
    float* __restrict__ resB)                // r stride N*128
{
    const int r = blockIdx.y;
    const int n = blockIdx.x * 8 + (threadIdx.x >> 5);
    if (n >= CN) return;
    const int lane = threadIdx.x & 31;
    const int col = lane * 4;

    const float* Y = YB + (size_t)r * 3 * CN * 128;
    const float* P0 = BIGp + 128 * r;
    const float* P1 = P1B + (size_t)r * CN * 128;
    const float* P2 = P2B + (size_t)r * CN * 128;

    float4 ya = *(const float4*)(Y + (size_t)n * 128 + col);
    float4 yb = *(const float4*)(Y + (size_t)CN * 128 + (size_t)n * 128 + col);
    float4 yc = *(const float4*)(Y + (size_t)2 * CN * 128 + (size_t)n * 128 + col);
    float4 bf = *(const float4*)(bf1 + (size_t)r * 128 + col);
    float4 wl = *(const float4*)(w2 + (size_t)r * 128 + col);

    float sc[5];
#pragma unroll
    for (int f = 0; f < 5; f++) {
        float t0 = c_th0[f], t1 = c_th1[f], t2 = c_th2[f];
        float gx = t0 * ya.x + t1 * yb.x + t2 * yc.x + bf.x;
        float gy = t0 * ya.y + t1 * yb.y + t2 * yc.y + bf.y;
        float gz = t0 * ya.z + t1 * yb.z + t2 * yc.z + bf.z;
        float gw = t0 * ya.w + t1 * yb.w + t2 * yc.w + bf.w;
        float p = tanhf(gx) * wl.x + tanhf(gy) * wl.y + tanhf(gz) * wl.z + tanhf(gw) * wl.w;
#pragma unroll
        for (int off = 16; off; off >>= 1) p += __shfl_xor_sync(0xffffffffu, p, off);
        sc[f] = p;
    }
    float mx = sc[0];
#pragma unroll
    for (int f = 1; f < 5; f++) mx = fmaxf(mx, sc[f]);
    float e[5], s = 0.f;
#pragma unroll
    for (int f = 0; f < 5; f++) { e[f] = expf(sc[f] - mx); s += e[f]; }
    float inv = 1.f / s;
    float ca = 0.f, cb = 0.f, cc = 0.f;
#pragma unroll
    for (int f = 0; f < 5; f++) {
        float w = e[f] * inv;
        ca += w * c_th0[f]; cb += w * c_th1[f]; cc += w * c_th2[f];
    }
    float4 a = *(const float4*)(P0 + (size_t)n * 768 + col);
    float4 b = *(const float4*)(P1 + (size_t)n * 128 + col);
    float4 c = *(const float4*)(P2 + (size_t)n * 128 + col);
    float4 rr = make_float4(ca * a.x + cb * b.x + cc * c.x,
                            ca * a.y + cb * b.y + cc * c.y,
                            ca * a.z + cb * b.z + cc * c.z,
                            ca * a.w + cb * b.w + cc * c.w);
    *(float4*)(resB + (size_t)r * CN * 128 + (size_t)n * 128 + col) = rr;
}

// out[n, c] = big[n, :] . W6[c, :] + b6[c], warp per node
__global__ void final_kernel(const float* __restrict__ big, const float* __restrict__ W6,
                             const float* __restrict__ b6, float* __restrict__ out)
{
    size_t gid = (size_t)blockIdx.x * blockDim.x + threadIdx.x;
    int n = (int)(gid >> 5);
    int lane = (int)(gid & 31);
    if (n >= CN) return;
    const float* row = big + (size_t)n * 768;
#pragma unroll
    for (int c = 0; c < 2; c++) {
        float a = 0.f;
        for (int j = lane; j < 768; j += 32) a += row[j] * W6[c * 768 + j];
#pragma unroll
        for (int off = 16; off; off >>= 1) a += __shfl_xor_sync(0xffffffffu, a, off);
        if (lane == 0) out[(size_t)n * 2 + c] = a + b6[c];
    }
}

// ---------------- orchestration ----------------
extern "C" void kernel_launch(void* const* d_in, const int* in_sizes, int n_in,
                              void* d_out, int out_size)
{
    const float* voc    = (const float*)d_in[0];
    const float* sms    = (const float*)d_in[1];
    const float* pers   = (const float*)d_in[2];
    const float* Wih_v  = (const float*)d_in[3];
    const float* Whh_v  = (const float*)d_in[4];
    const float* bih_v  = (const float*)d_in[5];
    const float* bhh_v  = (const float*)d_in[6];
    const float* Wih_s  = (const float*)d_in[7];
    const float* Whh_s  = (const float*)d_in[8];
    const float* bih_s  = (const float*)d_in[9];
    const float* bhh_s  = (const float*)d_in[10];
    const float* W_lin  = (const float*)d_in[11];
    const float* b_lin  = (const float*)d_in[12];
    const float* W_lin1 = (const float*)d_in[13];
    const float* b_lin1 = (const float*)d_in[14];
    const float* W_pers = (const float*)d_in[15];
    const float* b_pers = (const float*)d_in[16];
    const float* W_lin2 = (const float*)d_in[17];
    const float* b_lin2 = (const float*)d_in[18];
    const float* W_lin3 = (const float*)d_in[19];
    const float* b_lin3 = (const float*)d_in[20];
    const float* W_lin4 = (const float*)d_in[21];
    const float* b_lin4 = (const float*)d_in[22];
    const float* W_lin5 = (const float*)d_in[23];
    const float* b_lin5 = (const float*)d_in[24];
    const float* Wf1    = (const float*)d_in[25];
    const float* bf1    = (const float*)d_in[26];
    const float* Wf2    = (const float*)d_in[27];
    const float* W_lin6 = (const float*)d_in[28];
    const float* b_lin6 = (const float*)d_in[29];
    const int*   src    = (const int*)d_in[30];
    const int*   dst    = (const int*)d_in[31];
    float* out = (float*)d_out;

    float* S = nullptr;
    cudaGetSymbolAddress((void**)&S, g_scratch);
    int* csr = nullptr; cudaGetSymbolAddress((void**)&csr, g_csr);
    int* offp = nullptr; cudaGetSymbolAddress((void**)&offp, g_off);
    int* curp = nullptr; cudaGetSymbolAddress((void**)&curp, g_cur);

    // prep + zero states + zero deg (before the LSTM chain starts)
    prep_kernel<<<(256 * 128 + 255) / 256, 256>>>(Wih_v, Whh_v, bih_v, bhh_v,
                                                  Wih_s, Whh_s, bih_s, bhh_s, S);
    zero_kernel<<<4096, 256>>>(S + OFF_HV0, (size_t)6 * CN * 64);
    zero_kernel<<<256, 256>>>(S + OFF_DEG, (size_t)3 * CN);

    // ---- LSTMs: 16 steps; steps 0-2 piggyback the CSR build ----
    const int ygrid = (CN + 127) / 128;
    for (int t = 0; t < CT; t++) {
        const float* hv_in  = S + ((t & 1) ? OFF_HV1 : OFF_HV0);
        float*       hv_out = S + ((t & 1) ? OFF_HV0 : OFF_HV1);
        const float* hs_in  = S + ((t & 1) ? OFF_HS1 : OFF_HS0);
        float*       hs_out = S + ((t & 1) ? OFF_HS0 : OFF_HS1);
        const int aux = (t == 0) ? 1 : (t == 1) ? 2 : (t == 2) ? 3 : 0;
        dim3 lgrid(aux ? 5 : 4, ygrid);
        lstm_step2_kernel<<<lgrid, 256>>>(voc + (size_t)t * 64, sms + (size_t)t * 64, CT * 64,
                                          hv_in, hs_in,
                                          S + OFF_WCV, S + OFF_WCS,
                                          S + OFF_BCV, S + OFF_BCS,
                                          S + OFF_CV, S + OFF_CS,
                                          hv_out, hs_out,
                                          aux, src, dst,
                                          S + OFF_DEG, offp, curp,
                                          S + OFF_DINV, csr);
    }

    // ---- projections ----
    gemm(S + OFF_HV0, 64, 64, S + OFF_HV0, 64, W_lin, b_lin,
         S + OFF_XCAT + 0, 512, CN, 128, 64, 1);
    gemm(S + OFF_HS0, 64, 64, S + OFF_HS0, 64, W_lin1, b_lin1,
         S + OFF_XCAT + 256, 512, CN, 128, 64, 1);
    gemm(pers, 32, 32, pers, 32, W_pers, b_pers,
         S + OFF_XCAT + 128, 512, CN, 128, 32, 1, /*dup=*/256);

    gemm(S + OFF_XCAT, 512, 256, S + OFF_XCAT, 512, W_lin2, b_lin2,
         S + OFF_BIG + 384, 768, CN, 128, 256, 1);
    gemm(S + OFF_XCAT + 256, 512, 256, S + OFF_XCAT + 256, 512, W_lin3, b_lin3,
         S + OFF_BIG + 512, 768, CN, 128, 256, 1);
    gemm(S + OFF_XCAT, 512, 512, S + OFF_XCAT, 512, W_lin4, b_lin4,
         S + OFF_BIG + 640, 768, CN, 128, 512, 1);

    // ---- relation graphs: CSR already built during LSTM steps 0-2 ----
    const int pgrid = (CN + 7) / 8;
    const float* BIGp = S + OFF_BIG + 384;   // p0 base, ld 768, r offset 128

    prop3_kernel<<<dim3(pgrid, 3), 256>>>(BIGp, 768, 128,
                                          csr, offp, S + OFF_DINV, S + OFF_P1);
    prop3_kernel<<<dim3(pgrid, 3), 256>>>(S + OFF_P1, 128, (size_t)CN * 128,
                                          csr, offp, S + OFF_DINV, S + OFF_P2);

    yabc9_kernel<<<dim3(9, ygrid), 256>>>(BIGp, S + OFF_P1, S + OFF_P2,
                                          Wf1, S + OFF_Y);

    attn_comb3_kernel<<<dim3(pgrid, 3), 256>>>(S + OFF_Y, BIGp, S + OFF_P1, S + OFF_P2,
                                               bf1, Wf2, S + OFF_RES);

    lin5b_kernel<<<dim3(3, ygrid), 256>>>(S + OFF_RES, W_lin5, b_lin5, S + OFF_BIG);

    // ---- final head ----
    final_kernel<<<((size_t)CN * 32 + 255) / 256, 256>>>(S + OFF_BIG, W_lin6, b_lin6, out);
}

// round 13
// speedup vs baseline: 1.7179x; 1.0297x over previous
#include <cuda_runtime.h>
#include <math.h>
#include <stdint.h>

// Problem constants
#define CN 50000
#define CE 800000
#define CR 3
#define CT 16

typedef unsigned long long ull;

__device__ __forceinline__ ull pack2(float lo, float hi) {
    ull r; asm("mov.b64 %0, {%1,%2};" : "=l"(r) : "f"(lo), "f"(hi)); return r;
}
__device__ __forceinline__ ull fma2(ull a, ull b, ull c) {
    ull d; asm("fma.rn.f32x2 %0, %1, %2, %3;" : "=l"(d) : "l"(a), "l"(b), "l"(c)); return d;
}
__device__ __forceinline__ void unpack2(ull v, float& lo, float& hi) {
    asm("mov.b64 {%0,%1}, %2;" : "=f"(lo), "=f"(hi) : "l"(v));
}

// ---------------- scratch layout (floats) ----------------
constexpr size_t SZ_WCAT = 256 * 128;
constexpr size_t OFF_WCV = 0;
constexpr size_t OFF_WCS = OFF_WCV + SZ_WCAT;
constexpr size_t OFF_BCV = OFF_WCS + SZ_WCAT;
constexpr size_t OFF_BCS = OFF_BCV + 256;
constexpr size_t OFF_W3P = OFF_BCS + 256;                 // 128*256 (lin3, k-perm)
constexpr size_t OFF_W4P = OFF_W3P + 128 * 256;           // 128*384 (lin4, xp-combined)
constexpr size_t OFF_HV0 = OFF_W4P + 128 * 384;           // N*64 each
constexpr size_t OFF_HV1 = OFF_HV0 + (size_t)CN * 64;
constexpr size_t OFF_HS0 = OFF_HV1 + (size_t)CN * 64;
constexpr size_t OFF_HS1 = OFF_HS0 + (size_t)CN * 64;
constexpr size_t OFF_CV  = OFF_HS1 + (size_t)CN * 64;
constexpr size_t OFF_CS  = OFF_CV + (size_t)CN * 64;
constexpr size_t OFF_XCAT= OFF_CS + (size_t)CN * 64;      // [xv|xp|xs] N*384
constexpr size_t OFF_BIG = OFF_XCAT + (size_t)CN * 384;   // [hall0..2, xin0..2] N*768
constexpr size_t OFF_P1  = OFF_BIG + (size_t)CN * 768;    // 3 x N*128
constexpr size_t OFF_P2  = OFF_P1 + (size_t)3 * CN * 128; // 3 x N*128
constexpr size_t OFF_Y   = OFF_P2 + (size_t)3 * CN * 128; // 3 x 3 x N*128
constexpr size_t OFF_RES = OFF_Y + (size_t)9 * CN * 128;  // 3 x N*128
constexpr size_t OFF_DEG = OFF_RES + (size_t)3 * CN * 128;// 3 x N
constexpr size_t OFF_DINV= OFF_DEG + (size_t)3 * CN;      // 3 x N
constexpr size_t SCRATCH_TOTAL = OFF_DINV + (size_t)3 * CN + 64;

__device__ float g_scratch[SCRATCH_TOTAL];
__device__ int g_csr[3 * CE];
__device__ int g_off[3 * (CN + 1)];
__device__ int g_cur[3 * CN];

// THETAS coefficients on (p0, p1, p2)
__device__ __constant__ float c_th0[5] = {0.8f, 3.0f, 0.0f, 0.0f, -0.2f};
__device__ __constant__ float c_th1[5] = {-0.5f, -3.0f, 3.0f, 0.0f, 0.5f};
__device__ __constant__ float c_th2[5] = {0.0f, 0.75f, -1.5f, 0.75f, 0.0f};

// =====================================================================
// FFMA2 GEMM core (PROVEN shape): 128x128 tile, BK=16, double-buffered,
// 256 threads, 8x8/thread; acc2[i][jj] packs output cols (2jj, 2jj+1).
// =====================================================================
#define TILE_COMPUTE(cur)                                                      \
    _Pragma("unroll")                                                          \
    for (int kk = 0; kk < 16; kk++) {                                          \
        float a[8]; ull b2[4];                                                 \
        *(float4*)(&a[0]) = *(const float4*)(&As[cur][kk][ty * 8]);            \
        *(float4*)(&a[4]) = *(const float4*)(&As[cur][kk][ty * 8 + 4]);        \
        {                                                                      \
            const ulonglong2* wp = (const ulonglong2*)(&Ws[cur][kk][tx * 8]);  \
            ulonglong2 w0 = wp[0]; ulonglong2 w1 = wp[1];                      \
            b2[0] = w0.x; b2[1] = w0.y; b2[2] = w1.x; b2[3] = w1.y;            \
        }                                                                      \
        _Pragma("unroll")                                                      \
        for (int i = 0; i < 8; i++) {                                          \
            ull ai = pack2(a[i], a[i]);                                        \
            _Pragma("unroll")                                                  \
            for (int jj = 0; jj < 4; jj++)                                     \
                acc2[i][jj] = fma2(ai, b2[jj], acc2[i][jj]);                   \
        }                                                                      \
    }

#define STORE_TILE(buf)                                                                         \
    As[buf][lk+0][lr] = pa0.x; As[buf][lk+1][lr] = pa0.y;                                       \
    As[buf][lk+2][lr] = pa0.z; As[buf][lk+3][lr] = pa0.w;                                       \
    As[buf][lk+0][lr+64] = pa1.x; As[buf][lk+1][lr+64] = pa1.y;                                 \
    As[buf][lk+2][lr+64] = pa1.z; As[buf][lk+3][lr+64] = pa1.w;                                 \
    Ws[buf][lk+0][lr] = pw0.x; Ws[buf][lk+1][lr] = pw0.y;                                       \
    Ws[buf][lk+2][lr] = pw0.z; Ws[buf][lk+3][lr] = pw0.w;                                       \
    Ws[buf][lk+0][lr+64] = pw1.x; Ws[buf][lk+1][lr+64] = pw1.y;                                 \
    Ws[buf][lk+2][lr+64] = pw1.z; Ws[buf][lk+3][lr+64] = pw1.w;

// ---------------- batched projection A: XCAT cols from {hv, pers, hs} --------
// sel 0: hv @ W_lin^T (K=64) -> XCAT+0 ; sel 1: pers @ W_pers^T (K=32) -> XCAT+128
// sel 2: hs @ W_lin1^T (K=64) -> XCAT+256. All leaky, ldc=384.
__global__ __launch_bounds__(256) void projA_kernel(
    const float* __restrict__ HV, const float* __restrict__ HS,
    const float* __restrict__ PERS,
    const float* __restrict__ Wl, const float* __restrict__ bl,
    const float* __restrict__ Wl1, const float* __restrict__ bl1,
    const float* __restrict__ Wp, const float* __restrict__ bp,
    float* __restrict__ XCAT)
{
    __shared__ float As[2][16][128];
    __shared__ float Ws[2][16][128];

    const int sel = blockIdx.x;
    const float* A = sel == 0 ? HV : (sel == 1 ? PERS : HS);
    const int lda = sel == 1 ? 32 : 64;
    const int K = lda;
    const float* W = sel == 0 ? Wl : (sel == 1 ? Wp : Wl1);
    const float* bias = sel == 0 ? bl : (sel == 1 ? bp : bl1);
    float* C = XCAT + 128 * sel;

    const int M = CN;
    const int bm = blockIdx.y * 128;
    const int tid = threadIdx.x;
    const int lr = tid >> 2;
    const int lk = (tid & 3) << 2;
    const int ty = tid >> 4, tx = tid & 15;

    ull acc2[8][4];
#pragma unroll
    for (int i = 0; i < 8; i++)
#pragma unroll
        for (int jj = 0; jj < 4; jj++) acc2[i][jj] = 0ull;

    int r0 = bm + lr;      r0 = r0 < M ? r0 : (M - 1);
    int r1 = bm + lr + 64; r1 = r1 < M ? r1 : (M - 1);

    float4 pa0, pa1, pw0, pw1;
    {
        int kg = lk;
        pa0 = *(const float4*)(A + (size_t)r0 * lda + kg);
        pa1 = *(const float4*)(A + (size_t)r1 * lda + kg);
        pw0 = *(const float4*)(W + (size_t)lr * K + kg);
        pw1 = *(const float4*)(W + (size_t)(lr + 64) * K + kg);
    }
    STORE_TILE(0)
    __syncthreads();

    const int ntiles = K >> 4;
    for (int t = 0; t < ntiles; t++) {
        const int cur = t & 1, nxt = cur ^ 1;
        const bool has = (t + 1) < ntiles;
        if (has) {
            int kg = ((t + 1) << 4) + lk;
            pa0 = *(const float4*)(A + (size_t)r0 * lda + kg);
            pa1 = *(const float4*)(A + (size_t)r1 * lda + kg);
            pw0 = *(const float4*)(W + (size_t)lr * K + kg);
            pw1 = *(const float4*)(W + (size_t)(lr + 64) * K + kg);
        }
        TILE_COMPUTE(cur)
        if (has) { STORE_TILE(nxt) }
        __syncthreads();
    }

    float bs0[8];
    *(float4*)(&bs0[0]) = *(const float4*)(bias + tx * 8);
    *(float4*)(&bs0[4]) = *(const float4*)(bias + tx * 8 + 4);

#pragma unroll
    for (int i = 0; i < 8; i++) {
        int m = bm + ty * 8 + i;
        if (m >= M) continue;
        float v[8];
#pragma unroll
        for (int jj = 0; jj < 4; jj++) {
            float lo, hi; unpack2(acc2[i][jj], lo, hi);
            v[2 * jj] = lo; v[2 * jj + 1] = hi;
        }
#pragma unroll
        for (int j = 0; j < 8; j++) {
            float x = v[j] + bs0[j];
            v[j] = x > 0.f ? x : 0.01f * x;
        }
        float* cp = C + (size_t)m * 384 + tx * 8;
        *(float4*)(cp)     = *(float4*)(&v[0]);
        *(float4*)(cp + 4) = *(float4*)(&v[4]);
    }
}

// ---------------- batched projection B: xin GEMMs into BIG -------------------
// sel 0: XCAT[0:256]@W_lin2^T (K=256) -> BIG+384 ; sel 1: XCAT[128:384]@W3P^T
// (K=256) -> BIG+512 ; sel 2: XCAT[0:384]@W4P^T (K=384) -> BIG+640. leaky.
__global__ __launch_bounds__(256) void projB_kernel(
    const float* __restrict__ XCAT,
    const float* __restrict__ Wl2, const float* __restrict__ bl2,
    const float* __restrict__ W3P, const float* __restrict__ bl3,
    const float* __restrict__ W4P, const float* __restrict__ bl4,
    float* __restrict__ BIG)
{
    __shared__ float As[2][16][128];
    __shared__ float Ws[2][16][128];

    const int sel = blockIdx.x;
    const float* A = XCAT + (sel == 1 ? 128 : 0);
    const int K = sel == 2 ? 384 : 256;
    const float* W = sel == 0 ? Wl2 : (sel == 1 ? W3P : W4P);
    const float* bias = sel == 0 ? bl2 : (sel == 1 ? bl3 : bl4);
    float* C = BIG + 384 + 128 * sel;

    const int M = CN;
    const int bm = blockIdx.y * 128;
    const int tid = threadIdx.x;
    const int lr = tid >> 2;
    const int lk = (tid & 3) << 2;
    const int ty = tid >> 4, tx = tid & 15;

    ull acc2[8][4];
#pragma unroll
    for (int i = 0; i < 8; i++)
#pragma unroll
        for (int jj = 0; jj < 4; jj++) acc2[i][jj] = 0ull;

    int r0 = bm + lr;      r0 = r0 < M ? r0 : (M - 1);
    int r1 = bm + lr + 64; r1 = r1 < M ? r1 : (M - 1);

    float4 pa0, pa1, pw0, pw1;
    {
        int kg = lk;
        pa0 = *(const float4*)(A + (size_t)r0 * 384 + kg);
        pa1 = *(const float4*)(A + (size_t)r1 * 384 + kg);
        pw0 = *(const float4*)(W + (size_t)lr * K + kg);
        pw1 = *(const float4*)(W + (size_t)(lr + 64) * K + kg);
    }
    STORE_TILE(0)
    __syncthreads();

    const int ntiles = K >> 4;
    for (int t = 0; t < ntiles; t++) {
        const int cur = t & 1, nxt = cur ^ 1;
        const bool has = (t + 1) < ntiles;
        if (has) {
            int kg = ((t + 1) << 4) + lk;
            pa0 = *(const float4*)(A + (size_t)r0 * 384 + kg);
            pa1 = *(const float4*)(A + (size_t)r1 * 384 + kg);
            pw0 = *(const float4*)(W + (size_t)lr * K + kg);
            pw1 = *(const float4*)(W + (size_t)(lr + 64) * K + kg);
        }
        TILE_COMPUTE(cur)
        if (has) { STORE_TILE(nxt) }
        __syncthreads();
    }

    float bs0[8];
    *(float4*)(&bs0[0]) = *(const float4*)(bias + tx * 8);
    *(float4*)(&bs0[4]) = *(const float4*)(bias + tx * 8 + 4);

#pragma unroll
    for (int i = 0; i < 8; i++) {
        int m = bm + ty * 8 + i;
        if (m >= M) continue;
        float v[8];
#pragma unroll
        for (int jj = 0; jj < 4; jj++) {
            float lo, hi; unpack2(acc2[i][jj], lo, hi);
            v[2 * jj] = lo; v[2 * jj + 1] = hi;
        }
#pragma unroll
        for (int j = 0; j < 8; j++) {
            float x = v[j] + bs0[j];
            v[j] = x > 0.f ? x : 0.01f * x;
        }
        float* cp = C + (size_t)m * 768 + tx * 8;
        *(float4*)(cp)     = *(float4*)(&v[0]);
        *(float4*)(cp + 4) = *(float4*)(&v[4]);
    }
}

// ---------------- 9-way Y GEMM: Y[r][w] = P_w(r) @ Wf1[r]^T -----------------
__global__ __launch_bounds__(256) void yabc9_kernel(
    const float* __restrict__ BIGp,
    const float* __restrict__ P1,
    const float* __restrict__ P2,
    const float* __restrict__ Wf1,
    float* __restrict__ Y)
{
    __shared__ float As[2][16][128];
    __shared__ float Ws[2][16][128];

    const int sel = blockIdx.x;
    const int r = sel / 3, w = sel % 3;
    const float* A = w == 0 ? (BIGp + 128 * r)
                   : (w == 1 ? (P1 + (size_t)r * CN * 128) : (P2 + (size_t)r * CN * 128));
    const int lda = w == 0 ? 768 : 128;
    const float* W = Wf1 + (size_t)r * 128 * 128;
    float* C = Y + (size_t)sel * CN * 128;

    const int M = CN;
    const int bm = blockIdx.y * 128;
    const int tid = threadIdx.x;
    const int lr = tid >> 2;
    const int lk = (tid & 3) << 2;
    const int ty = tid >> 4, tx = tid & 15;
    const int K = 128;

    ull acc2[8][4];
#pragma unroll
    for (int i = 0; i < 8; i++)
#pragma unroll
        for (int jj = 0; jj < 4; jj++) acc2[i][jj] = 0ull;

    int r0 = bm + lr;      r0 = r0 < M ? r0 : (M - 1);
    int r1 = bm + lr + 64; r1 = r1 < M ? r1 : (M - 1);

    float4 pa0, pa1, pw0, pw1;
    {
        int kg = lk;
        pa0 = *(const float4*)(A + (size_t)r0 * lda + kg);
        pa1 = *(const float4*)(A + (size_t)r1 * lda + kg);
        pw0 = *(const float4*)(W + (size_t)lr * K + kg);
        pw1 = *(const float4*)(W + (size_t)(lr + 64) * K + kg);
    }
    STORE_TILE(0)
    __syncthreads();

#pragma unroll
    for (int t = 0; t < 8; t++) {
        const int cur = t & 1, nxt = cur ^ 1;
        const bool has = t < 7;
        if (has) {
            int kg = ((t + 1) << 4) + lk;
            pa0 = *(const float4*)(A + (size_t)r0 * lda + kg);
            pa1 = *(const float4*)(A + (size_t)r1 * lda + kg);
            pw0 = *(const float4*)(W + (size_t)lr * K + kg);
            pw1 = *(const float4*)(W + (size_t)(lr + 64) * K + kg);
        }
        TILE_COMPUTE(cur)
        if (has) { STORE_TILE(nxt) }
        __syncthreads();
    }

#pragma unroll
    for (int i = 0; i < 8; i++) {
        int m = bm + ty * 8 + i;
        if (m >= M) continue;
        float v[8];
#pragma unroll
        for (int jj = 0; jj < 4; jj++) {
            float lo, hi; unpack2(acc2[i][jj], lo, hi);
            v[2 * jj] = lo; v[2 * jj + 1] = hi;
        }
        float* cp = C + (size_t)m * 128 + tx * 8;
        *(float4*)(cp)     = *(float4*)(&v[0]);
        *(float4*)(cp + 4) = *(float4*)(&v[4]);
    }
}

// ---------------- 3-way lin5 GEMM ----
__global__ __launch_bounds__(256) void lin5b_kernel(
    const float* __restrict__ RES,
    const float* __restrict__ W5,
    const float* __restrict__ b5,
    float* __restrict__ BIGc)
{
    __shared__ float As[2][16][128];
    __shared__ float Ws[2][16][128];

    const int r = blockIdx.x;
    const float* A = RES + (size_t)r * CN * 128;
    const float* W = W5 + (size_t)r * 128 * 128;
    const float* bias = b5 + (size_t)r * 128;
    float* C = BIGc + 128 * r;

    const int M = CN;
    const int bm = blockIdx.y * 128;
    const int tid = threadIdx.x;
    const int lr = tid >> 2;
    const int lk = (tid & 3) << 2;
    const int ty = tid >> 4, tx = tid & 15;
    const int K = 128;

    ull acc2[8][4];
#pragma unroll
    for (int i = 0; i < 8; i++)
#pragma unroll
        for (int jj = 0; jj < 4; jj++) acc2[i][jj] = 0ull;

    int r0 = bm + lr;      r0 = r0 < M ? r0 : (M - 1);
    int r1 = bm + lr + 64; r1 = r1 < M ? r1 : (M - 1);

    float4 pa0, pa1, pw0, pw1;
    {
        int kg = lk;
        pa0 = *(const float4*)(A + (size_t)r0 * 128 + kg);
        pa1 = *(const float4*)(A + (size_t)r1 * 128 + kg);
        pw0 = *(const float4*)(W + (size_t)lr * K + kg);
        pw1 = *(const float4*)(W + (size_t)(lr + 64) * K + kg);
    }
    STORE_TILE(0)
    __syncthreads();

#pragma unroll
    for (int t = 0; t < 8; t++) {
        const int cur = t & 1, nxt = cur ^ 1;
        const bool has = t < 7;
        if (has) {
            int kg = ((t + 1) << 4) + lk;
            pa0 = *(const float4*)(A + (size_t)r0 * 128 + kg);
            pa1 = *(const float4*)(A + (size_t)r1 * 128 + kg);
            pw0 = *(const float4*)(W + (size_t)lr * K + kg);
            pw1 = *(const float4*)(W + (size_t)(lr + 64) * K + kg);
        }
        TILE_COMPUTE(cur)
        if (has) { STORE_TILE(nxt) }
        __syncthreads();
    }

    float bs0[8];
    *(float4*)(&bs0[0]) = *(const float4*)(bias + tx * 8);
    *(float4*)(&bs0[4]) = *(const float4*)(bias + tx * 8 + 4);

#pragma unroll
    for (int i = 0; i < 8; i++) {
        int m = bm + ty * 8 + i;
        if (m >= M) continue;
        float v[8];
#pragma unroll
        for (int jj = 0; jj < 4; jj++) {
            float lo, hi; unpack2(acc2[i][jj], lo, hi);
            v[2 * jj] = lo; v[2 * jj + 1] = hi;
        }
#pragma unroll
        for (int j = 0; j < 8; j++) {
            float x = v[j] + bs0[j];
            v[j] = x > 0.f ? x : 0.01f * x;
        }
        float* cp = C + (size_t)m * 768 + tx * 8;
        *(float4*)(cp)     = *(float4*)(&v[0]);
        *(float4*)(cp + 4) = *(float4*)(&v[4]);
    }
}

// ---------------- fused dual-LSTM step kernel + CSR piggyback ----------------
__device__ __forceinline__ float sigf(float x) { return 1.f / (1.f + expf(-x)); }

__global__ __launch_bounds__(256, 2) void lstm_step2_kernel(
    const float* __restrict__ Xv, const float* __restrict__ Xs, int ldx,
    const float* __restrict__ Hv, const float* __restrict__ Hs,
    const float* __restrict__ Wcv, const float* __restrict__ Wcs,
    const float* __restrict__ bcv, const float* __restrict__ bcs,
    float* __restrict__ Cv, float* __restrict__ Cs,
    float* __restrict__ Hvo, float* __restrict__ Hso,
    int aux_mode,
    const int* __restrict__ srcB, const int* __restrict__ dstB,
    float* __restrict__ degB, int* __restrict__ offB, int* __restrict__ curB,
    float* __restrict__ dinvB, int* __restrict__ csrB)
{
    __shared__ float As[2][16][128];
    __shared__ float Ws[2][16][128];
    __shared__ int part[256];

    const int tid = threadIdx.x;

    if (blockIdx.x == 4) {
        if (aux_mode == 1) {
            size_t idx = (size_t)blockIdx.y * 256 + tid;
            const size_t stride = (size_t)gridDim.y * 256;
            for (; idx < (size_t)3 * CE; idx += stride) {
                int r = (int)(idx / CE);
                atomicAdd(&degB[(size_t)r * CN + dstB[idx]], 1.0f);
            }
        } else if (aux_mode == 2) {
            const int r = blockIdx.y;
            if (r < 3) {
                const float* deg = degB + (size_t)r * CN;
                int* off = offB + (size_t)r * (CN + 1);
                int* cur = curB + (size_t)r * CN;
                float* dinv = dinvB + (size_t)r * CN;
                const int chunk = (CN + 255) / 256;
                const int start = tid * chunk;
                const int end = min(start + chunk, CN);
                int s = 0;
                for (int i = start; i < end; i++) s += (int)deg[i];
                part[tid] = s;
                __syncthreads();
                for (int d = 1; d < 256; d <<= 1) {
                    int v = (tid >= d) ? part[tid - d] : 0;
                    __syncthreads();
                    part[tid] += v;
                    __syncthreads();
                }
                int pre = (tid == 0) ? 0 : part[tid - 1];
                for (int i = start; i < end; i++) {
                    off[i] = pre;
                    cur[i] = pre;
                    float dg = deg[i];
                    dinv[i] = rsqrtf(fmaxf(dg, 1.0f));
                    pre += (int)dg;
                }
                if (tid == 255) off[CN] = pre;
            }
        } else if (aux_mode == 3) {
            size_t idx = (size_t)blockIdx.y * 256 + tid;
            const size_t stride = (size_t)gridDim.y * 256;
            for (; idx < (size_t)3 * CE; idx += stride) {
                int r = (int)(idx / CE);
                int d = dstB[idx];
                int pos = atomicAdd(&curB[(size_t)r * CN + d], 1);
                csrB[(size_t)r * CE + pos] = srcB[idx];
            }
        }
        return;
    }

    const int sel = blockIdx.x >> 1;
    const float* X   = sel ? Xs  : Xv;
    const float* Hin = sel ? Hs  : Hv;
    const float* Wc  = sel ? Wcs : Wcv;
    const float* bc  = sel ? bcs : bcv;
    float* Cst  = sel ? Cs  : Cv;
    float* Hout = sel ? Hso : Hvo;

    const int M = CN;
    const int bm = blockIdx.y * 128;
    const int bn = (blockIdx.x & 1) * 128;
    const int lr = tid >> 2;
    const int lk = (tid & 3) << 2;
    const int ty = tid >> 4, tx = tid & 15;

    ull acc2[8][4];
#pragma unroll
    for (int i = 0; i < 8; i++)
#pragma unroll
        for (int jj = 0; jj < 4; jj++) acc2[i][jj] = 0ull;

    int r0 = bm + lr;      r0 = r0 < M ? r0 : (M - 1);
    int r1 = bm + lr + 64; r1 = r1 < M ? r1 : (M - 1);

    float4 pa0, pa1, pw0, pw1;
    {
        int kg = lk;
        pa0 = (kg < 64) ? *(const float4*)(X + (size_t)r0 * ldx + kg)
                        : *(const float4*)(Hin + (size_t)r0 * 64 + (kg - 64));
        pa1 = (kg < 64) ? *(const float4*)(X + (size_t)r1 * ldx + kg)
                        : *(const float4*)(Hin + (size_t)r1 * 64 + (kg - 64));
        pw0 = *(const float4*)(Wc + (size_t)(bn + lr) * 128 + kg);
        pw1 = *(const float4*)(Wc + (size_t)(bn + lr + 64) * 128 + kg);
    }
    STORE_TILE(0)
    __syncthreads();

#pragma unroll
    for (int t = 0; t < 8; t++) {
        const int cur = t & 1, nxt = cur ^ 1;
        const bool has = t < 7;
        if (has) {
            int kg = ((t + 1) << 4) + lk;
            pa0 = (kg < 64) ? *(const float4*)(X + (size_t)r0 * ldx + kg)
                            : *(const float4*)(Hin + (size_t)r0 * 64 + (kg - 64));
            pa1 = (kg < 64) ? *(const float4*)(X + (size_t)r1 * ldx + kg)
                            : *(const float4*)(Hin + (size_t)r1 * 64 + (kg - 64));
            pw0 = *(const float4*)(Wc + (size_t)(bn + lr) * 128 + kg);
            pw1 = *(const float4*)(Wc + (size_t)(bn + lr + 64) * 128 + kg);
        }
        TILE_COMPUTE(cur)
        if (has) { STORE_TILE(nxt) }
        __syncthreads();
    }

    const int colbase = bn + tx * 8;
    const int u0 = colbase >> 2;
    float bb[8];
    *(float4*)(&bb[0]) = *(const float4*)(bc + colbase);
    *(float4*)(&bb[4]) = *(const float4*)(bc + colbase + 4);

#pragma unroll
    for (int i = 0; i < 8; i++) {
        int m = bm + ty * 8 + i;
        if (m >= M) continue;
        float g[8];
#pragma unroll
        for (int jj = 0; jj < 4; jj++) {
            float lo, hi; unpack2(acc2[i][jj], lo, hi);
            g[2 * jj] = lo + bb[2 * jj]; g[2 * jj + 1] = hi + bb[2 * jj + 1];
        }
        float2 cold = *(float2*)(Cst + (size_t)m * 64 + u0);
        float c0 = sigf(g[1]) * cold.x + sigf(g[0]) * tanhf(g[2]);
        float c1 = sigf(g[5]) * cold.y + sigf(g[4]) * tanhf(g[6]);
        float2 cn = make_float2(c0, c1);
        float2 hn = make_float2(sigf(g[3]) * tanhf(c0), sigf(g[7]) * tanhf(c1));
        *(float2*)(Cst + (size_t)m * 64 + u0) = cn;
        *(float2*)(Hout + (size_t)m * 64 + u0) = hn;
    }
}

// ---------------- small kernels ----------------
__global__ void zero_kernel(float* p, size_t n)
{
    size_t i = (size_t)blockIdx.x * blockDim.x + threadIdx.x;
    size_t stride = (size_t)gridDim.x * blockDim.x;
    for (; i < n; i += stride) p[i] = 0.f;
}

__global__ void prep_kernel(const float* __restrict__ Wih_v, const float* __restrict__ Whh_v,
                            const float* __restrict__ bih_v, const float* __restrict__ bhh_v,
                            const float* __restrict__ Wih_s, const float* __restrict__ Whh_s,
                            const float* __restrict__ bih_s, const float* __restrict__ bhh_s,
                            float* __restrict__ S)
{
    int idx = blockIdx.x * blockDim.x + threadIdx.x;
    if (idx < 256 * 128) {
        int o = idx >> 7, k = idx & 127;
        int u = o >> 2, g = o & 3;
        int orow = g * 64 + u;
        S[OFF_WCV + idx] = (k < 64) ? Wih_v[orow * 64 + k] : Whh_v[orow * 64 + (k - 64)];
        S[OFF_WCS + idx] = (k < 64) ? Wih_s[orow * 64 + k] : Whh_s[orow * 64 + (k - 64)];
        if (idx < 256) {
            int uu = idx >> 2, gg = idx & 3;
            int ob = gg * 64 + uu;
            S[OFF_BCV + idx] = bih_v[ob] + bhh_v[ob];
            S[OFF_BCS + idx] = bih_s[ob] + bhh_s[ob];
        }
    }
}

// build W3P (k-permuted lin3) and W4P (xp-combined lin4)
__global__ void prep2_kernel(const float* __restrict__ W3, const float* __restrict__ W4,
                             float* __restrict__ S)
{
    int idx = blockIdx.x * blockDim.x + threadIdx.x;
    if (idx < 128 * 384) {
        int o = idx / 384, k = idx % 384;
        float v;
        if (k < 128)       v = W4[o * 512 + k];
        else if (k < 256)  v = W4[o * 512 + k] + W4[o * 512 + k + 256];
        else               v = W4[o * 512 + k];
        S[OFF_W4P + o * 384 + k] = v;
    }
    if (idx < 128 * 256) {
        int o = idx >> 8, k = idx & 255;
        // W3P cols [0:128) = xp part (orig 128:256), [128:256) = xs part (orig 0:128)
        float v = (k < 128) ? W3[o * 256 + 128 + k] : W3[o * 256 + (k - 128)];
        S[OFF_W3P + o * 256 + k] = v;
    }
}

// batched gather propagation, grid.y = r; edge loop unrolled x4 for MLP
__global__ __launch_bounds__(256) void prop3_kernel(
    const float* __restrict__ pin, int ldin, size_t pin_rstride,
    const int* __restrict__ csrB, const int* __restrict__ offB,
    const float* __restrict__ dinvB, float* __restrict__ outB)
{
    const int r = blockIdx.y;
    const int n = blockIdx.x * 8 + (threadIdx.x >> 5);
    if (n >= CN) return;
    const int lane = threadIdx.x & 31;
    const int col = lane * 4;
    const float* pinr = pin + (size_t)r * pin_rstride;
    const int* csr = csrB + (size_t)r * CE;
    const int* off = offB + (size_t)r * (CN + 1);
    const float* dinv = dinvB + (size_t)r * CN;
    float* outp = outB + (size_t)r * CN * 128;

    float4 acc = make_float4(0.f, 0.f, 0.f, 0.f);
    const int s0 = off[n], s1 = off[n + 1];
    int e = s0;
    for (; e + 4 <= s1; e += 4) {
        int sn0 = csr[e], sn1 = csr[e + 1], sn2 = csr[e + 2], sn3 = csr[e + 3];
        float d0 = __ldg(&dinv[sn0]), d1 = __ldg(&dinv[sn1]);
        float d2 = __ldg(&dinv[sn2]), d3 = __ldg(&dinv[sn3]);
        float4 v0 = *(const float4*)(pinr + (size_t)sn0 * ldin + col);
        float4 v1 = *(const float4*)(pinr + (size_t)sn1 * ldin + col);
        float4 v2 = *(const float4*)(pinr + (size_t)sn2 * ldin + col);
        float4 v3 = *(const float4*)(pinr + (size_t)sn3 * ldin + col);
        acc.x += v0.x * d0 + v1.x * d1 + v2.x * d2 + v3.x * d3;
        acc.y += v0.y * d0 + v1.y * d1 + v2.y * d2 + v3.y * d3;
        acc.z += v0.z * d0 + v1.z * d1 + v2.z * d2 + v3.z * d3;
        acc.w += v0.w * d0 + v1.w * d1 + v2.w * d2 + v3.w * d3;
    }
    for (; e < s1; e++) {
        int sn = csr[e];
        float ds = __ldg(&dinv[sn]);
        float4 v = *(const float4*)(pinr + (size_t)sn * ldin + col);
        acc.x += v.x * ds; acc.y += v.y * ds; acc.z += v.z * ds; acc.w += v.w * ds;
    }
    const float dn = dinv[n];
    float4 pv = *(const float4*)(pinr + (size_t)n * ldin + col);
    float4 o = make_float4(pv.x - acc.x * dn, pv.y - acc.y * dn,
                           pv.z - acc.z * dn, pv.w - acc.w * dn);
    *(float4*)(outp + (size_t)n * 128 + col) = o;
}

// combine batched over relations: grid.y = r
__global__ __launch_bounds__(256) void attn_comb3_kernel(
    const float* __restrict__ YB,
    const float* __restrict__ BIGp,
    const float* __restrict__ P1B,
    const float* __restrict__ P2B,
    const float* __restrict__ bf1,
    const float* __restrict__ w2,
    float* __restrict__ resB)
{
    const int r = blockIdx.y;
    const int n = blockIdx.x * 8 + (threadIdx.x >> 5);
    if (n >= CN) return;
    const int lane = threadIdx.x & 31;
    const int col = lane * 4;

    const float* Y = YB + (size_t)r * 3 * CN * 128;
    const float* P0 = BIGp + 128 * r;
    const float* P1 = P1B + (size_t)r * CN * 128;
    const float* P2 = P2B + (size_t)r * CN * 128;

    float4 ya = *(const float4*)(Y + (size_t)n * 128 + col);
    float4 yb = *(const float4*)(Y + (size_t)CN * 128 + (size_t)n * 128 + col);
    float4 yc = *(const float4*)(Y + (size_t)2 * CN * 128 + (size_t)n * 128 + col);
    float4 bf = *(const float4*)(bf1 + (size_t)r * 128 + col);
    float4 wl = *(const float4*)(w2 + (size_t)r * 128 + col);

    float sc[5];
#pragma unroll
    for (int f = 0; f < 5; f++) {
        float t0 = c_th0[f], t1 = c_th1[f], t2 = c_th2[f];
        float gx = t0 * ya.x + t1 * yb.x + t2 * yc.x + bf.x;
        float gy = t0 * ya.y + t1 * yb.y + t2 * yc.y + bf.y;
        float gz = t0 * ya.z + t1 * yb.z + t2 * yc.z + bf.z;
        float gw = t0 * ya.w + t1 * yb.w + t2 * yc.w + bf.w;
        float p = tanhf(gx) * wl.x + tanhf(gy) * wl.y + tanhf(gz) * wl.z + tanhf(gw) * wl.w;
#pragma unroll
        for (int off = 16; off; off >>= 1) p += __shfl_xor_sync(0xffffffffu, p, off);
        sc[f] = p;
    }
    float mx = sc[0];
#pragma unroll
    for (int f = 1; f < 5; f++) mx = fmaxf(mx, sc[f]);
    float e[5], s = 0.f;
#pragma unroll
    for (int f = 0; f < 5; f++) { e[f] = expf(sc[f] - mx); s += e[f]; }
    float inv = 1.f / s;
    float ca = 0.f, cb = 0.f, cc = 0.f;
#pragma unroll
    for (int f = 0; f < 5; f++) {
        float w = e[f] * inv;
        ca += w * c_th0[f]; cb += w * c_th1[f]; cc += w * c_th2[f];
    }
    float4 a = *(const float4*)(P0 + (size_t)n * 768 + col);
    float4 b = *(const float4*)(P1 + (size_t)n * 128 + col);
    float4 c = *(const float4*)(P2 + (size_t)n * 128 + col);
    float4 rr = make_float4(ca * a.x + cb * b.x + cc * c.x,
                            ca * a.y + cb * b.y + cc * c.y,
                            ca * a.z + cb * b.z + cc * c.z,
                            ca * a.w + cb * b.w + cc * c.w);
    *(float4*)(resB + (size_t)r * CN * 128 + (size_t)n * 128 + col) = rr;
}

// out[n, c] = big[n, :] . W6[c, :] + b6[c], warp per node
__global__ void final_kernel(const float* __restrict__ big, const float* __restrict__ W6,
                             const float* __restrict__ b6, float* __restrict__ out)
{
    size_t gid = (size_t)blockIdx.x * blockDim.x + threadIdx.x;
    int n = (int)(gid >> 5);
    int lane = (int)(gid & 31);
    if (n >= CN) return;
    const float* row = big + (size_t)n * 768;
#pragma unroll
    for (int c = 0; c < 2; c++) {
        float a = 0.f;
        for (int j = lane; j < 768; j += 32) a += row[j] * W6[c * 768 + j];
#pragma unroll
        for (int off = 16; off; off >>= 1) a += __shfl_xor_sync(0xffffffffu, a, off);
        if (lane == 0) out[(size_t)n * 2 + c] = a + b6[c];
    }
}

// ---------------- orchestration ----------------
extern "C" void kernel_launch(void* const* d_in, const int* in_sizes, int n_in,
                              void* d_out, int out_size)
{
    const float* voc    = (const float*)d_in[0];
    const float* sms    = (const float*)d_in[1];
    const float* pers   = (const float*)d_in[2];
    const float* Wih_v  = (const float*)d_in[3];
    const float* Whh_v  = (const float*)d_in[4];
    const float* bih_v  = (const float*)d_in[5];
    const float* bhh_v  = (const float*)d_in[6];
    const float* Wih_s  = (const float*)d_in[7];
    const float* Whh_s  = (const float*)d_in[8];
    const float* bih_s  = (const float*)d_in[9];
    const float* bhh_s  = (const float*)d_in[10];
    const float* W_lin  = (const float*)d_in[11];
    const float* b_lin  = (const float*)d_in[12];
    const float* W_lin1 = (const float*)d_in[13];
    const float* b_lin1 = (const float*)d_in[14];
    const float* W_pers = (const float*)d_in[15];
    const float* b_pers = (const float*)d_in[16];
    const float* W_lin2 = (const float*)d_in[17];
    const float* b_lin2 = (const float*)d_in[18];
    const float* W_lin3 = (const float*)d_in[19];
    const float* b_lin3 = (const float*)d_in[20];
    const float* W_lin4 = (const float*)d_in[21];
    const float* b_lin4 = (const float*)d_in[22];
    const float* W_lin5 = (const float*)d_in[23];
    const float* b_lin5 = (const float*)d_in[24];
    const float* Wf1    = (const float*)d_in[25];
    const float* bf1    = (const float*)d_in[26];
    const float* Wf2    = (const float*)d_in[27];
    const float* W_lin6 = (const float*)d_in[28];
    const float* b_lin6 = (const float*)d_in[29];
    const int*   src    = (const int*)d_in[30];
    const int*   dst    = (const int*)d_in[31];
    float* out = (float*)d_out;

    float* S = nullptr;
    cudaGetSymbolAddress((void**)&S, g_scratch);
    int* csr = nullptr; cudaGetSymbolAddress((void**)&csr, g_csr);
    int* offp = nullptr; cudaGetSymbolAddress((void**)&offp, g_off);
    int* curp = nullptr; cudaGetSymbolAddress((void**)&curp, g_cur);

    // prep + derived weights + zero states + zero deg
    prep_kernel<<<(256 * 128 + 255) / 256, 256>>>(Wih_v, Whh_v, bih_v, bhh_v,
                                                  Wih_s, Whh_s, bih_s, bhh_s, S);
    prep2_kernel<<<(128 * 384 + 255) / 256, 256>>>(W_lin3, W_lin4, S);
    zero_kernel<<<4096, 256>>>(S + OFF_HV0, (size_t)6 * CN * 64);
    zero_kernel<<<256, 256>>>(S + OFF_DEG, (size_t)3 * CN);

    // ---- LSTMs: 16 steps; steps 0-2 piggyback the CSR build ----
    const int ygrid = (CN + 127) / 128;
    for (int t = 0; t < CT; t++) {
        const float* hv_in  = S + ((t & 1) ? OFF_HV1 : OFF_HV0);
        float*       hv_out = S + ((t & 1) ? OFF_HV0 : OFF_HV1);
        const float* hs_in  = S + ((t & 1) ? OFF_HS1 : OFF_HS0);
        float*       hs_out = S + ((t & 1) ? OFF_HS0 : OFF_HS1);
        const int aux = (t == 0) ? 1 : (t == 1) ? 2 : (t == 2) ? 3 : 0;
        dim3 lgrid(aux ? 5 : 4, ygrid);
        lstm_step2_kernel<<<lgrid, 256>>>(voc + (size_t)t * 64, sms + (size_t)t * 64, CT * 64,
                                          hv_in, hs_in,
                                          S + OFF_WCV, S + OFF_WCS,
                                          S + OFF_BCV, S + OFF_BCS,
                                          S + OFF_CV, S + OFF_CS,
                                          hv_out, hs_out,
                                          aux, src, dst,
                                          S + OFF_DEG, offp, curp,
                                          S + OFF_DINV, csr);
    }

    // ---- projections (batched) ----
    projA_kernel<<<dim3(3, ygrid), 256>>>(S + OFF_HV0, S + OFF_HS0, pers,
                                          W_lin, b_lin, W_lin1, b_lin1,
                                          W_pers, b_pers, S + OFF_XCAT);
    projB_kernel<<<dim3(3, ygrid), 256>>>(S + OFF_XCAT,
                                          W_lin2, b_lin2,
                                          S + OFF_W3P, b_lin3,
                                          S + OFF_W4P, b_lin4,
                                          S + OFF_BIG);

    // ---- relation graphs: CSR already built during LSTM steps 0-2 ----
    const int pgrid = (CN + 7) / 8;
    const float* BIGp = S + OFF_BIG + 384;

    prop3_kernel<<<dim3(pgrid, 3), 256>>>(BIGp, 768, 128,
                                          csr, offp, S + OFF_DINV, S + OFF_P1);
    prop3_kernel<<<dim3(pgrid, 3), 256>>>(S + OFF_P1, 128, (size_t)CN * 128,
                                          csr, offp, S + OFF_DINV, S + OFF_P2);

    yabc9_kernel<<<dim3(9, ygrid), 256>>>(BIGp, S + OFF_P1, S + OFF_P2,
                                          Wf1, S + OFF_Y);

    attn_comb3_kernel<<<dim3(pgrid, 3), 256>>>(S + OFF_Y, BIGp, S + OFF_P1, S + OFF_P2,
                                               bf1, Wf2, S + OFF_RES);

    lin5b_kernel<<<dim3(3, ygrid), 256>>>(S + OFF_RES, W_lin5, b_lin5, S + OFF_BIG);

    // ---- final head ----
    final_kernel<<<((size_t)CN * 32 + 255) / 256, 256>>>(S + OFF_BIG, W_lin6, b_lin6, out);
}